// round 8
// baseline (speedup 1.0000x reference)
#include <cuda_runtime.h>
#include <cuda_bf16.h>
#include <cuda_fp16.h>
#include <math.h>
#include <stdint.h>

#define BB 2
#define TT 2048
#define DD 1024
#define NH 16
#define NKV 4
#define HD 64
#define NREP 4           // NH / NKV
#define MM (BB*TT)       // 4096
#define NQKV (NH*HD + 2*NKV*HD)   // 1536 fused QKV output width

// ---------------- scratch (device globals; no runtime allocation) -----------
__device__ __align__(16) float g_cos[TT*32];
__device__ __align__(16) float g_sin[TT*32];
__device__ __nv_bfloat16 g_xhi[MM*DD],  g_xlo[MM*DD];
__device__ __nv_bfloat16 g_ahi[MM*DD],  g_alo[MM*DD];          // attention out (bf16 split)
__device__ __nv_bfloat16 g_wt_hi[NQKV*DD], g_wt_lo[NQKV*DD];   // fused QKV weights^T [N][K]
__device__ __nv_bfloat16 g_wot_hi[DD*DD],  g_wot_lo[DD*DD];    // Wo^T [N][K]
__device__ __nv_bfloat16 g_qhi[BB*NH*TT*HD],  g_qlo[BB*NH*TT*HD];   // [b][h][t][d]
__device__ __nv_bfloat16 g_khi[BB*NKV*TT*HD], g_klo[BB*NKV*TT*HD];  // [b][kvh][t][d]
__device__ __half g_v16[BB*NKV*TT*HD];      // V fp16 [b][kvh][t][d]

// ---------------- helpers ----------------------------------------------------
__device__ __forceinline__ uint32_t smem_u32(const void* p) {
    uint32_t a;
    asm("{ .reg .u64 t; cvta.to.shared.u64 t, %1; cvt.u32.u64 %0, t; }"
        : "=r"(a) : "l"(p));
    return a;
}
#define SWZ(off) ((off) ^ (((off) >> 3) & 0x70))

#define CP_ASYNC16(dst, src) \
    asm volatile("cp.async.cg.shared.global [%0], [%1], 16;" \
                 :: "r"(dst), "l"(src) : "memory")
#define CP_COMMIT() asm volatile("cp.async.commit_group;" ::: "memory")
#define CP_WAIT(n)  asm volatile("cp.async.wait_group %0;" :: "n"(n) : "memory")

#define LDSM4(r0, r1, r2, r3, addr) \
    asm volatile("ldmatrix.sync.aligned.m8n8.x4.shared.b16 {%0,%1,%2,%3}, [%4];" \
                 : "=r"(r0), "=r"(r1), "=r"(r2), "=r"(r3) : "r"(addr))

#define LDSM4T(r0, r1, r2, r3, addr) \
    asm volatile("ldmatrix.sync.aligned.m8n8.x4.trans.shared.b16 {%0,%1,%2,%3}, [%4];" \
                 : "=r"(r0), "=r"(r1), "=r"(r2), "=r"(r3) : "r"(addr))

#define MMAS(c, a, b0, b1) \
    asm volatile("mma.sync.aligned.m16n8k16.row.col.f32.bf16.bf16.f32 " \
                 "{%0,%1,%2,%3}, {%4,%5,%6,%7}, {%8,%9}, {%0,%1,%2,%3};" \
                 : "+f"((c)[0]), "+f"((c)[1]), "+f"((c)[2]), "+f"((c)[3]) \
                 : "r"((a)[0]), "r"((a)[1]), "r"((a)[2]), "r"((a)[3]), \
                   "r"(b0), "r"(b1))

#define MMAH(c, a, b0, b1) \
    asm volatile("mma.sync.aligned.m16n8k16.row.col.f32.f16.f16.f32 " \
                 "{%0,%1,%2,%3}, {%4,%5,%6,%7}, {%8,%9}, {%0,%1,%2,%3};" \
                 : "+f"((c)[0]), "+f"((c)[1]), "+f"((c)[2]), "+f"((c)[3]) \
                 : "r"((a)[0]), "r"((a)[1]), "r"((a)[2]), "r"((a)[3]), \
                   "r"(b0), "r"(b1))

__device__ __forceinline__ void split2(float x0, float x1, uint32_t& hi, uint32_t& lo) {
    __nv_bfloat16 h0 = __float2bfloat16(x0), h1 = __float2bfloat16(x1);
    float r0 = x0 - __bfloat162float(h0), r1 = x1 - __bfloat162float(h1);
    __nv_bfloat162 H; H.x = h0; H.y = h1;
    __nv_bfloat162 L = __floats2bfloat162_rn(r0, r1);
    hi = *(uint32_t*)&H; lo = *(uint32_t*)&L;
}

__device__ __forceinline__ uint32_t packh(float a, float b) {
    __half2 h = __floats2half2_rn(a, b);
    return *(uint32_t*)&h;
}

// ---------------------------------------------------------------------------
// Split-bf16 HMMA GEMM: C[M,N] = (Ahi+Alo)[M,K] @ (Bhi+Blo)[N,K]^T (fp32 acc)
// 128x128 CTA tile, 8 warps (2m x 4n), BK=64, 3-stage cp.async.
// EPI=0: plain fp32 C store.  EPI=1: fused RoPE+split QKV epilogue
// (writes g_qhi/qlo, g_khi/klo, g_v16 directly; C unused).
// ---------------------------------------------------------------------------
template <int EPI>
__global__ __launch_bounds__(256, 1) void gemm_mma(
        const __nv_bfloat16* __restrict__ Ahi, const __nv_bfloat16* __restrict__ Alo,
        const __nv_bfloat16* __restrict__ Bhi, const __nv_bfloat16* __restrict__ Blo,
        float* __restrict__ C, int M, int N, int K) {
    extern __shared__ char smem[];
    uint32_t sbase = smem_u32(smem);
    int tid = threadIdx.x, wid = tid >> 5, lid = tid & 31;
    int m0 = blockIdx.y * 128, n0 = blockIdx.x * 128;
    int wm = wid & 1, wn = wid >> 1;
    const int nch = K / 64;
    const int rr = tid >> 3;
    const int uu = tid & 7;

    float acc[4][4][4] = {};

    auto load_chunk = [&](int buf, int ch) {
        int k0 = ch * 64;
        uint32_t dbase = sbase + (uint32_t)buf * 65536u;
        #pragma unroll
        for (int arr = 0; arr < 4; arr++) {
            const __nv_bfloat16* s = (arr == 0) ? Ahi : (arr == 1) ? Alo
                                    : (arr == 2) ? Bhi : Blo;
            int rb = (arr < 2) ? m0 : n0;
            uint32_t ab = dbase + (uint32_t)arr * 16384u;
            #pragma unroll
            for (int it = 0; it < 4; it++) {
                int r = it * 32 + rr;
                CP_ASYNC16(ab + SWZ(r * 128 + uu * 16),
                           s + (size_t)(rb + r) * K + k0 + uu * 8);
            }
        }
        CP_COMMIT();
    };

    load_chunk(0, 0);
    load_chunk(1, 1);

    for (int ch = 0; ch < nch; ch++) {
        if (ch < nch - 1) { CP_WAIT(1); } else { CP_WAIT(0); }
        __syncthreads();
        if (ch + 2 < nch) load_chunk((ch + 2) % 3, ch + 2);   // early prefetch

        uint32_t db = sbase + (uint32_t)(ch % 3) * 65536u;
        uint32_t abh = db, abl = db + 16384u;
        uint32_t bbh = db + 32768u, bbl = db + 49152u;
        int g = lid >> 3, w8 = lid & 7;

        #pragma unroll
        for (int ks = 0; ks < 4; ks++) {
            uint32_t ah[4][4], al[4][4], bh[4][2], bl[4][2];
            int arow = wm * 64 + (lid & 15);
            int acol = ks * 32 + (lid >> 4) * 16;
            #pragma unroll
            for (int mi = 0; mi < 4; mi++) {
                uint32_t off = SWZ((arow + mi * 16) * 128 + acol);
                LDSM4(ah[mi][0], ah[mi][1], ah[mi][2], ah[mi][3], abh + off);
                LDSM4(al[mi][0], al[mi][1], al[mi][2], al[mi][3], abl + off);
            }
            #pragma unroll
            for (int p = 0; p < 2; p++) {
                int nrow = wn * 32 + p * 16 + (g >> 1) * 8 + w8;
                int ncol = ks * 32 + (g & 1) * 16;
                uint32_t off = SWZ(nrow * 128 + ncol);
                LDSM4(bh[2*p][0], bh[2*p][1], bh[2*p+1][0], bh[2*p+1][1], bbh + off);
                LDSM4(bl[2*p][0], bl[2*p][1], bl[2*p+1][0], bl[2*p+1][1], bbl + off);
            }
            #pragma unroll
            for (int mi = 0; mi < 4; mi++)
                #pragma unroll
                for (int ni = 0; ni < 4; ni++) {
                    MMAS(acc[mi][ni], ah[mi], bh[ni][0], bh[ni][1]);
                    MMAS(acc[mi][ni], ah[mi], bl[ni][0], bl[ni][1]);
                    MMAS(acc[mi][ni], al[mi], bh[ni][0], bh[ni][1]);
                }
        }
        __syncthreads();
    }

    if (EPI == 0) {
        #pragma unroll
        for (int mi = 0; mi < 4; mi++) {
            int row = m0 + wm * 64 + mi * 16 + (lid >> 2);
            #pragma unroll
            for (int ni = 0; ni < 4; ni++) {
                int col = n0 + wn * 32 + ni * 8 + (lid & 3) * 2;
                *(float2*)&C[(size_t)row * N + col] =
                    make_float2(acc[mi][ni][0], acc[mi][ni][1]);
                *(float2*)&C[(size_t)(row + 8) * N + col] =
                    make_float2(acc[mi][ni][2], acc[mi][ni][3]);
            }
        }
    } else {
        // region uniform per CTA: cols [0,1024)=Q, [1024,1280)=K, [1280,1536)=V
        int region = (blockIdx.x < 8) ? 0 : (blockIdx.x < 10) ? 1 : 2;
        #pragma unroll
        for (int mi = 0; mi < 4; mi++) {
            int row = m0 + wm * 64 + mi * 16 + (lid >> 2);
            #pragma unroll
            for (int r2 = 0; r2 < 2; r2++) {
                int trow = row + r2 * 8;
                int b = trow >> 11, t = trow & (TT - 1);
                #pragma unroll
                for (int ni = 0; ni < 4; ni++) {
                    int c = n0 + wn * 32 + ni * 8 + (lid & 3) * 2;
                    float v0 = acc[mi][ni][r2 * 2], v1 = acc[mi][ni][r2 * 2 + 1];
                    if (region == 2) {
                        int cc = c - 1280;
                        int kvh = cc >> 6, d = cc & 63;
                        uint32_t hv = packh(v0, v1);
                        *(uint32_t*)&g_v16[((size_t)(b * NKV + kvh) * TT + t) * HD + d] = hv;
                    } else {
                        int cc = (region == 1) ? c - 1024 : c;
                        int hh = cc >> 6, d = cc & 63;
                        int ci = t * 32 + (d >> 1);
                        float cs = g_cos[ci], sn = g_sin[ci];
                        float r0 = v0 * cs - v1 * sn;
                        float r1 = v1 * cs + v0 * sn;
                        uint32_t hi, lo;
                        split2(r0, r1, hi, lo);
                        if (region == 1) {
                            size_t o = ((size_t)(b * NKV + hh) * TT + t) * HD + d;
                            *(uint32_t*)&g_khi[o] = hi;
                            *(uint32_t*)&g_klo[o] = lo;
                        } else {
                            size_t o = ((size_t)(b * NH + hh) * TT + t) * HD + d;
                            *(uint32_t*)&g_qhi[o] = hi;
                            *(uint32_t*)&g_qlo[o] = lo;
                        }
                    }
                }
            }
        }
    }
}

// ---------------------------------------------------------------------------
// HMMA flash attention, causal. Grid (T/128 reversed, B*NH), 256 threads.
// S = QK^T 3-term split bf16; PV single-term fp16, V consumed untransposed
// via ldmatrix.trans. 3-stage cp.async; exp2 softmax; fp32 accum.
// smem: Q 32KB + 3 x 24KB (Khi 8K | Klo 8K | Vfp16 8K) = 104KB.
// ---------------------------------------------------------------------------
__global__ __launch_bounds__(256, 1) void attn_mma(
        const __nv_bfloat16* __restrict__ Qhi, const __nv_bfloat16* __restrict__ Qlo,
        const __nv_bfloat16* __restrict__ Khi, const __nv_bfloat16* __restrict__ Klo,
        const __half* __restrict__ Vt,
        __nv_bfloat16* __restrict__ Ohi, __nv_bfloat16* __restrict__ Olo) {
    extern __shared__ char smem[];
    uint32_t sbase = smem_u32(smem);
    const uint32_t QHI = 0, QLO = 16384, BUF = 32768;   // 3 x 24KB chunk buffers

    int tid = threadIdx.x, wid = tid >> 5, lid = tid & 31;
    int qt = gridDim.x - 1 - blockIdx.x;
    int bh = blockIdx.y;
    int b = bh / NH, h = bh % NH, kvh = h / NREP;
    int q0 = qt * 128;

    const __nv_bfloat16* qbh = Qhi + (size_t)(b * NH + h) * TT * HD;
    const __nv_bfloat16* qbl = Qlo + (size_t)(b * NH + h) * TT * HD;
    const __nv_bfloat16* kbh = Khi + (size_t)(b * NKV + kvh) * TT * HD;
    const __nv_bfloat16* kbl = Klo + (size_t)(b * NKV + kvh) * TT * HD;
    const __half* vbase = Vt + (size_t)(b * NKV + kvh) * TT * HD;   // [t][d]

    // stage Q (own commit group)
    {
        #pragma unroll
        for (int arr = 0; arr < 2; arr++) {
            const __nv_bfloat16* s = arr ? qbl : qbh;
            uint32_t ab = sbase + (arr ? QLO : QHI);
            #pragma unroll
            for (int it = 0; it < 4; it++) {
                int idx = it * 256 + tid;
                int r = idx >> 3, u = idx & 7;
                CP_ASYNC16(ab + SWZ(r * 128 + u * 16),
                           s + (size_t)(q0 + r) * HD + u * 8);
            }
        }
        CP_COMMIT();
    }

    auto load_chunk = [&](int buf, int kt) {
        uint32_t db = sbase + BUF + (uint32_t)buf * 24576u;
        #pragma unroll
        for (int arr = 0; arr < 3; arr++) {
            uint32_t ab = db + (uint32_t)arr * 8192u;
            #pragma unroll
            for (int it = 0; it < 2; it++) {
                int idx = it * 256 + tid;
                int r = idx >> 3, u = idx & 7;
                const char* src;
                if (arr == 0)      src = (const char*)(kbh + (size_t)(kt * 64 + r) * HD + u * 8);
                else if (arr == 1) src = (const char*)(kbl + (size_t)(kt * 64 + r) * HD + u * 8);
                else               src = (const char*)(vbase + (size_t)(kt * 64 + r) * HD + u * 8);
                CP_ASYNC16(ab + SWZ(r * 128 + u * 16), src);
            }
        }
        CP_COMMIT();
    };

    int nch = 2 * qt + 2;
    load_chunk(0, 0);
    load_chunk(1, 1);

    // Q fragments (leave both chunk groups pending)
    CP_WAIT(2);
    __syncthreads();
    uint32_t qfh[4][4], qfl[4][4];
    {
        int arow = wid * 16 + (lid & 15);
        #pragma unroll
        for (int ks = 0; ks < 4; ks++) {
            uint32_t off = SWZ(arow * 128 + ks * 32 + (lid >> 4) * 16);
            LDSM4(qfh[ks][0], qfh[ks][1], qfh[ks][2], qfh[ks][3], sbase + QHI + off);
            LDSM4(qfl[ks][0], qfl[ks][1], qfl[ks][2], qfl[ks][3], sbase + QLO + off);
        }
    }

    float oacc[8][4] = {};
    float mA = -1e30f, mB = -1e30f, lA = 0.f, lB = 0.f;
    const int g = lid >> 3, w8 = lid & 7;
    const int qrA = q0 + wid * 16 + (lid >> 2);
    const float SC = 0.125f * 1.4426950408889634f;   // scale * log2(e)
    const int vrow16 = lid & 15, vhi16 = (lid >> 4) & 1;

    for (int ch = 0; ch < nch; ch++) {
        if (ch < nch - 1) { CP_WAIT(1); } else { CP_WAIT(0); }
        __syncthreads();
        if (ch + 2 < nch) load_chunk((ch + 2) % 3, ch + 2);   // early prefetch

        int kt = ch;
        bool active = (kt * 64 <= q0 + wid * 16 + 15);
        if (active) {
            uint32_t kb = sbase + BUF + (uint32_t)(ch % 3) * 24576u;
            uint32_t vb = kb + 16384u;

            // ---- S = Q K^T (3-term split bf16) ----
            float sacc[8][4] = {};
            #pragma unroll
            for (int ks = 0; ks < 4; ks++) {
                #pragma unroll
                for (int p = 0; p < 4; p++) {
                    int nrow = p * 16 + (g >> 1) * 8 + w8;
                    uint32_t off = SWZ(nrow * 128 + ks * 32 + (g & 1) * 16);
                    uint32_t b0, b1, b2, b3, c0, c1, c2, c3;
                    LDSM4(b0, b1, b2, b3, kb + off);
                    LDSM4(c0, c1, c2, c3, kb + 8192u + off);
                    MMAS(sacc[2*p],   qfh[ks], b0, b1);
                    MMAS(sacc[2*p+1], qfh[ks], b2, b3);
                    MMAS(sacc[2*p],   qfh[ks], c0, c1);
                    MMAS(sacc[2*p+1], qfh[ks], c2, c3);
                    MMAS(sacc[2*p],   qfl[ks], b0, b1);
                    MMAS(sacc[2*p+1], qfl[ks], b2, b3);
                }
            }

            // ---- scale (log2 domain) + causal mask ----
            #pragma unroll
            for (int nt = 0; nt < 8; nt++) {
                int kc = kt * 64 + nt * 8 + (lid & 3) * 2;
                #pragma unroll
                for (int j = 0; j < 4; j++) sacc[nt][j] *= SC;
                if (kc > qrA)         sacc[nt][0] = -1e9f;
                if (kc + 1 > qrA)     sacc[nt][1] = -1e9f;
                if (kc > qrA + 8)     sacc[nt][2] = -1e9f;
                if (kc + 1 > qrA + 8) sacc[nt][3] = -1e9f;
            }

            // ---- online softmax (base-2) ----
            float rmA = -1e30f, rmB = -1e30f;
            #pragma unroll
            for (int nt = 0; nt < 8; nt++) {
                rmA = fmaxf(rmA, fmaxf(sacc[nt][0], sacc[nt][1]));
                rmB = fmaxf(rmB, fmaxf(sacc[nt][2], sacc[nt][3]));
            }
            rmA = fmaxf(rmA, __shfl_xor_sync(0xffffffffu, rmA, 1));
            rmA = fmaxf(rmA, __shfl_xor_sync(0xffffffffu, rmA, 2));
            rmB = fmaxf(rmB, __shfl_xor_sync(0xffffffffu, rmB, 1));
            rmB = fmaxf(rmB, __shfl_xor_sync(0xffffffffu, rmB, 2));
            float mnA = fmaxf(mA, rmA), mnB = fmaxf(mB, rmB);
            float corrA = exp2f(mA - mnA), corrB = exp2f(mB - mnB);
            mA = mnA; mB = mnB;
            float rsA = 0.f, rsB = 0.f;
            #pragma unroll
            for (int nt = 0; nt < 8; nt++) {
                sacc[nt][0] = exp2f(sacc[nt][0] - mA);
                sacc[nt][1] = exp2f(sacc[nt][1] - mA);
                sacc[nt][2] = exp2f(sacc[nt][2] - mB);
                sacc[nt][3] = exp2f(sacc[nt][3] - mB);
                rsA += sacc[nt][0] + sacc[nt][1];
                rsB += sacc[nt][2] + sacc[nt][3];
            }
            rsA += __shfl_xor_sync(0xffffffffu, rsA, 1);
            rsA += __shfl_xor_sync(0xffffffffu, rsA, 2);
            rsB += __shfl_xor_sync(0xffffffffu, rsB, 1);
            rsB += __shfl_xor_sync(0xffffffffu, rsB, 2);
            lA = lA * corrA + rsA;
            lB = lB * corrB + rsB;
            #pragma unroll
            for (int nt = 0; nt < 8; nt++) {
                oacc[nt][0] *= corrA; oacc[nt][1] *= corrA;
                oacc[nt][2] *= corrB; oacc[nt][3] *= corrB;
            }

            // ---- O += P V (fp16; V untransposed via ldmatrix.trans) ----
            #pragma unroll
            for (int k2 = 0; k2 < 4; k2++) {
                uint32_t pa[4];
                pa[0] = packh(sacc[2*k2][0],   sacc[2*k2][1]);
                pa[1] = packh(sacc[2*k2][2],   sacc[2*k2][3]);
                pa[2] = packh(sacc[2*k2+1][0], sacc[2*k2+1][1]);
                pa[3] = packh(sacc[2*k2+1][2], sacc[2*k2+1][3]);
                #pragma unroll
                for (int p = 0; p < 4; p++) {
                    uint32_t off = SWZ((k2 * 16 + vrow16) * 128 + p * 32 + vhi16 * 16);
                    uint32_t b0, b1, b2, b3;
                    LDSM4T(b0, b1, b2, b3, vb + off);
                    MMAH(oacc[2*p],   pa, b0, b1);
                    MMAH(oacc[2*p+1], pa, b2, b3);
                }
            }
        }
        __syncthreads();
    }

    // ---- epilogue ----
    float invA = 1.f / lA, invB = 1.f / lB;
    size_t rowA = (size_t)(b * TT + qrA);
    size_t rowB = rowA + 8;
    int colb = h * HD + (lid & 3) * 2;
    #pragma unroll
    for (int nt = 0; nt < 8; nt++) {
        uint32_t hi, lo;
        split2(oacc[nt][0] * invA, oacc[nt][1] * invA, hi, lo);
        *(uint32_t*)&Ohi[rowA * DD + colb + nt * 8] = hi;
        *(uint32_t*)&Olo[rowA * DD + colb + nt * 8] = lo;
        split2(oacc[nt][2] * invB, oacc[nt][3] * invB, hi, lo);
        *(uint32_t*)&Ohi[rowB * DD + colb + nt * 8] = hi;
        *(uint32_t*)&Olo[rowB * DD + colb + nt * 8] = lo;
    }
}

// ---------------------------------------------------------------------------
// prep: fused x split + 4 weight transposes + rope table (sections on blockIdx.x)
// ---------------------------------------------------------------------------
__device__ __forceinline__ void convT_body(const float* __restrict__ W,
        __nv_bfloat16* __restrict__ thi, __nv_bfloat16* __restrict__ tlo,
        int Kd, int Nd, int idx, int tid, float (*Ts)[33]) {
    int nt = idx % (Nd / 32), kt = idx / (Nd / 32);
    int k0 = kt * 32, n0 = nt * 32;
    int r = tid >> 3, c4 = (tid & 7) * 4;
    float4 v = *(const float4*)&W[(size_t)(k0 + r) * Nd + n0 + c4];
    Ts[r][c4] = v.x; Ts[r][c4 + 1] = v.y; Ts[r][c4 + 2] = v.z; Ts[r][c4 + 3] = v.w;
    __syncthreads();
    #pragma unroll
    for (int j = 0; j < 4; j++) {
        float x = Ts[c4 + j][r];
        __nv_bfloat16 h = __float2bfloat16(x);
        size_t o = (size_t)(n0 + r) * Kd + k0 + c4 + j;
        thi[o] = h;
        tlo[o] = __float2bfloat16(x - __bfloat162float(h));
    }
}

__global__ __launch_bounds__(256) void prep(const float* __restrict__ x,
        const float* __restrict__ Wq, const float* __restrict__ Wk,
        const float* __restrict__ Wv, const float* __restrict__ Wo) {
    __shared__ float Ts[32][33];
    int bx = blockIdx.x, tid = threadIdx.x;
    if (bx < 4096) {                       // x hi/lo split
        int i = (bx * 256 + tid) * 4;
        float4 v = *(const float4*)(x + i);
        float vv[4] = {v.x, v.y, v.z, v.w};
        #pragma unroll
        for (int j = 0; j < 4; j++) {
            __nv_bfloat16 h = __float2bfloat16(vv[j]);
            g_xhi[i + j] = h;
            g_xlo[i + j] = __float2bfloat16(vv[j] - __bfloat162float(h));
        }
    } else if (bx < 5120) {
        convT_body(Wq, g_wt_hi, g_wt_lo, DD, DD, bx - 4096, tid, Ts);
    } else if (bx < 5376) {
        convT_body(Wk, g_wt_hi + (size_t)NH * HD * DD, g_wt_lo + (size_t)NH * HD * DD,
                   DD, NKV * HD, bx - 5120, tid, Ts);
    } else if (bx < 5632) {
        convT_body(Wv, g_wt_hi + (size_t)(NH + NKV) * HD * DD,
                   g_wt_lo + (size_t)(NH + NKV) * HD * DD, DD, NKV * HD, bx - 5376, tid, Ts);
    } else if (bx < 6656) {
        convT_body(Wo, g_wot_hi, g_wot_lo, DD, DD, bx - 5632, tid, Ts);
    } else {                               // rope table
        int idx = (bx - 6656) * 256 + tid;
        int t = idx >> 5, pair = idx & 31;
        float freq = (float)pow(500000.0, -(double)pair / 32.0);
        float ang = (float)t * freq;
        g_cos[idx] = (float)cos((double)ang);
        g_sin[idx] = (float)sin((double)ang);
    }
}

// ---------------------------------------------------------------------------
extern "C" void kernel_launch(void* const* d_in, const int* in_sizes, int n_in,
                              void* d_out, int out_size) {
    const float* x  = (const float*)d_in[0];
    // d_in[1] = causal mask — handled analytically
    const float* Wq = (const float*)d_in[2];
    const float* Wk = (const float*)d_in[3];
    const float* Wv = (const float*)d_in[4];
    const float* Wo = (const float*)d_in[5];
    float* out = (float*)d_out;

    __nv_bfloat16 *xhi, *xlo, *ahi, *alo, *wth, *wtl, *woh, *wol;
    __nv_bfloat16 *qhi, *qlo, *khi, *klo;
    __half *v16;
    cudaGetSymbolAddress((void**)&xhi, g_xhi);
    cudaGetSymbolAddress((void**)&xlo, g_xlo);
    cudaGetSymbolAddress((void**)&ahi, g_ahi);
    cudaGetSymbolAddress((void**)&alo, g_alo);
    cudaGetSymbolAddress((void**)&wth, g_wt_hi);
    cudaGetSymbolAddress((void**)&wtl, g_wt_lo);
    cudaGetSymbolAddress((void**)&woh, g_wot_hi);
    cudaGetSymbolAddress((void**)&wol, g_wot_lo);
    cudaGetSymbolAddress((void**)&qhi, g_qhi);
    cudaGetSymbolAddress((void**)&qlo, g_qlo);
    cudaGetSymbolAddress((void**)&khi, g_khi);
    cudaGetSymbolAddress((void**)&klo, g_klo);
    cudaGetSymbolAddress((void**)&v16, g_v16);

    cudaFuncSetAttribute(gemm_mma<0>, cudaFuncAttributeMaxDynamicSharedMemorySize, 196608);
    cudaFuncSetAttribute(gemm_mma<1>, cudaFuncAttributeMaxDynamicSharedMemorySize, 196608);
    cudaFuncSetAttribute(attn_mma, cudaFuncAttributeMaxDynamicSharedMemorySize, 106496);

    prep<<<6912, 256>>>(x, Wq, Wk, Wv, Wo);

    // fused QKV projection + RoPE/split/V-fp16 epilogue
    gemm_mma<1><<<dim3(NQKV / 128, MM / 128), 256, 196608>>>(xhi, xlo, wth, wtl,
                                                             nullptr, MM, NQKV, DD);

    attn_mma<<<dim3(TT / 128, BB * NH), 256, 106496>>>(qhi, qlo, khi, klo,
                                                       v16, ahi, alo);

    gemm_mma<0><<<dim3(DD / 128, MM / 128), 256, 196608>>>(ahi, alo, woh, wol,
                                                           out, MM, DD, DD);
}

// round 9
// speedup vs baseline: 1.1317x; 1.1317x over previous
#include <cuda_runtime.h>
#include <cuda_bf16.h>
#include <cuda_fp16.h>
#include <math.h>
#include <stdint.h>

#define BB 2
#define TT 2048
#define DD 1024
#define NH 16
#define NKV 4
#define HD 64
#define NREP 4           // NH / NKV
#define MM (BB*TT)       // 4096
#define NQKV (NH*HD + 2*NKV*HD)   // 1536 fused QKV output width

// ---------------- scratch (device globals; no runtime allocation) -----------
__device__ __align__(16) float g_cos[TT*32];
__device__ __align__(16) float g_sin[TT*32];
__device__ __nv_bfloat16 g_xhi[MM*DD],  g_xlo[MM*DD];
__device__ __nv_bfloat16 g_wt_hi[NQKV*DD], g_wt_lo[NQKV*DD];   // fused QKV weights^T [N][K]
__device__ __half g_wo16[DD*DD];            // Wo^T fp16 [N][K]
__device__ __nv_bfloat16 g_qhi[BB*NH*TT*HD],  g_qlo[BB*NH*TT*HD];   // [b][h][t][d]
__device__ __nv_bfloat16 g_khi[BB*NKV*TT*HD], g_klo[BB*NKV*TT*HD];  // [b][kvh][t][d]
__device__ __half g_v16[BB*NKV*TT*HD];      // V fp16 [b][kvh][t][d]
__device__ __half g_a16[MM*DD];             // attention out fp16

// ---------------- helpers ----------------------------------------------------
__device__ __forceinline__ uint32_t smem_u32(const void* p) {
    uint32_t a;
    asm("{ .reg .u64 t; cvta.to.shared.u64 t, %1; cvt.u32.u64 %0, t; }"
        : "=r"(a) : "l"(p));
    return a;
}
#define SWZ(off) ((off) ^ (((off) >> 3) & 0x70))

#define CP_ASYNC16(dst, src) \
    asm volatile("cp.async.cg.shared.global [%0], [%1], 16;" \
                 :: "r"(dst), "l"(src) : "memory")
#define CP_COMMIT() asm volatile("cp.async.commit_group;" ::: "memory")
#define CP_WAIT(n)  asm volatile("cp.async.wait_group %0;" :: "n"(n) : "memory")

#define LDSM4(r0, r1, r2, r3, addr) \
    asm volatile("ldmatrix.sync.aligned.m8n8.x4.shared.b16 {%0,%1,%2,%3}, [%4];" \
                 : "=r"(r0), "=r"(r1), "=r"(r2), "=r"(r3) : "r"(addr))

#define LDSM4T(r0, r1, r2, r3, addr) \
    asm volatile("ldmatrix.sync.aligned.m8n8.x4.trans.shared.b16 {%0,%1,%2,%3}, [%4];" \
                 : "=r"(r0), "=r"(r1), "=r"(r2), "=r"(r3) : "r"(addr))

#define MMAS(c, a, b0, b1) \
    asm volatile("mma.sync.aligned.m16n8k16.row.col.f32.bf16.bf16.f32 " \
                 "{%0,%1,%2,%3}, {%4,%5,%6,%7}, {%8,%9}, {%0,%1,%2,%3};" \
                 : "+f"((c)[0]), "+f"((c)[1]), "+f"((c)[2]), "+f"((c)[3]) \
                 : "r"((a)[0]), "r"((a)[1]), "r"((a)[2]), "r"((a)[3]), \
                   "r"(b0), "r"(b1))

#define MMAH(c, a, b0, b1) \
    asm volatile("mma.sync.aligned.m16n8k16.row.col.f32.f16.f16.f32 " \
                 "{%0,%1,%2,%3}, {%4,%5,%6,%7}, {%8,%9}, {%0,%1,%2,%3};" \
                 : "+f"((c)[0]), "+f"((c)[1]), "+f"((c)[2]), "+f"((c)[3]) \
                 : "r"((a)[0]), "r"((a)[1]), "r"((a)[2]), "r"((a)[3]), \
                   "r"(b0), "r"(b1))

__device__ __forceinline__ void split2(float x0, float x1, uint32_t& hi, uint32_t& lo) {
    __nv_bfloat16 h0 = __float2bfloat16(x0), h1 = __float2bfloat16(x1);
    float r0 = x0 - __bfloat162float(h0), r1 = x1 - __bfloat162float(h1);
    __nv_bfloat162 H; H.x = h0; H.y = h1;
    __nv_bfloat162 L = __floats2bfloat162_rn(r0, r1);
    hi = *(uint32_t*)&H; lo = *(uint32_t*)&L;
}

__device__ __forceinline__ uint32_t packh(float a, float b) {
    __half2 h = __floats2half2_rn(a, b);
    return *(uint32_t*)&h;
}

// ---------------------------------------------------------------------------
// QKV GEMM: split-bf16 3-term, 128x128 tile, BK=64, 3-stage cp.async.
// Fused epilogue: RoPE (smem-staged cos/sin) + bf16 hi/lo split for Q/K,
// fp16 pack for V. Writes g_qhi/qlo, g_khi/klo, g_v16.
// ---------------------------------------------------------------------------
__global__ __launch_bounds__(256, 1) void gemm_qkv(
        const __nv_bfloat16* __restrict__ Ahi, const __nv_bfloat16* __restrict__ Alo,
        const __nv_bfloat16* __restrict__ Bhi, const __nv_bfloat16* __restrict__ Blo,
        int M, int N, int K) {
    extern __shared__ char smem[];
    uint32_t sbase = smem_u32(smem);
    int tid = threadIdx.x, wid = tid >> 5, lid = tid & 31;
    int m0 = blockIdx.y * 128, n0 = blockIdx.x * 128;
    int wm = wid & 1, wn = wid >> 1;
    const int nch = K / 64;
    const int rr = tid >> 3;
    const int uu = tid & 7;

    float acc[4][4][4] = {};

    auto load_chunk = [&](int buf, int ch) {
        int k0 = ch * 64;
        uint32_t dbase = sbase + (uint32_t)buf * 65536u;
        #pragma unroll
        for (int arr = 0; arr < 4; arr++) {
            const __nv_bfloat16* s = (arr == 0) ? Ahi : (arr == 1) ? Alo
                                    : (arr == 2) ? Bhi : Blo;
            int rb = (arr < 2) ? m0 : n0;
            uint32_t ab = dbase + (uint32_t)arr * 16384u;
            #pragma unroll
            for (int it = 0; it < 4; it++) {
                int r = it * 32 + rr;
                CP_ASYNC16(ab + SWZ(r * 128 + uu * 16),
                           s + (size_t)(rb + r) * K + k0 + uu * 8);
            }
        }
        CP_COMMIT();
    };

    load_chunk(0, 0);
    load_chunk(1, 1);

    for (int ch = 0; ch < nch; ch++) {
        if (ch < nch - 1) { CP_WAIT(1); } else { CP_WAIT(0); }
        __syncthreads();
        if (ch + 2 < nch) load_chunk((ch + 2) % 3, ch + 2);

        uint32_t db = sbase + (uint32_t)(ch % 3) * 65536u;
        uint32_t abh = db, abl = db + 16384u;
        uint32_t bbh = db + 32768u, bbl = db + 49152u;
        int g = lid >> 3, w8 = lid & 7;

        #pragma unroll
        for (int ks = 0; ks < 4; ks++) {
            uint32_t ah[4][4], al[4][4], bh[4][2], bl[4][2];
            int arow = wm * 64 + (lid & 15);
            int acol = ks * 32 + (lid >> 4) * 16;
            #pragma unroll
            for (int mi = 0; mi < 4; mi++) {
                uint32_t off = SWZ((arow + mi * 16) * 128 + acol);
                LDSM4(ah[mi][0], ah[mi][1], ah[mi][2], ah[mi][3], abh + off);
                LDSM4(al[mi][0], al[mi][1], al[mi][2], al[mi][3], abl + off);
            }
            #pragma unroll
            for (int p = 0; p < 2; p++) {
                int nrow = wn * 32 + p * 16 + (g >> 1) * 8 + w8;
                int ncol = ks * 32 + (g & 1) * 16;
                uint32_t off = SWZ(nrow * 128 + ncol);
                LDSM4(bh[2*p][0], bh[2*p][1], bh[2*p+1][0], bh[2*p+1][1], bbh + off);
                LDSM4(bl[2*p][0], bl[2*p][1], bl[2*p+1][0], bl[2*p+1][1], bbl + off);
            }
            #pragma unroll
            for (int mi = 0; mi < 4; mi++)
                #pragma unroll
                for (int ni = 0; ni < 4; ni++) {
                    MMAS(acc[mi][ni], ah[mi], bh[ni][0], bh[ni][1]);
                    MMAS(acc[mi][ni], ah[mi], bl[ni][0], bl[ni][1]);
                    MMAS(acc[mi][ni], al[mi], bh[ni][0], bh[ni][1]);
                }
        }
        __syncthreads();
    }

    // ---- fused epilogue ----
    // cols [0,1024)=Q, [1024,1280)=K, [1280,1536)=V (uniform per CTA)
    int region = (blockIdx.x < 8) ? 0 : (blockIdx.x < 10) ? 1 : 2;
    float* cs_s = (float*)smem;               // 16KB: cos[128][32]
    float* sn_s = (float*)(smem + 16384);     // 16KB: sin[128][32]
    if (region < 2) {
        // stage this CTA's 128-row cos/sin slab (coalesced; buffers are dead)
        int tbase = m0 & (TT - 1);
        #pragma unroll
        for (int i = 0; i < 4; i++) {
            int idx = i * 256 + tid;          // 1024 float4 per table
            *(float4*)(smem + idx * 16) =
                *(const float4*)&g_cos[(size_t)tbase * 32 + idx * 4];
            *(float4*)(smem + 16384 + idx * 16) =
                *(const float4*)&g_sin[(size_t)tbase * 32 + idx * 4];
        }
        __syncthreads();
    }
    #pragma unroll
    for (int mi = 0; mi < 4; mi++) {
        int row = m0 + wm * 64 + mi * 16 + (lid >> 2);
        #pragma unroll
        for (int r2 = 0; r2 < 2; r2++) {
            int trow = row + r2 * 8;
            int b = trow >> 11, t = trow & (TT - 1);
            int tl = trow - m0;               // local row for smem tables
            #pragma unroll
            for (int ni = 0; ni < 4; ni++) {
                int c = n0 + wn * 32 + ni * 8 + (lid & 3) * 2;
                float v0 = acc[mi][ni][r2 * 2], v1 = acc[mi][ni][r2 * 2 + 1];
                if (region == 2) {
                    int cc = c - 1280;
                    int kvh = cc >> 6, d = cc & 63;
                    *(uint32_t*)&g_v16[((size_t)(b * NKV + kvh) * TT + t) * HD + d] =
                        packh(v0, v1);
                } else {
                    int cc = (region == 1) ? c - 1024 : c;
                    int hh = cc >> 6, d = cc & 63;
                    int ci = tl * 32 + (d >> 1);
                    float cs = cs_s[ci], sn = sn_s[ci];
                    float r0 = v0 * cs - v1 * sn;
                    float r1 = v1 * cs + v0 * sn;
                    uint32_t hi, lo;
                    split2(r0, r1, hi, lo);
                    if (region == 1) {
                        size_t o = ((size_t)(b * NKV + hh) * TT + t) * HD + d;
                        *(uint32_t*)&g_khi[o] = hi;
                        *(uint32_t*)&g_klo[o] = lo;
                    } else {
                        size_t o = ((size_t)(b * NH + hh) * TT + t) * HD + d;
                        *(uint32_t*)&g_qhi[o] = hi;
                        *(uint32_t*)&g_qlo[o] = lo;
                    }
                }
            }
        }
    }
}

// ---------------------------------------------------------------------------
// O-projection GEMM: single-term fp16 x fp16 (fp32 acc).
// A = g_a16 [M][K], B = g_wo16 [N][K]. 128x128 tile, 3-stage (3 x 32KB).
// ---------------------------------------------------------------------------
__global__ __launch_bounds__(256, 1) void gemm_out(
        const __half* __restrict__ A, const __half* __restrict__ B,
        float* __restrict__ C, int M, int N, int K) {
    extern __shared__ char smem[];
    uint32_t sbase = smem_u32(smem);
    int tid = threadIdx.x, wid = tid >> 5, lid = tid & 31;
    int m0 = blockIdx.y * 128, n0 = blockIdx.x * 128;
    int wm = wid & 1, wn = wid >> 1;
    const int nch = K / 64;
    const int rr = tid >> 3, uu = tid & 7;

    float acc[4][4][4] = {};

    auto load_chunk = [&](int buf, int ch) {
        int k0 = ch * 64;
        uint32_t dbase = sbase + (uint32_t)buf * 32768u;
        #pragma unroll
        for (int arr = 0; arr < 2; arr++) {
            const __half* s = arr ? B : A;
            int rb = arr ? n0 : m0;
            uint32_t ab = dbase + (uint32_t)arr * 16384u;
            #pragma unroll
            for (int it = 0; it < 4; it++) {
                int r = it * 32 + rr;
                CP_ASYNC16(ab + SWZ(r * 128 + uu * 16),
                           s + (size_t)(rb + r) * K + k0 + uu * 8);
            }
        }
        CP_COMMIT();
    };

    load_chunk(0, 0);
    load_chunk(1, 1);

    for (int ch = 0; ch < nch; ch++) {
        if (ch < nch - 1) { CP_WAIT(1); } else { CP_WAIT(0); }
        __syncthreads();
        if (ch + 2 < nch) load_chunk((ch + 2) % 3, ch + 2);

        uint32_t db = sbase + (uint32_t)(ch % 3) * 32768u;
        uint32_t ab_ = db, bb = db + 16384u;
        int g = lid >> 3, w8 = lid & 7;

        #pragma unroll
        for (int ks = 0; ks < 4; ks++) {
            uint32_t ah[4][4], bh[4][2];
            int arow = wm * 64 + (lid & 15);
            int acol = ks * 32 + (lid >> 4) * 16;
            #pragma unroll
            for (int mi = 0; mi < 4; mi++) {
                uint32_t off = SWZ((arow + mi * 16) * 128 + acol);
                LDSM4(ah[mi][0], ah[mi][1], ah[mi][2], ah[mi][3], ab_ + off);
            }
            #pragma unroll
            for (int p = 0; p < 2; p++) {
                int nrow = wn * 32 + p * 16 + (g >> 1) * 8 + w8;
                uint32_t off = SWZ(nrow * 128 + ks * 32 + (g & 1) * 16);
                LDSM4(bh[2*p][0], bh[2*p][1], bh[2*p+1][0], bh[2*p+1][1], bb + off);
            }
            #pragma unroll
            for (int mi = 0; mi < 4; mi++)
                #pragma unroll
                for (int ni = 0; ni < 4; ni++)
                    MMAH(acc[mi][ni], ah[mi], bh[ni][0], bh[ni][1]);
        }
        __syncthreads();
    }

    #pragma unroll
    for (int mi = 0; mi < 4; mi++) {
        int row = m0 + wm * 64 + mi * 16 + (lid >> 2);
        #pragma unroll
        for (int ni = 0; ni < 4; ni++) {
            int col = n0 + wn * 32 + ni * 8 + (lid & 3) * 2;
            *(float2*)&C[(size_t)row * N + col] =
                make_float2(acc[mi][ni][0], acc[mi][ni][1]);
            *(float2*)&C[(size_t)(row + 8) * N + col] =
                make_float2(acc[mi][ni][2], acc[mi][ni][3]);
        }
    }
}

// ---------------------------------------------------------------------------
// HMMA flash attention, causal. Grid (T/128 reversed, B*NH), 256 threads.
// S = QK^T 3-term split bf16; PV fp16 with V untransposed (ldmatrix.trans).
// 3-stage cp.async; exp2 softmax with corr-skip; fp16 output.
// ---------------------------------------------------------------------------
__global__ __launch_bounds__(256, 1) void attn_mma(
        const __nv_bfloat16* __restrict__ Qhi, const __nv_bfloat16* __restrict__ Qlo,
        const __nv_bfloat16* __restrict__ Khi, const __nv_bfloat16* __restrict__ Klo,
        const __half* __restrict__ Vt, __half* __restrict__ Oh) {
    extern __shared__ char smem[];
    uint32_t sbase = smem_u32(smem);
    const uint32_t QHI = 0, QLO = 16384, BUF = 32768;   // 3 x 24KB chunk buffers

    int tid = threadIdx.x, wid = tid >> 5, lid = tid & 31;
    int qt = gridDim.x - 1 - blockIdx.x;
    int bh = blockIdx.y;
    int b = bh / NH, h = bh % NH, kvh = h / NREP;
    int q0 = qt * 128;

    const __nv_bfloat16* qbh = Qhi + (size_t)(b * NH + h) * TT * HD;
    const __nv_bfloat16* qbl = Qlo + (size_t)(b * NH + h) * TT * HD;
    const __nv_bfloat16* kbh = Khi + (size_t)(b * NKV + kvh) * TT * HD;
    const __nv_bfloat16* kbl = Klo + (size_t)(b * NKV + kvh) * TT * HD;
    const __half* vbase = Vt + (size_t)(b * NKV + kvh) * TT * HD;   // [t][d]

    // stage Q (own commit group)
    {
        #pragma unroll
        for (int arr = 0; arr < 2; arr++) {
            const __nv_bfloat16* s = arr ? qbl : qbh;
            uint32_t ab = sbase + (arr ? QLO : QHI);
            #pragma unroll
            for (int it = 0; it < 4; it++) {
                int idx = it * 256 + tid;
                int r = idx >> 3, u = idx & 7;
                CP_ASYNC16(ab + SWZ(r * 128 + u * 16),
                           s + (size_t)(q0 + r) * HD + u * 8);
            }
        }
        CP_COMMIT();
    }

    auto load_chunk = [&](int buf, int kt) {
        uint32_t db = sbase + BUF + (uint32_t)buf * 24576u;
        #pragma unroll
        for (int arr = 0; arr < 3; arr++) {
            uint32_t ab = db + (uint32_t)arr * 8192u;
            #pragma unroll
            for (int it = 0; it < 2; it++) {
                int idx = it * 256 + tid;
                int r = idx >> 3, u = idx & 7;
                const char* src;
                if (arr == 0)      src = (const char*)(kbh + (size_t)(kt * 64 + r) * HD + u * 8);
                else if (arr == 1) src = (const char*)(kbl + (size_t)(kt * 64 + r) * HD + u * 8);
                else               src = (const char*)(vbase + (size_t)(kt * 64 + r) * HD + u * 8);
                CP_ASYNC16(ab + SWZ(r * 128 + u * 16), src);
            }
        }
        CP_COMMIT();
    };

    int nch = 2 * qt + 2;
    load_chunk(0, 0);
    load_chunk(1, 1);

    CP_WAIT(2);
    __syncthreads();
    uint32_t qfh[4][4], qfl[4][4];
    {
        int arow = wid * 16 + (lid & 15);
        #pragma unroll
        for (int ks = 0; ks < 4; ks++) {
            uint32_t off = SWZ(arow * 128 + ks * 32 + (lid >> 4) * 16);
            LDSM4(qfh[ks][0], qfh[ks][1], qfh[ks][2], qfh[ks][3], sbase + QHI + off);
            LDSM4(qfl[ks][0], qfl[ks][1], qfl[ks][2], qfl[ks][3], sbase + QLO + off);
        }
    }

    float oacc[8][4] = {};
    float mA = -1e30f, mB = -1e30f, lA = 0.f, lB = 0.f;
    const int g = lid >> 3, w8 = lid & 7;
    const int qrA = q0 + wid * 16 + (lid >> 2);
    const float SC = 0.125f * 1.4426950408889634f;   // scale * log2(e)
    const int vrow16 = lid & 15, vhi16 = (lid >> 4) & 1;

    for (int ch = 0; ch < nch; ch++) {
        if (ch < nch - 1) { CP_WAIT(1); } else { CP_WAIT(0); }
        __syncthreads();
        if (ch + 2 < nch) load_chunk((ch + 2) % 3, ch + 2);

        int kt = ch;
        bool active = (kt * 64 <= q0 + wid * 16 + 15);
        if (active) {
            uint32_t kb = sbase + BUF + (uint32_t)(ch % 3) * 24576u;
            uint32_t vb = kb + 16384u;

            // ---- S = Q K^T (3-term split bf16) ----
            float sacc[8][4] = {};
            #pragma unroll
            for (int ks = 0; ks < 4; ks++) {
                #pragma unroll
                for (int p = 0; p < 4; p++) {
                    int nrow = p * 16 + (g >> 1) * 8 + w8;
                    uint32_t off = SWZ(nrow * 128 + ks * 32 + (g & 1) * 16);
                    uint32_t b0, b1, b2, b3, c0, c1, c2, c3;
                    LDSM4(b0, b1, b2, b3, kb + off);
                    LDSM4(c0, c1, c2, c3, kb + 8192u + off);
                    MMAS(sacc[2*p],   qfh[ks], b0, b1);
                    MMAS(sacc[2*p+1], qfh[ks], b2, b3);
                    MMAS(sacc[2*p],   qfh[ks], c0, c1);
                    MMAS(sacc[2*p+1], qfh[ks], c2, c3);
                    MMAS(sacc[2*p],   qfl[ks], b0, b1);
                    MMAS(sacc[2*p+1], qfl[ks], b2, b3);
                }
            }

            // ---- scale (log2 domain) + causal mask ----
            #pragma unroll
            for (int nt = 0; nt < 8; nt++) {
                int kc = kt * 64 + nt * 8 + (lid & 3) * 2;
                #pragma unroll
                for (int j = 0; j < 4; j++) sacc[nt][j] *= SC;
                if (kc > qrA)         sacc[nt][0] = -1e9f;
                if (kc + 1 > qrA)     sacc[nt][1] = -1e9f;
                if (kc > qrA + 8)     sacc[nt][2] = -1e9f;
                if (kc + 1 > qrA + 8) sacc[nt][3] = -1e9f;
            }

            // ---- online softmax (base-2) with corr-skip ----
            float rmA = -1e30f, rmB = -1e30f;
            #pragma unroll
            for (int nt = 0; nt < 8; nt++) {
                rmA = fmaxf(rmA, fmaxf(sacc[nt][0], sacc[nt][1]));
                rmB = fmaxf(rmB, fmaxf(sacc[nt][2], sacc[nt][3]));
            }
            rmA = fmaxf(rmA, __shfl_xor_sync(0xffffffffu, rmA, 1));
            rmA = fmaxf(rmA, __shfl_xor_sync(0xffffffffu, rmA, 2));
            rmB = fmaxf(rmB, __shfl_xor_sync(0xffffffffu, rmB, 1));
            rmB = fmaxf(rmB, __shfl_xor_sync(0xffffffffu, rmB, 2));
            float mnA = fmaxf(mA, rmA), mnB = fmaxf(mB, rmB);
            float corrA = 1.f, corrB = 1.f;
            if (mnA > mA || mnB > mB) {
                corrA = exp2f(mA - mnA);
                corrB = exp2f(mB - mnB);
                #pragma unroll
                for (int nt = 0; nt < 8; nt++) {
                    oacc[nt][0] *= corrA; oacc[nt][1] *= corrA;
                    oacc[nt][2] *= corrB; oacc[nt][3] *= corrB;
                }
            }
            mA = mnA; mB = mnB;
            float rsA = 0.f, rsB = 0.f;
            #pragma unroll
            for (int nt = 0; nt < 8; nt++) {
                sacc[nt][0] = exp2f(sacc[nt][0] - mA);
                sacc[nt][1] = exp2f(sacc[nt][1] - mA);
                sacc[nt][2] = exp2f(sacc[nt][2] - mB);
                sacc[nt][3] = exp2f(sacc[nt][3] - mB);
                rsA += sacc[nt][0] + sacc[nt][1];
                rsB += sacc[nt][2] + sacc[nt][3];
            }
            rsA += __shfl_xor_sync(0xffffffffu, rsA, 1);
            rsA += __shfl_xor_sync(0xffffffffu, rsA, 2);
            rsB += __shfl_xor_sync(0xffffffffu, rsB, 1);
            rsB += __shfl_xor_sync(0xffffffffu, rsB, 2);
            lA = lA * corrA + rsA;
            lB = lB * corrB + rsB;

            // ---- O += P V (fp16; V untransposed via ldmatrix.trans) ----
            #pragma unroll
            for (int k2 = 0; k2 < 4; k2++) {
                uint32_t pa[4];
                pa[0] = packh(sacc[2*k2][0],   sacc[2*k2][1]);
                pa[1] = packh(sacc[2*k2][2],   sacc[2*k2][3]);
                pa[2] = packh(sacc[2*k2+1][0], sacc[2*k2+1][1]);
                pa[3] = packh(sacc[2*k2+1][2], sacc[2*k2+1][3]);
                #pragma unroll
                for (int p = 0; p < 4; p++) {
                    uint32_t off = SWZ((k2 * 16 + vrow16) * 128 + p * 32 + vhi16 * 16);
                    uint32_t b0, b1, b2, b3;
                    LDSM4T(b0, b1, b2, b3, vb + off);
                    MMAH(oacc[2*p],   pa, b0, b1);
                    MMAH(oacc[2*p+1], pa, b2, b3);
                }
            }
        }
        __syncthreads();
    }

    // ---- epilogue: normalize, fp16 store ----
    float invA = 1.f / lA, invB = 1.f / lB;
    size_t rowA = (size_t)(b * TT + qrA);
    size_t rowB = rowA + 8;
    int colb = h * HD + (lid & 3) * 2;
    #pragma unroll
    for (int nt = 0; nt < 8; nt++) {
        *(uint32_t*)&Oh[rowA * DD + colb + nt * 8] =
            packh(oacc[nt][0] * invA, oacc[nt][1] * invA);
        *(uint32_t*)&Oh[rowB * DD + colb + nt * 8] =
            packh(oacc[nt][2] * invB, oacc[nt][3] * invB);
    }
}

// ---------------------------------------------------------------------------
// prep: x split + QKV weight transposes (bf16 hi/lo) + Wo transpose (fp16) +
// rope table (sections on blockIdx.x)
// ---------------------------------------------------------------------------
__device__ __forceinline__ void convT_body(const float* __restrict__ W,
        __nv_bfloat16* __restrict__ thi, __nv_bfloat16* __restrict__ tlo,
        int Kd, int Nd, int idx, int tid, float (*Ts)[33]) {
    int nt = idx % (Nd / 32), kt = idx / (Nd / 32);
    int k0 = kt * 32, n0 = nt * 32;
    int r = tid >> 3, c4 = (tid & 7) * 4;
    float4 v = *(const float4*)&W[(size_t)(k0 + r) * Nd + n0 + c4];
    Ts[r][c4] = v.x; Ts[r][c4 + 1] = v.y; Ts[r][c4 + 2] = v.z; Ts[r][c4 + 3] = v.w;
    __syncthreads();
    #pragma unroll
    for (int j = 0; j < 4; j++) {
        float x = Ts[c4 + j][r];
        __nv_bfloat16 h = __float2bfloat16(x);
        size_t o = (size_t)(n0 + r) * Kd + k0 + c4 + j;
        thi[o] = h;
        tlo[o] = __float2bfloat16(x - __bfloat162float(h));
    }
}

__device__ __forceinline__ void convT16_body(const float* __restrict__ W,
        __half* __restrict__ t16, int Kd, int Nd, int idx, int tid, float (*Ts)[33]) {
    int nt = idx % (Nd / 32), kt = idx / (Nd / 32);
    int k0 = kt * 32, n0 = nt * 32;
    int r = tid >> 3, c4 = (tid & 7) * 4;
    float4 v = *(const float4*)&W[(size_t)(k0 + r) * Nd + n0 + c4];
    Ts[r][c4] = v.x; Ts[r][c4 + 1] = v.y; Ts[r][c4 + 2] = v.z; Ts[r][c4 + 3] = v.w;
    __syncthreads();
    #pragma unroll
    for (int j = 0; j < 4; j++) {
        size_t o = (size_t)(n0 + r) * Kd + k0 + c4 + j;
        t16[o] = __float2half(Ts[c4 + j][r]);
    }
}

__global__ __launch_bounds__(256) void prep(const float* __restrict__ x,
        const float* __restrict__ Wq, const float* __restrict__ Wk,
        const float* __restrict__ Wv, const float* __restrict__ Wo) {
    __shared__ float Ts[32][33];
    int bx = blockIdx.x, tid = threadIdx.x;
    if (bx < 4096) {                       // x hi/lo split
        int i = (bx * 256 + tid) * 4;
        float4 v = *(const float4*)(x + i);
        float vv[4] = {v.x, v.y, v.z, v.w};
        #pragma unroll
        for (int j = 0; j < 4; j++) {
            __nv_bfloat16 h = __float2bfloat16(vv[j]);
            g_xhi[i + j] = h;
            g_xlo[i + j] = __float2bfloat16(vv[j] - __bfloat162float(h));
        }
    } else if (bx < 5120) {
        convT_body(Wq, g_wt_hi, g_wt_lo, DD, DD, bx - 4096, tid, Ts);
    } else if (bx < 5376) {
        convT_body(Wk, g_wt_hi + (size_t)NH * HD * DD, g_wt_lo + (size_t)NH * HD * DD,
                   DD, NKV * HD, bx - 5120, tid, Ts);
    } else if (bx < 5632) {
        convT_body(Wv, g_wt_hi + (size_t)(NH + NKV) * HD * DD,
                   g_wt_lo + (size_t)(NH + NKV) * HD * DD, DD, NKV * HD, bx - 5376, tid, Ts);
    } else if (bx < 6656) {
        convT16_body(Wo, g_wo16, DD, DD, bx - 5632, tid, Ts);
    } else {                               // rope table
        int idx = (bx - 6656) * 256 + tid;
        int t = idx >> 5, pair = idx & 31;
        float freq = (float)pow(500000.0, -(double)pair / 32.0);
        float ang = (float)t * freq;
        g_cos[idx] = (float)cos((double)ang);
        g_sin[idx] = (float)sin((double)ang);
    }
}

// ---------------------------------------------------------------------------
extern "C" void kernel_launch(void* const* d_in, const int* in_sizes, int n_in,
                              void* d_out, int out_size) {
    const float* x  = (const float*)d_in[0];
    // d_in[1] = causal mask — handled analytically
    const float* Wq = (const float*)d_in[2];
    const float* Wk = (const float*)d_in[3];
    const float* Wv = (const float*)d_in[4];
    const float* Wo = (const float*)d_in[5];
    float* out = (float*)d_out;

    __nv_bfloat16 *xhi, *xlo, *wth, *wtl;
    __nv_bfloat16 *qhi, *qlo, *khi, *klo;
    __half *v16, *a16, *wo16;
    cudaGetSymbolAddress((void**)&xhi, g_xhi);
    cudaGetSymbolAddress((void**)&xlo, g_xlo);
    cudaGetSymbolAddress((void**)&wth, g_wt_hi);
    cudaGetSymbolAddress((void**)&wtl, g_wt_lo);
    cudaGetSymbolAddress((void**)&qhi, g_qhi);
    cudaGetSymbolAddress((void**)&qlo, g_qlo);
    cudaGetSymbolAddress((void**)&khi, g_khi);
    cudaGetSymbolAddress((void**)&klo, g_klo);
    cudaGetSymbolAddress((void**)&v16, g_v16);
    cudaGetSymbolAddress((void**)&a16, g_a16);
    cudaGetSymbolAddress((void**)&wo16, g_wo16);

    cudaFuncSetAttribute(gemm_qkv, cudaFuncAttributeMaxDynamicSharedMemorySize, 196608);
    cudaFuncSetAttribute(gemm_out, cudaFuncAttributeMaxDynamicSharedMemorySize, 98304);
    cudaFuncSetAttribute(attn_mma, cudaFuncAttributeMaxDynamicSharedMemorySize, 106496);

    prep<<<6912, 256>>>(x, Wq, Wk, Wv, Wo);

    // fused QKV projection + RoPE/split/V-fp16 epilogue
    gemm_qkv<<<dim3(NQKV / 128, MM / 128), 256, 196608>>>(xhi, xlo, wth, wtl,
                                                          MM, NQKV, DD);

    attn_mma<<<dim3(TT / 128, BB * NH), 256, 106496>>>(qhi, qlo, khi, klo,
                                                       v16, a16);

    gemm_out<<<dim3(DD / 128, MM / 128), 256, 98304>>>(a16, wo16, out,
                                                       MM, DD, DD);
}

// round 10
// speedup vs baseline: 1.2078x; 1.0673x over previous
#include <cuda_runtime.h>
#include <cuda_bf16.h>
#include <cuda_fp16.h>
#include <math.h>
#include <stdint.h>

#define BB 2
#define TT 2048
#define DD 1024
#define NH 16
#define NKV 4
#define HD 64
#define NREP 4           // NH / NKV
#define MM (BB*TT)       // 4096
#define NQKV (NH*HD + 2*NKV*HD)   // 1536 fused QKV output width

// ---------------- scratch (device globals; no runtime allocation) -----------
__device__ __align__(16) float g_cos[TT*32];
__device__ __align__(16) float g_sin[TT*32];
__device__ __nv_bfloat16 g_xhi[MM*DD],  g_xlo[MM*DD];
__device__ __nv_bfloat16 g_wt_hi[NQKV*DD], g_wt_lo[NQKV*DD];   // fused QKV weights^T [N][K]
__device__ __half g_wo16[DD*DD];            // Wo^T fp16 [N][K]
__device__ __nv_bfloat16 g_qhi[BB*NH*TT*HD],  g_qlo[BB*NH*TT*HD];   // [b][h][t][d]
__device__ __nv_bfloat16 g_khi[BB*NKV*TT*HD], g_klo[BB*NKV*TT*HD];  // [b][kvh][t][d]
__device__ __half g_v16[BB*NKV*TT*HD];      // V fp16 [b][kvh][t][d]
__device__ __half g_a16[MM*DD];             // attention out fp16

// ---------------- helpers ----------------------------------------------------
__device__ __forceinline__ uint32_t smem_u32(const void* p) {
    uint32_t a;
    asm("{ .reg .u64 t; cvta.to.shared.u64 t, %1; cvt.u32.u64 %0, t; }"
        : "=r"(a) : "l"(p));
    return a;
}
#define SWZ(off) ((off) ^ (((off) >> 3) & 0x70))

#define CP_ASYNC16(dst, src) \
    asm volatile("cp.async.cg.shared.global [%0], [%1], 16;" \
                 :: "r"(dst), "l"(src) : "memory")
#define CP_COMMIT() asm volatile("cp.async.commit_group;" ::: "memory")
#define CP_WAIT(n)  asm volatile("cp.async.wait_group %0;" :: "n"(n) : "memory")

#define LDSM4(r0, r1, r2, r3, addr) \
    asm volatile("ldmatrix.sync.aligned.m8n8.x4.shared.b16 {%0,%1,%2,%3}, [%4];" \
                 : "=r"(r0), "=r"(r1), "=r"(r2), "=r"(r3) : "r"(addr))

#define LDSM4T(r0, r1, r2, r3, addr) \
    asm volatile("ldmatrix.sync.aligned.m8n8.x4.trans.shared.b16 {%0,%1,%2,%3}, [%4];" \
                 : "=r"(r0), "=r"(r1), "=r"(r2), "=r"(r3) : "r"(addr))

#define MMAS(c, a, b0, b1) \
    asm volatile("mma.sync.aligned.m16n8k16.row.col.f32.bf16.bf16.f32 " \
                 "{%0,%1,%2,%3}, {%4,%5,%6,%7}, {%8,%9}, {%0,%1,%2,%3};" \
                 : "+f"((c)[0]), "+f"((c)[1]), "+f"((c)[2]), "+f"((c)[3]) \
                 : "r"((a)[0]), "r"((a)[1]), "r"((a)[2]), "r"((a)[3]), \
                   "r"(b0), "r"(b1))

#define MMAH(c, a, b0, b1) \
    asm volatile("mma.sync.aligned.m16n8k16.row.col.f32.f16.f16.f32 " \
                 "{%0,%1,%2,%3}, {%4,%5,%6,%7}, {%8,%9}, {%0,%1,%2,%3};" \
                 : "+f"((c)[0]), "+f"((c)[1]), "+f"((c)[2]), "+f"((c)[3]) \
                 : "r"((a)[0]), "r"((a)[1]), "r"((a)[2]), "r"((a)[3]), \
                   "r"(b0), "r"(b1))

__device__ __forceinline__ void split2(float x0, float x1, uint32_t& hi, uint32_t& lo) {
    __nv_bfloat16 h0 = __float2bfloat16(x0), h1 = __float2bfloat16(x1);
    float r0 = x0 - __bfloat162float(h0), r1 = x1 - __bfloat162float(h1);
    __nv_bfloat162 H; H.x = h0; H.y = h1;
    __nv_bfloat162 L = __floats2bfloat162_rn(r0, r1);
    hi = *(uint32_t*)&H; lo = *(uint32_t*)&L;
}

__device__ __forceinline__ uint32_t packh(float a, float b) {
    __half2 h = __floats2half2_rn(a, b);
    return *(uint32_t*)&h;
}

// ---------------------------------------------------------------------------
// QKV GEMM: split-bf16 3-term, 128x128 tile, BK=64, 3-stage cp.async.
// Fused epilogue: RoPE (smem-staged cos/sin) + bf16 hi/lo split for Q/K,
// fp16 pack for V. Writes g_qhi/qlo, g_khi/klo, g_v16.
// ---------------------------------------------------------------------------
__global__ __launch_bounds__(256, 1) void gemm_qkv(
        const __nv_bfloat16* __restrict__ Ahi, const __nv_bfloat16* __restrict__ Alo,
        const __nv_bfloat16* __restrict__ Bhi, const __nv_bfloat16* __restrict__ Blo,
        int M, int N, int K) {
    extern __shared__ char smem[];
    uint32_t sbase = smem_u32(smem);
    int tid = threadIdx.x, wid = tid >> 5, lid = tid & 31;
    int m0 = blockIdx.y * 128, n0 = blockIdx.x * 128;
    int wm = wid & 1, wn = wid >> 1;
    const int nch = K / 64;
    const int rr = tid >> 3;
    const int uu = tid & 7;

    float acc[4][4][4] = {};

    auto load_chunk = [&](int buf, int ch) {
        int k0 = ch * 64;
        uint32_t dbase = sbase + (uint32_t)buf * 65536u;
        #pragma unroll
        for (int arr = 0; arr < 4; arr++) {
            const __nv_bfloat16* s = (arr == 0) ? Ahi : (arr == 1) ? Alo
                                    : (arr == 2) ? Bhi : Blo;
            int rb = (arr < 2) ? m0 : n0;
            uint32_t ab = dbase + (uint32_t)arr * 16384u;
            #pragma unroll
            for (int it = 0; it < 4; it++) {
                int r = it * 32 + rr;
                CP_ASYNC16(ab + SWZ(r * 128 + uu * 16),
                           s + (size_t)(rb + r) * K + k0 + uu * 8);
            }
        }
        CP_COMMIT();
    };

    load_chunk(0, 0);
    load_chunk(1, 1);

    for (int ch = 0; ch < nch; ch++) {
        if (ch < nch - 1) { CP_WAIT(1); } else { CP_WAIT(0); }
        __syncthreads();
        if (ch + 2 < nch) load_chunk((ch + 2) % 3, ch + 2);

        uint32_t db = sbase + (uint32_t)(ch % 3) * 65536u;
        uint32_t abh = db, abl = db + 16384u;
        uint32_t bbh = db + 32768u, bbl = db + 49152u;
        int g = lid >> 3, w8 = lid & 7;

        #pragma unroll
        for (int ks = 0; ks < 4; ks++) {
            uint32_t ah[4][4], al[4][4], bh[4][2], bl[4][2];
            int arow = wm * 64 + (lid & 15);
            int acol = ks * 32 + (lid >> 4) * 16;
            #pragma unroll
            for (int mi = 0; mi < 4; mi++) {
                uint32_t off = SWZ((arow + mi * 16) * 128 + acol);
                LDSM4(ah[mi][0], ah[mi][1], ah[mi][2], ah[mi][3], abh + off);
                LDSM4(al[mi][0], al[mi][1], al[mi][2], al[mi][3], abl + off);
            }
            #pragma unroll
            for (int p = 0; p < 2; p++) {
                int nrow = wn * 32 + p * 16 + (g >> 1) * 8 + w8;
                int ncol = ks * 32 + (g & 1) * 16;
                uint32_t off = SWZ(nrow * 128 + ncol);
                LDSM4(bh[2*p][0], bh[2*p][1], bh[2*p+1][0], bh[2*p+1][1], bbh + off);
                LDSM4(bl[2*p][0], bl[2*p][1], bl[2*p+1][0], bl[2*p+1][1], bbl + off);
            }
            #pragma unroll
            for (int mi = 0; mi < 4; mi++)
                #pragma unroll
                for (int ni = 0; ni < 4; ni++) {
                    MMAS(acc[mi][ni], ah[mi], bh[ni][0], bh[ni][1]);
                    MMAS(acc[mi][ni], ah[mi], bl[ni][0], bl[ni][1]);
                    MMAS(acc[mi][ni], al[mi], bh[ni][0], bh[ni][1]);
                }
        }
        __syncthreads();
    }

    // ---- fused epilogue ----
    // cols [0,1024)=Q, [1024,1280)=K, [1280,1536)=V (uniform per CTA)
    int region = (blockIdx.x < 8) ? 0 : (blockIdx.x < 10) ? 1 : 2;
    float* cs_s = (float*)smem;               // 16KB: cos[128][32]
    float* sn_s = (float*)(smem + 16384);     // 16KB: sin[128][32]
    if (region < 2) {
        int tbase = m0 & (TT - 1);
        #pragma unroll
        for (int i = 0; i < 4; i++) {
            int idx = i * 256 + tid;          // 1024 float4 per table
            *(float4*)(smem + idx * 16) =
                *(const float4*)&g_cos[(size_t)tbase * 32 + idx * 4];
            *(float4*)(smem + 16384 + idx * 16) =
                *(const float4*)&g_sin[(size_t)tbase * 32 + idx * 4];
        }
        __syncthreads();
    }
    #pragma unroll
    for (int mi = 0; mi < 4; mi++) {
        int row = m0 + wm * 64 + mi * 16 + (lid >> 2);
        #pragma unroll
        for (int r2 = 0; r2 < 2; r2++) {
            int trow = row + r2 * 8;
            int b = trow >> 11, t = trow & (TT - 1);
            int tl = trow - m0;               // local row for smem tables
            #pragma unroll
            for (int ni = 0; ni < 4; ni++) {
                int c = n0 + wn * 32 + ni * 8 + (lid & 3) * 2;
                float v0 = acc[mi][ni][r2 * 2], v1 = acc[mi][ni][r2 * 2 + 1];
                if (region == 2) {
                    int cc = c - 1280;
                    int kvh = cc >> 6, d = cc & 63;
                    *(uint32_t*)&g_v16[((size_t)(b * NKV + kvh) * TT + t) * HD + d] =
                        packh(v0, v1);
                } else {
                    int cc = (region == 1) ? c - 1024 : c;
                    int hh = cc >> 6, d = cc & 63;
                    int ci = tl * 32 + (d >> 1);
                    float cs = cs_s[ci], sn = sn_s[ci];
                    float r0 = v0 * cs - v1 * sn;
                    float r1 = v1 * cs + v0 * sn;
                    uint32_t hi, lo;
                    split2(r0, r1, hi, lo);
                    if (region == 1) {
                        size_t o = ((size_t)(b * NKV + hh) * TT + t) * HD + d;
                        *(uint32_t*)&g_khi[o] = hi;
                        *(uint32_t*)&g_klo[o] = lo;
                    } else {
                        size_t o = ((size_t)(b * NH + hh) * TT + t) * HD + d;
                        *(uint32_t*)&g_qhi[o] = hi;
                        *(uint32_t*)&g_qlo[o] = lo;
                    }
                }
            }
        }
    }
}

// ---------------------------------------------------------------------------
// O-projection GEMM: single-term fp16 x fp16 (fp32 acc).
// 64x128 CTA tile, 128 threads (4 warps, each full-M x 32-N), 3-stage.
// smem 3 x 24KB = 72KB -> 2 CTAs/SM.
// ---------------------------------------------------------------------------
__global__ __launch_bounds__(128, 2) void gemm_out(
        const __half* __restrict__ A, const __half* __restrict__ B,
        float* __restrict__ C, int M, int N, int K) {
    extern __shared__ char smem[];
    uint32_t sbase = smem_u32(smem);
    int tid = threadIdx.x, wid = tid >> 5, lid = tid & 31;
    int m0 = blockIdx.y * 64, n0 = blockIdx.x * 128;
    const int nch = K / 64;
    const int rr = tid >> 3, uu = tid & 7;   // rr 0..15

    float acc[4][4][4] = {};

    auto load_chunk = [&](int buf, int ch) {
        int k0 = ch * 64;
        uint32_t dbase = sbase + (uint32_t)buf * 24576u;
        #pragma unroll
        for (int it = 0; it < 4; it++) {     // A: 64 rows
            int r = it * 16 + rr;
            CP_ASYNC16(dbase + SWZ(r * 128 + uu * 16),
                       A + (size_t)(m0 + r) * K + k0 + uu * 8);
        }
        #pragma unroll
        for (int it = 0; it < 8; it++) {     // B: 128 rows
            int r = it * 16 + rr;
            CP_ASYNC16(dbase + 8192u + SWZ(r * 128 + uu * 16),
                       B + (size_t)(n0 + r) * K + k0 + uu * 8);
        }
        CP_COMMIT();
    };

    load_chunk(0, 0);
    load_chunk(1, 1);

    for (int ch = 0; ch < nch; ch++) {
        if (ch < nch - 1) { CP_WAIT(1); } else { CP_WAIT(0); }
        __syncthreads();
        if (ch + 2 < nch) load_chunk((ch + 2) % 3, ch + 2);

        uint32_t db = sbase + (uint32_t)(ch % 3) * 24576u;
        uint32_t ab_ = db, bb = db + 8192u;
        int g = lid >> 3, w8 = lid & 7;

        #pragma unroll
        for (int ks = 0; ks < 4; ks++) {
            uint32_t ah[4][4], bh[4][2];
            int arow = lid & 15;
            int acol = ks * 32 + (lid >> 4) * 16;
            #pragma unroll
            for (int mi = 0; mi < 4; mi++) {
                uint32_t off = SWZ((arow + mi * 16) * 128 + acol);
                LDSM4(ah[mi][0], ah[mi][1], ah[mi][2], ah[mi][3], ab_ + off);
            }
            #pragma unroll
            for (int p = 0; p < 2; p++) {
                int nrow = wid * 32 + p * 16 + (g >> 1) * 8 + w8;
                uint32_t off = SWZ(nrow * 128 + ks * 32 + (g & 1) * 16);
                LDSM4(bh[2*p][0], bh[2*p][1], bh[2*p+1][0], bh[2*p+1][1], bb + off);
            }
            #pragma unroll
            for (int mi = 0; mi < 4; mi++)
                #pragma unroll
                for (int ni = 0; ni < 4; ni++)
                    MMAH(acc[mi][ni], ah[mi], bh[ni][0], bh[ni][1]);
        }
        __syncthreads();
    }

    #pragma unroll
    for (int mi = 0; mi < 4; mi++) {
        int row = m0 + mi * 16 + (lid >> 2);
        #pragma unroll
        for (int ni = 0; ni < 4; ni++) {
            int col = n0 + wid * 32 + ni * 8 + (lid & 3) * 2;
            *(float2*)&C[(size_t)row * N + col] =
                make_float2(acc[mi][ni][0], acc[mi][ni][1]);
            *(float2*)&C[(size_t)(row + 8) * N + col] =
                make_float2(acc[mi][ni][2], acc[mi][ni][3]);
        }
    }
}

// ---------------------------------------------------------------------------
// HMMA flash attention, causal. 64-query tiles, 128 threads (4 warps),
// grid (T/64 reversed, B*NH). smem: Q 16KB + 3 x 24KB = 88KB -> 2 CTAs/SM.
// S = QK^T 3-term split bf16; PV fp16 with V untransposed (ldmatrix.trans).
// ---------------------------------------------------------------------------
__global__ __launch_bounds__(128, 2) void attn_mma(
        const __nv_bfloat16* __restrict__ Qhi, const __nv_bfloat16* __restrict__ Qlo,
        const __nv_bfloat16* __restrict__ Khi, const __nv_bfloat16* __restrict__ Klo,
        const __half* __restrict__ Vt, __half* __restrict__ Oh) {
    extern __shared__ char smem[];
    uint32_t sbase = smem_u32(smem);
    const uint32_t QHI = 0, QLO = 8192, BUF = 16384;   // 3 x 24KB chunk buffers

    int tid = threadIdx.x, wid = tid >> 5, lid = tid & 31;
    int qt = gridDim.x - 1 - blockIdx.x;
    int bh = blockIdx.y;
    int b = bh / NH, h = bh % NH, kvh = h / NREP;
    int q0 = qt * 64;

    const __nv_bfloat16* qbh = Qhi + (size_t)(b * NH + h) * TT * HD;
    const __nv_bfloat16* qbl = Qlo + (size_t)(b * NH + h) * TT * HD;
    const __nv_bfloat16* kbh = Khi + (size_t)(b * NKV + kvh) * TT * HD;
    const __nv_bfloat16* kbl = Klo + (size_t)(b * NKV + kvh) * TT * HD;
    const __half* vbase = Vt + (size_t)(b * NKV + kvh) * TT * HD;   // [t][d]

    // stage Q (own commit group): 64 rows hi+lo
    {
        #pragma unroll
        for (int arr = 0; arr < 2; arr++) {
            const __nv_bfloat16* s = arr ? qbl : qbh;
            uint32_t ab = sbase + (arr ? QLO : QHI);
            #pragma unroll
            for (int it = 0; it < 4; it++) {
                int idx = it * 128 + tid;
                int r = idx >> 3, u = idx & 7;
                CP_ASYNC16(ab + SWZ(r * 128 + u * 16),
                           s + (size_t)(q0 + r) * HD + u * 8);
            }
        }
        CP_COMMIT();
    }

    auto load_chunk = [&](int buf, int kt) {
        uint32_t db = sbase + BUF + (uint32_t)buf * 24576u;
        #pragma unroll
        for (int arr = 0; arr < 3; arr++) {
            uint32_t ab = db + (uint32_t)arr * 8192u;
            #pragma unroll
            for (int it = 0; it < 4; it++) {
                int idx = it * 128 + tid;
                int r = idx >> 3, u = idx & 7;
                const char* src;
                if (arr == 0)      src = (const char*)(kbh + (size_t)(kt * 64 + r) * HD + u * 8);
                else if (arr == 1) src = (const char*)(kbl + (size_t)(kt * 64 + r) * HD + u * 8);
                else               src = (const char*)(vbase + (size_t)(kt * 64 + r) * HD + u * 8);
                CP_ASYNC16(ab + SWZ(r * 128 + u * 16), src);
            }
        }
        CP_COMMIT();
    };

    int nch = qt + 1;
    load_chunk(0, 0);
    load_chunk(1, (nch > 1) ? 1 : 0);

    CP_WAIT(2);
    __syncthreads();
    uint32_t qfh[4][4], qfl[4][4];
    {
        int arow = wid * 16 + (lid & 15);
        #pragma unroll
        for (int ks = 0; ks < 4; ks++) {
            uint32_t off = SWZ(arow * 128 + ks * 32 + (lid >> 4) * 16);
            LDSM4(qfh[ks][0], qfh[ks][1], qfh[ks][2], qfh[ks][3], sbase + QHI + off);
            LDSM4(qfl[ks][0], qfl[ks][1], qfl[ks][2], qfl[ks][3], sbase + QLO + off);
        }
    }

    float oacc[8][4] = {};
    float mA = -1e30f, mB = -1e30f, lA = 0.f, lB = 0.f;
    const int g = lid >> 3, w8 = lid & 7;
    const int qrA = q0 + wid * 16 + (lid >> 2);
    const float SC = 0.125f * 1.4426950408889634f;   // scale * log2(e)
    const int vrow16 = lid & 15, vhi16 = (lid >> 4) & 1;

    for (int ch = 0; ch < nch; ch++) {
        if (ch < nch - 1) { CP_WAIT(1); } else { CP_WAIT(0); }
        __syncthreads();
        if (ch + 2 < nch) load_chunk((ch + 2) % 3, ch + 2);

        int kt = ch;
        {
            uint32_t kb = sbase + BUF + (uint32_t)(ch % 3) * 24576u;
            uint32_t vb = kb + 16384u;

            // ---- S = Q K^T (3-term split bf16) ----
            float sacc[8][4] = {};
            #pragma unroll
            for (int ks = 0; ks < 4; ks++) {
                #pragma unroll
                for (int p = 0; p < 4; p++) {
                    int nrow = p * 16 + (g >> 1) * 8 + w8;
                    uint32_t off = SWZ(nrow * 128 + ks * 32 + (g & 1) * 16);
                    uint32_t b0, b1, b2, b3, c0, c1, c2, c3;
                    LDSM4(b0, b1, b2, b3, kb + off);
                    LDSM4(c0, c1, c2, c3, kb + 8192u + off);
                    MMAS(sacc[2*p],   qfh[ks], b0, b1);
                    MMAS(sacc[2*p+1], qfh[ks], b2, b3);
                    MMAS(sacc[2*p],   qfh[ks], c0, c1);
                    MMAS(sacc[2*p+1], qfh[ks], c2, c3);
                    MMAS(sacc[2*p],   qfl[ks], b0, b1);
                    MMAS(sacc[2*p+1], qfl[ks], b2, b3);
                }
            }

            // ---- scale (log2 domain) + causal mask ----
            #pragma unroll
            for (int nt = 0; nt < 8; nt++) {
                int kc = kt * 64 + nt * 8 + (lid & 3) * 2;
                #pragma unroll
                for (int j = 0; j < 4; j++) sacc[nt][j] *= SC;
                if (kc > qrA)         sacc[nt][0] = -1e9f;
                if (kc + 1 > qrA)     sacc[nt][1] = -1e9f;
                if (kc > qrA + 8)     sacc[nt][2] = -1e9f;
                if (kc + 1 > qrA + 8) sacc[nt][3] = -1e9f;
            }

            // ---- online softmax (base-2) with corr-skip ----
            float rmA = -1e30f, rmB = -1e30f;
            #pragma unroll
            for (int nt = 0; nt < 8; nt++) {
                rmA = fmaxf(rmA, fmaxf(sacc[nt][0], sacc[nt][1]));
                rmB = fmaxf(rmB, fmaxf(sacc[nt][2], sacc[nt][3]));
            }
            rmA = fmaxf(rmA, __shfl_xor_sync(0xffffffffu, rmA, 1));
            rmA = fmaxf(rmA, __shfl_xor_sync(0xffffffffu, rmA, 2));
            rmB = fmaxf(rmB, __shfl_xor_sync(0xffffffffu, rmB, 1));
            rmB = fmaxf(rmB, __shfl_xor_sync(0xffffffffu, rmB, 2));
            float mnA = fmaxf(mA, rmA), mnB = fmaxf(mB, rmB);
            float corrA = 1.f, corrB = 1.f;
            if (mnA > mA || mnB > mB) {
                corrA = exp2f(mA - mnA);
                corrB = exp2f(mB - mnB);
                #pragma unroll
                for (int nt = 0; nt < 8; nt++) {
                    oacc[nt][0] *= corrA; oacc[nt][1] *= corrA;
                    oacc[nt][2] *= corrB; oacc[nt][3] *= corrB;
                }
            }
            mA = mnA; mB = mnB;
            float rsA = 0.f, rsB = 0.f;
            #pragma unroll
            for (int nt = 0; nt < 8; nt++) {
                sacc[nt][0] = exp2f(sacc[nt][0] - mA);
                sacc[nt][1] = exp2f(sacc[nt][1] - mA);
                sacc[nt][2] = exp2f(sacc[nt][2] - mB);
                sacc[nt][3] = exp2f(sacc[nt][3] - mB);
                rsA += sacc[nt][0] + sacc[nt][1];
                rsB += sacc[nt][2] + sacc[nt][3];
            }
            rsA += __shfl_xor_sync(0xffffffffu, rsA, 1);
            rsA += __shfl_xor_sync(0xffffffffu, rsA, 2);
            rsB += __shfl_xor_sync(0xffffffffu, rsB, 1);
            rsB += __shfl_xor_sync(0xffffffffu, rsB, 2);
            lA = lA * corrA + rsA;
            lB = lB * corrB + rsB;

            // ---- O += P V (fp16; V untransposed via ldmatrix.trans) ----
            #pragma unroll
            for (int k2 = 0; k2 < 4; k2++) {
                uint32_t pa[4];
                pa[0] = packh(sacc[2*k2][0],   sacc[2*k2][1]);
                pa[1] = packh(sacc[2*k2][2],   sacc[2*k2][3]);
                pa[2] = packh(sacc[2*k2+1][0], sacc[2*k2+1][1]);
                pa[3] = packh(sacc[2*k2+1][2], sacc[2*k2+1][3]);
                #pragma unroll
                for (int p = 0; p < 4; p++) {
                    uint32_t off = SWZ((k2 * 16 + vrow16) * 128 + p * 32 + vhi16 * 16);
                    uint32_t b0, b1, b2, b3;
                    LDSM4T(b0, b1, b2, b3, vb + off);
                    MMAH(oacc[2*p],   pa, b0, b1);
                    MMAH(oacc[2*p+1], pa, b2, b3);
                }
            }
        }
        __syncthreads();
    }

    // ---- epilogue: normalize, fp16 store ----
    float invA = 1.f / lA, invB = 1.f / lB;
    size_t rowA = (size_t)(b * TT + qrA);
    size_t rowB = rowA + 8;
    int colb = h * HD + (lid & 3) * 2;
    #pragma unroll
    for (int nt = 0; nt < 8; nt++) {
        *(uint32_t*)&Oh[rowA * DD + colb + nt * 8] =
            packh(oacc[nt][0] * invA, oacc[nt][1] * invA);
        *(uint32_t*)&Oh[rowB * DD + colb + nt * 8] =
            packh(oacc[nt][2] * invB, oacc[nt][3] * invB);
    }
}

// ---------------------------------------------------------------------------
// prep: x split + QKV weight transposes (bf16 hi/lo) + Wo transpose (fp16) +
// rope table (sections on blockIdx.x)
// ---------------------------------------------------------------------------
__device__ __forceinline__ void convT_body(const float* __restrict__ W,
        __nv_bfloat16* __restrict__ thi, __nv_bfloat16* __restrict__ tlo,
        int Kd, int Nd, int idx, int tid, float (*Ts)[33]) {
    int nt = idx % (Nd / 32), kt = idx / (Nd / 32);
    int k0 = kt * 32, n0 = nt * 32;
    int r = tid >> 3, c4 = (tid & 7) * 4;
    float4 v = *(const float4*)&W[(size_t)(k0 + r) * Nd + n0 + c4];
    Ts[r][c4] = v.x; Ts[r][c4 + 1] = v.y; Ts[r][c4 + 2] = v.z; Ts[r][c4 + 3] = v.w;
    __syncthreads();
    #pragma unroll
    for (int j = 0; j < 4; j++) {
        float x = Ts[c4 + j][r];
        __nv_bfloat16 h = __float2bfloat16(x);
        size_t o = (size_t)(n0 + r) * Kd + k0 + c4 + j;
        thi[o] = h;
        tlo[o] = __float2bfloat16(x - __bfloat162float(h));
    }
}

__device__ __forceinline__ void convT16_body(const float* __restrict__ W,
        __half* __restrict__ t16, int Kd, int Nd, int idx, int tid, float (*Ts)[33]) {
    int nt = idx % (Nd / 32), kt = idx / (Nd / 32);
    int k0 = kt * 32, n0 = nt * 32;
    int r = tid >> 3, c4 = (tid & 7) * 4;
    float4 v = *(const float4*)&W[(size_t)(k0 + r) * Nd + n0 + c4];
    Ts[r][c4] = v.x; Ts[r][c4 + 1] = v.y; Ts[r][c4 + 2] = v.z; Ts[r][c4 + 3] = v.w;
    __syncthreads();
    #pragma unroll
    for (int j = 0; j < 4; j++) {
        size_t o = (size_t)(n0 + r) * Kd + k0 + c4 + j;
        t16[o] = __float2half(Ts[c4 + j][r]);
    }
}

__global__ __launch_bounds__(256) void prep(const float* __restrict__ x,
        const float* __restrict__ Wq, const float* __restrict__ Wk,
        const float* __restrict__ Wv, const float* __restrict__ Wo) {
    __shared__ float Ts[32][33];
    int bx = blockIdx.x, tid = threadIdx.x;
    if (bx < 4096) {                       // x hi/lo split
        int i = (bx * 256 + tid) * 4;
        float4 v = *(const float4*)(x + i);
        float vv[4] = {v.x, v.y, v.z, v.w};
        #pragma unroll
        for (int j = 0; j < 4; j++) {
            __nv_bfloat16 h = __float2bfloat16(vv[j]);
            g_xhi[i + j] = h;
            g_xlo[i + j] = __float2bfloat16(vv[j] - __bfloat162float(h));
        }
    } else if (bx < 5120) {
        convT_body(Wq, g_wt_hi, g_wt_lo, DD, DD, bx - 4096, tid, Ts);
    } else if (bx < 5376) {
        convT_body(Wk, g_wt_hi + (size_t)NH * HD * DD, g_wt_lo + (size_t)NH * HD * DD,
                   DD, NKV * HD, bx - 5120, tid, Ts);
    } else if (bx < 5632) {
        convT_body(Wv, g_wt_hi + (size_t)(NH + NKV) * HD * DD,
                   g_wt_lo + (size_t)(NH + NKV) * HD * DD, DD, NKV * HD, bx - 5376, tid, Ts);
    } else if (bx < 6656) {
        convT16_body(Wo, g_wo16, DD, DD, bx - 5632, tid, Ts);
    } else {                               // rope table
        int idx = (bx - 6656) * 256 + tid;
        int t = idx >> 5, pair = idx & 31;
        float freq = (float)pow(500000.0, -(double)pair / 32.0);
        float ang = (float)t * freq;
        g_cos[idx] = (float)cos((double)ang);
        g_sin[idx] = (float)sin((double)ang);
    }
}

// ---------------------------------------------------------------------------
extern "C" void kernel_launch(void* const* d_in, const int* in_sizes, int n_in,
                              void* d_out, int out_size) {
    const float* x  = (const float*)d_in[0];
    // d_in[1] = causal mask — handled analytically
    const float* Wq = (const float*)d_in[2];
    const float* Wk = (const float*)d_in[3];
    const float* Wv = (const float*)d_in[4];
    const float* Wo = (const float*)d_in[5];
    float* out = (float*)d_out;

    __nv_bfloat16 *xhi, *xlo, *wth, *wtl;
    __nv_bfloat16 *qhi, *qlo, *khi, *klo;
    __half *v16, *a16, *wo16;
    cudaGetSymbolAddress((void**)&xhi, g_xhi);
    cudaGetSymbolAddress((void**)&xlo, g_xlo);
    cudaGetSymbolAddress((void**)&wth, g_wt_hi);
    cudaGetSymbolAddress((void**)&wtl, g_wt_lo);
    cudaGetSymbolAddress((void**)&qhi, g_qhi);
    cudaGetSymbolAddress((void**)&qlo, g_qlo);
    cudaGetSymbolAddress((void**)&khi, g_khi);
    cudaGetSymbolAddress((void**)&klo, g_klo);
    cudaGetSymbolAddress((void**)&v16, g_v16);
    cudaGetSymbolAddress((void**)&a16, g_a16);
    cudaGetSymbolAddress((void**)&wo16, g_wo16);

    cudaFuncSetAttribute(gemm_qkv, cudaFuncAttributeMaxDynamicSharedMemorySize, 196608);
    cudaFuncSetAttribute(gemm_out, cudaFuncAttributeMaxDynamicSharedMemorySize, 73728);
    cudaFuncSetAttribute(attn_mma, cudaFuncAttributeMaxDynamicSharedMemorySize, 90112);

    prep<<<6912, 256>>>(x, Wq, Wk, Wv, Wo);

    // fused QKV projection + RoPE/split/V-fp16 epilogue
    gemm_qkv<<<dim3(NQKV / 128, MM / 128), 256, 196608>>>(xhi, xlo, wth, wtl,
                                                          MM, NQKV, DD);

    attn_mma<<<dim3(TT / 64, BB * NH), 128, 90112>>>(qhi, qlo, khi, klo,
                                                     v16, a16);

    gemm_out<<<dim3(DD / 128, MM / 64), 128, 73728>>>(a16, wo16, out,
                                                      MM, DD, DD);
}

// round 11
// speedup vs baseline: 1.4675x; 1.2150x over previous
#include <cuda_runtime.h>
#include <cuda_bf16.h>
#include <cuda_fp16.h>
#include <math.h>
#include <stdint.h>

#define BB 2
#define TT 2048
#define DD 1024
#define NH 16
#define NKV 4
#define HD 64
#define NREP 4           // NH / NKV
#define MM (BB*TT)       // 4096
#define NQKV (NH*HD + 2*NKV*HD)   // 1536 fused QKV output width

// ---------------- scratch (device globals; no runtime allocation) -----------
__device__ __align__(16) float g_cos[TT*32];
__device__ __align__(16) float g_sin[TT*32];
__device__ __half g_x16hi[MM*DD], g_x16lo[MM*DD];   // x fp16 2-term split
__device__ __half g_w16[NQKV*DD];                   // fused QKV weights^T fp16 [N][K]
__device__ __half g_wo16[DD*DD];                    // Wo^T fp16 [N][K]
__device__ __half g_q16hi[BB*NH*TT*HD], g_q16lo[BB*NH*TT*HD];  // Q fp16 2-term [b][h][t][d]
__device__ __half g_k16[BB*NKV*TT*HD];              // K fp16 single [b][kvh][t][d]
__device__ __half g_v16[BB*NKV*TT*HD];              // V fp16 [b][kvh][t][d]
__device__ __half g_a16[MM*DD];                     // attention out fp16

// ---------------- helpers ----------------------------------------------------
__device__ __forceinline__ uint32_t smem_u32(const void* p) {
    uint32_t a;
    asm("{ .reg .u64 t; cvta.to.shared.u64 t, %1; cvt.u32.u64 %0, t; }"
        : "=r"(a) : "l"(p));
    return a;
}
#define SWZ(off) ((off) ^ (((off) >> 3) & 0x70))

#define CP_ASYNC16(dst, src) \
    asm volatile("cp.async.cg.shared.global [%0], [%1], 16;" \
                 :: "r"(dst), "l"(src) : "memory")
#define CP_COMMIT() asm volatile("cp.async.commit_group;" ::: "memory")
#define CP_WAIT(n)  asm volatile("cp.async.wait_group %0;" :: "n"(n) : "memory")

#define LDSM4(r0, r1, r2, r3, addr) \
    asm volatile("ldmatrix.sync.aligned.m8n8.x4.shared.b16 {%0,%1,%2,%3}, [%4];" \
                 : "=r"(r0), "=r"(r1), "=r"(r2), "=r"(r3) : "r"(addr))

#define LDSM4T(r0, r1, r2, r3, addr) \
    asm volatile("ldmatrix.sync.aligned.m8n8.x4.trans.shared.b16 {%0,%1,%2,%3}, [%4];" \
                 : "=r"(r0), "=r"(r1), "=r"(r2), "=r"(r3) : "r"(addr))

#define MMAH(c, a, b0, b1) \
    asm volatile("mma.sync.aligned.m16n8k16.row.col.f32.f16.f16.f32 " \
                 "{%0,%1,%2,%3}, {%4,%5,%6,%7}, {%8,%9}, {%0,%1,%2,%3};" \
                 : "+f"((c)[0]), "+f"((c)[1]), "+f"((c)[2]), "+f"((c)[3]) \
                 : "r"((a)[0]), "r"((a)[1]), "r"((a)[2]), "r"((a)[3]), \
                   "r"(b0), "r"(b1))

__device__ __forceinline__ uint32_t packh(float a, float b) {
    __half2 h = __floats2half2_rn(a, b);
    return *(uint32_t*)&h;
}

// fp16 2-term split of a pair
__device__ __forceinline__ void split2h(float x0, float x1, uint32_t& hi, uint32_t& lo) {
    __half h0 = __float2half_rn(x0), h1 = __float2half_rn(x1);
    float r0 = x0 - __half2float(h0), r1 = x1 - __half2float(h1);
    __half2 H; H.x = h0; H.y = h1;
    __half2 L = __floats2half2_rn(r0, r1);
    hi = *(uint32_t*)&H; lo = *(uint32_t*)&L;
}

// ---------------------------------------------------------------------------
// QKV GEMM: (xhi+xlo fp16) @ (W fp16)^T, fp32 acc. 128x128 tile, BK=64,
// 3-stage cp.async (3 x 48KB). Fused epilogue: RoPE (smem-staged cos/sin),
// Q -> fp16 hi/lo, K -> fp16, V -> fp16.
// ---------------------------------------------------------------------------
__global__ __launch_bounds__(256, 1) void gemm_qkv(
        const __half* __restrict__ Ahi, const __half* __restrict__ Alo,
        const __half* __restrict__ B16, int M, int N, int K) {
    extern __shared__ char smem[];
    uint32_t sbase = smem_u32(smem);
    int tid = threadIdx.x, wid = tid >> 5, lid = tid & 31;
    int m0 = blockIdx.y * 128, n0 = blockIdx.x * 128;
    int wm = wid & 1, wn = wid >> 1;
    const int nch = K / 64;
    const int rr = tid >> 3;
    const int uu = tid & 7;

    float acc[4][4][4] = {};

    auto load_chunk = [&](int buf, int ch) {
        int k0 = ch * 64;
        uint32_t dbase = sbase + (uint32_t)buf * 49152u;
        #pragma unroll
        for (int arr = 0; arr < 3; arr++) {
            const __half* s = (arr == 0) ? Ahi : (arr == 1) ? Alo : B16;
            int rb = (arr < 2) ? m0 : n0;
            uint32_t ab = dbase + (uint32_t)arr * 16384u;
            #pragma unroll
            for (int it = 0; it < 4; it++) {
                int r = it * 32 + rr;
                CP_ASYNC16(ab + SWZ(r * 128 + uu * 16),
                           s + (size_t)(rb + r) * K + k0 + uu * 8);
            }
        }
        CP_COMMIT();
    };

    load_chunk(0, 0);
    load_chunk(1, 1);

    for (int ch = 0; ch < nch; ch++) {
        if (ch < nch - 1) { CP_WAIT(1); } else { CP_WAIT(0); }
        __syncthreads();
        if (ch + 2 < nch) load_chunk((ch + 2) % 3, ch + 2);

        uint32_t db = sbase + (uint32_t)(ch % 3) * 49152u;
        uint32_t abh = db, abl = db + 16384u, bb = db + 32768u;
        int g = lid >> 3, w8 = lid & 7;

        #pragma unroll
        for (int ks = 0; ks < 4; ks++) {
            uint32_t ah[4][4], al[4][4], bh[4][2];
            int arow = wm * 64 + (lid & 15);
            int acol = ks * 32 + (lid >> 4) * 16;
            #pragma unroll
            for (int mi = 0; mi < 4; mi++) {
                uint32_t off = SWZ((arow + mi * 16) * 128 + acol);
                LDSM4(ah[mi][0], ah[mi][1], ah[mi][2], ah[mi][3], abh + off);
                LDSM4(al[mi][0], al[mi][1], al[mi][2], al[mi][3], abl + off);
            }
            #pragma unroll
            for (int p = 0; p < 2; p++) {
                int nrow = wn * 32 + p * 16 + (g >> 1) * 8 + w8;
                uint32_t off = SWZ(nrow * 128 + ks * 32 + (g & 1) * 16);
                LDSM4(bh[2*p][0], bh[2*p][1], bh[2*p+1][0], bh[2*p+1][1], bb + off);
            }
            #pragma unroll
            for (int mi = 0; mi < 4; mi++)
                #pragma unroll
                for (int ni = 0; ni < 4; ni++) {
                    MMAH(acc[mi][ni], ah[mi], bh[ni][0], bh[ni][1]);
                    MMAH(acc[mi][ni], al[mi], bh[ni][0], bh[ni][1]);
                }
        }
        __syncthreads();
    }

    // ---- fused epilogue ----
    // cols [0,1024)=Q, [1024,1280)=K, [1280,1536)=V (uniform per CTA)
    int region = (blockIdx.x < 8) ? 0 : (blockIdx.x < 10) ? 1 : 2;
    float* cs_s = (float*)smem;               // 16KB: cos[128][32]
    float* sn_s = (float*)(smem + 16384);     // 16KB: sin[128][32]
    if (region < 2) {
        int tbase = m0 & (TT - 1);
        #pragma unroll
        for (int i = 0; i < 4; i++) {
            int idx = i * 256 + tid;
            *(float4*)(smem + idx * 16) =
                *(const float4*)&g_cos[(size_t)tbase * 32 + idx * 4];
            *(float4*)(smem + 16384 + idx * 16) =
                *(const float4*)&g_sin[(size_t)tbase * 32 + idx * 4];
        }
        __syncthreads();
    }
    #pragma unroll
    for (int mi = 0; mi < 4; mi++) {
        int row = m0 + wm * 64 + mi * 16 + (lid >> 2);
        #pragma unroll
        for (int r2 = 0; r2 < 2; r2++) {
            int trow = row + r2 * 8;
            int b = trow >> 11, t = trow & (TT - 1);
            int tl = trow - m0;
            #pragma unroll
            for (int ni = 0; ni < 4; ni++) {
                int c = n0 + wn * 32 + ni * 8 + (lid & 3) * 2;
                float v0 = acc[mi][ni][r2 * 2], v1 = acc[mi][ni][r2 * 2 + 1];
                if (region == 2) {
                    int cc = c - 1280;
                    int kvh = cc >> 6, d = cc & 63;
                    *(uint32_t*)&g_v16[((size_t)(b * NKV + kvh) * TT + t) * HD + d] =
                        packh(v0, v1);
                } else {
                    int cc = (region == 1) ? c - 1024 : c;
                    int hh = cc >> 6, d = cc & 63;
                    int ci = tl * 32 + (d >> 1);
                    float cs = cs_s[ci], sn = sn_s[ci];
                    float r0 = v0 * cs - v1 * sn;
                    float r1 = v1 * cs + v0 * sn;
                    if (region == 1) {
                        size_t o = ((size_t)(b * NKV + hh) * TT + t) * HD + d;
                        *(uint32_t*)&g_k16[o] = packh(r0, r1);
                    } else {
                        uint32_t hi, lo;
                        split2h(r0, r1, hi, lo);
                        size_t o = ((size_t)(b * NH + hh) * TT + t) * HD + d;
                        *(uint32_t*)&g_q16hi[o] = hi;
                        *(uint32_t*)&g_q16lo[o] = lo;
                    }
                }
            }
        }
    }
}

// ---------------------------------------------------------------------------
// O-projection GEMM: single-term fp16 x fp16 (fp32 acc).
// 64x128 CTA tile, 128 threads, 3-stage (3 x 24KB) -> 2 CTAs/SM.
// ---------------------------------------------------------------------------
__global__ __launch_bounds__(128, 2) void gemm_out(
        const __half* __restrict__ A, const __half* __restrict__ B,
        float* __restrict__ C, int M, int N, int K) {
    extern __shared__ char smem[];
    uint32_t sbase = smem_u32(smem);
    int tid = threadIdx.x, wid = tid >> 5, lid = tid & 31;
    int m0 = blockIdx.y * 64, n0 = blockIdx.x * 128;
    const int nch = K / 64;
    const int rr = tid >> 3, uu = tid & 7;

    float acc[4][4][4] = {};

    auto load_chunk = [&](int buf, int ch) {
        int k0 = ch * 64;
        uint32_t dbase = sbase + (uint32_t)buf * 24576u;
        #pragma unroll
        for (int it = 0; it < 4; it++) {
            int r = it * 16 + rr;
            CP_ASYNC16(dbase + SWZ(r * 128 + uu * 16),
                       A + (size_t)(m0 + r) * K + k0 + uu * 8);
        }
        #pragma unroll
        for (int it = 0; it < 8; it++) {
            int r = it * 16 + rr;
            CP_ASYNC16(dbase + 8192u + SWZ(r * 128 + uu * 16),
                       B + (size_t)(n0 + r) * K + k0 + uu * 8);
        }
        CP_COMMIT();
    };

    load_chunk(0, 0);
    load_chunk(1, 1);

    for (int ch = 0; ch < nch; ch++) {
        if (ch < nch - 1) { CP_WAIT(1); } else { CP_WAIT(0); }
        __syncthreads();
        if (ch + 2 < nch) load_chunk((ch + 2) % 3, ch + 2);

        uint32_t db = sbase + (uint32_t)(ch % 3) * 24576u;
        uint32_t ab_ = db, bb = db + 8192u;
        int g = lid >> 3, w8 = lid & 7;

        #pragma unroll
        for (int ks = 0; ks < 4; ks++) {
            uint32_t ah[4][4], bh[4][2];
            int arow = lid & 15;
            int acol = ks * 32 + (lid >> 4) * 16;
            #pragma unroll
            for (int mi = 0; mi < 4; mi++) {
                uint32_t off = SWZ((arow + mi * 16) * 128 + acol);
                LDSM4(ah[mi][0], ah[mi][1], ah[mi][2], ah[mi][3], ab_ + off);
            }
            #pragma unroll
            for (int p = 0; p < 2; p++) {
                int nrow = wid * 32 + p * 16 + (g >> 1) * 8 + w8;
                uint32_t off = SWZ(nrow * 128 + ks * 32 + (g & 1) * 16);
                LDSM4(bh[2*p][0], bh[2*p][1], bh[2*p+1][0], bh[2*p+1][1], bb + off);
            }
            #pragma unroll
            for (int mi = 0; mi < 4; mi++)
                #pragma unroll
                for (int ni = 0; ni < 4; ni++)
                    MMAH(acc[mi][ni], ah[mi], bh[ni][0], bh[ni][1]);
        }
        __syncthreads();
    }

    #pragma unroll
    for (int mi = 0; mi < 4; mi++) {
        int row = m0 + mi * 16 + (lid >> 2);
        #pragma unroll
        for (int ni = 0; ni < 4; ni++) {
            int col = n0 + wid * 32 + ni * 8 + (lid & 3) * 2;
            *(float2*)&C[(size_t)row * N + col] =
                make_float2(acc[mi][ni][0], acc[mi][ni][1]);
            *(float2*)&C[(size_t)(row + 8) * N + col] =
                make_float2(acc[mi][ni][2], acc[mi][ni][3]);
        }
    }
}

// ---------------------------------------------------------------------------
// HMMA flash attention, causal. 64-query tiles, 128 threads (4 warps),
// grid (T/64 reversed, B*NH). smem: Q 16KB + 3 x 16KB = 64KB -> 2 CTAs/SM.
// S = (Qhi+Qlo fp16) K(fp16)^T: 2-term; PV fp16 (V via ldmatrix.trans).
// ---------------------------------------------------------------------------
__global__ __launch_bounds__(128, 2) void attn_mma(
        const __half* __restrict__ Qhi, const __half* __restrict__ Qlo,
        const __half* __restrict__ K16,
        const __half* __restrict__ Vt, __half* __restrict__ Oh) {
    extern __shared__ char smem[];
    uint32_t sbase = smem_u32(smem);
    const uint32_t QHI = 0, QLO = 8192, BUF = 16384;   // 3 x 16KB chunk buffers

    int tid = threadIdx.x, wid = tid >> 5, lid = tid & 31;
    int qt = gridDim.x - 1 - blockIdx.x;
    int bh = blockIdx.y;
    int b = bh / NH, h = bh % NH, kvh = h / NREP;
    int q0 = qt * 64;

    const __half* qbh = Qhi + (size_t)(b * NH + h) * TT * HD;
    const __half* qbl = Qlo + (size_t)(b * NH + h) * TT * HD;
    const __half* kb16 = K16 + (size_t)(b * NKV + kvh) * TT * HD;
    const __half* vbase = Vt + (size_t)(b * NKV + kvh) * TT * HD;   // [t][d]

    // stage Q (own commit group): 64 rows hi+lo
    {
        #pragma unroll
        for (int arr = 0; arr < 2; arr++) {
            const __half* s = arr ? qbl : qbh;
            uint32_t ab = sbase + (arr ? QLO : QHI);
            #pragma unroll
            for (int it = 0; it < 4; it++) {
                int idx = it * 128 + tid;
                int r = idx >> 3, u = idx & 7;
                CP_ASYNC16(ab + SWZ(r * 128 + u * 16),
                           s + (size_t)(q0 + r) * HD + u * 8);
            }
        }
        CP_COMMIT();
    }

    auto load_chunk = [&](int buf, int kt) {
        uint32_t db = sbase + BUF + (uint32_t)buf * 16384u;
        #pragma unroll
        for (int arr = 0; arr < 2; arr++) {
            uint32_t ab = db + (uint32_t)arr * 8192u;
            const __half* s = arr ? vbase : kb16;
            #pragma unroll
            for (int it = 0; it < 4; it++) {
                int idx = it * 128 + tid;
                int r = idx >> 3, u = idx & 7;
                CP_ASYNC16(ab + SWZ(r * 128 + u * 16),
                           s + (size_t)(kt * 64 + r) * HD + u * 8);
            }
        }
        CP_COMMIT();
    };

    int nch = qt + 1;
    load_chunk(0, 0);
    load_chunk(1, (nch > 1) ? 1 : 0);

    CP_WAIT(2);
    __syncthreads();
    uint32_t qfh[4][4], qfl[4][4];
    {
        int arow = wid * 16 + (lid & 15);
        #pragma unroll
        for (int ks = 0; ks < 4; ks++) {
            uint32_t off = SWZ(arow * 128 + ks * 32 + (lid >> 4) * 16);
            LDSM4(qfh[ks][0], qfh[ks][1], qfh[ks][2], qfh[ks][3], sbase + QHI + off);
            LDSM4(qfl[ks][0], qfl[ks][1], qfl[ks][2], qfl[ks][3], sbase + QLO + off);
        }
    }

    float oacc[8][4] = {};
    float mA = -1e30f, mB = -1e30f, lA = 0.f, lB = 0.f;
    const int g = lid >> 3, w8 = lid & 7;
    const int qrA = q0 + wid * 16 + (lid >> 2);
    const float SC = 0.125f * 1.4426950408889634f;   // scale * log2(e)
    const int vrow16 = lid & 15, vhi16 = (lid >> 4) & 1;

    for (int ch = 0; ch < nch; ch++) {
        if (ch < nch - 1) { CP_WAIT(1); } else { CP_WAIT(0); }
        __syncthreads();
        if (ch + 2 < nch) load_chunk((ch + 2) % 3, ch + 2);

        int kt = ch;
        {
            uint32_t kb = sbase + BUF + (uint32_t)(ch % 3) * 16384u;
            uint32_t vb = kb + 8192u;

            // ---- S = Q K^T (Q 2-term fp16, K single fp16) ----
            float sacc[8][4] = {};
            #pragma unroll
            for (int ks = 0; ks < 4; ks++) {
                #pragma unroll
                for (int p = 0; p < 4; p++) {
                    int nrow = p * 16 + (g >> 1) * 8 + w8;
                    uint32_t off = SWZ(nrow * 128 + ks * 32 + (g & 1) * 16);
                    uint32_t b0, b1, b2, b3;
                    LDSM4(b0, b1, b2, b3, kb + off);
                    MMAH(sacc[2*p],   qfh[ks], b0, b1);
                    MMAH(sacc[2*p+1], qfh[ks], b2, b3);
                    MMAH(sacc[2*p],   qfl[ks], b0, b1);
                    MMAH(sacc[2*p+1], qfl[ks], b2, b3);
                }
            }

            // ---- scale (log2 domain) + causal mask ----
            #pragma unroll
            for (int nt = 0; nt < 8; nt++) {
                int kc = kt * 64 + nt * 8 + (lid & 3) * 2;
                #pragma unroll
                for (int j = 0; j < 4; j++) sacc[nt][j] *= SC;
                if (kc > qrA)         sacc[nt][0] = -1e9f;
                if (kc + 1 > qrA)     sacc[nt][1] = -1e9f;
                if (kc > qrA + 8)     sacc[nt][2] = -1e9f;
                if (kc + 1 > qrA + 8) sacc[nt][3] = -1e9f;
            }

            // ---- online softmax (base-2) with corr-skip ----
            float rmA = -1e30f, rmB = -1e30f;
            #pragma unroll
            for (int nt = 0; nt < 8; nt++) {
                rmA = fmaxf(rmA, fmaxf(sacc[nt][0], sacc[nt][1]));
                rmB = fmaxf(rmB, fmaxf(sacc[nt][2], sacc[nt][3]));
            }
            rmA = fmaxf(rmA, __shfl_xor_sync(0xffffffffu, rmA, 1));
            rmA = fmaxf(rmA, __shfl_xor_sync(0xffffffffu, rmA, 2));
            rmB = fmaxf(rmB, __shfl_xor_sync(0xffffffffu, rmB, 1));
            rmB = fmaxf(rmB, __shfl_xor_sync(0xffffffffu, rmB, 2));
            float mnA = fmaxf(mA, rmA), mnB = fmaxf(mB, rmB);
            float corrA = 1.f, corrB = 1.f;
            if (mnA > mA || mnB > mB) {
                corrA = exp2f(mA - mnA);
                corrB = exp2f(mB - mnB);
                #pragma unroll
                for (int nt = 0; nt < 8; nt++) {
                    oacc[nt][0] *= corrA; oacc[nt][1] *= corrA;
                    oacc[nt][2] *= corrB; oacc[nt][3] *= corrB;
                }
            }
            mA = mnA; mB = mnB;
            float rsA = 0.f, rsB = 0.f;
            #pragma unroll
            for (int nt = 0; nt < 8; nt++) {
                sacc[nt][0] = exp2f(sacc[nt][0] - mA);
                sacc[nt][1] = exp2f(sacc[nt][1] - mA);
                sacc[nt][2] = exp2f(sacc[nt][2] - mB);
                sacc[nt][3] = exp2f(sacc[nt][3] - mB);
                rsA += sacc[nt][0] + sacc[nt][1];
                rsB += sacc[nt][2] + sacc[nt][3];
            }
            rsA += __shfl_xor_sync(0xffffffffu, rsA, 1);
            rsA += __shfl_xor_sync(0xffffffffu, rsA, 2);
            rsB += __shfl_xor_sync(0xffffffffu, rsB, 1);
            rsB += __shfl_xor_sync(0xffffffffu, rsB, 2);
            lA = lA * corrA + rsA;
            lB = lB * corrB + rsB;

            // ---- O += P V (fp16; V untransposed via ldmatrix.trans) ----
            #pragma unroll
            for (int k2 = 0; k2 < 4; k2++) {
                uint32_t pa[4];
                pa[0] = packh(sacc[2*k2][0],   sacc[2*k2][1]);
                pa[1] = packh(sacc[2*k2][2],   sacc[2*k2][3]);
                pa[2] = packh(sacc[2*k2+1][0], sacc[2*k2+1][1]);
                pa[3] = packh(sacc[2*k2+1][2], sacc[2*k2+1][3]);
                #pragma unroll
                for (int p = 0; p < 4; p++) {
                    uint32_t off = SWZ((k2 * 16 + vrow16) * 128 + p * 32 + vhi16 * 16);
                    uint32_t b0, b1, b2, b3;
                    LDSM4T(b0, b1, b2, b3, vb + off);
                    MMAH(oacc[2*p],   pa, b0, b1);
                    MMAH(oacc[2*p+1], pa, b2, b3);
                }
            }
        }
        __syncthreads();
    }

    // ---- epilogue: normalize, fp16 store ----
    float invA = 1.f / lA, invB = 1.f / lB;
    size_t rowA = (size_t)(b * TT + qrA);
    size_t rowB = rowA + 8;
    int colb = h * HD + (lid & 3) * 2;
    #pragma unroll
    for (int nt = 0; nt < 8; nt++) {
        *(uint32_t*)&Oh[rowA * DD + colb + nt * 8] =
            packh(oacc[nt][0] * invA, oacc[nt][1] * invA);
        *(uint32_t*)&Oh[rowB * DD + colb + nt * 8] =
            packh(oacc[nt][2] * invB, oacc[nt][3] * invB);
    }
}

// ---------------------------------------------------------------------------
// prep: x fp16 hi/lo split + fused QKV weight transpose (fp16) +
// Wo transpose (fp16) + rope table (sections on blockIdx.x)
// ---------------------------------------------------------------------------
__device__ __forceinline__ void convT16_body(const float* __restrict__ W,
        __half* __restrict__ t16, int Kd, int Nd, int idx, int tid, float (*Ts)[33]) {
    int nt = idx % (Nd / 32), kt = idx / (Nd / 32);
    int k0 = kt * 32, n0 = nt * 32;
    int r = tid >> 3, c4 = (tid & 7) * 4;
    float4 v = *(const float4*)&W[(size_t)(k0 + r) * Nd + n0 + c4];
    Ts[r][c4] = v.x; Ts[r][c4 + 1] = v.y; Ts[r][c4 + 2] = v.z; Ts[r][c4 + 3] = v.w;
    __syncthreads();
    #pragma unroll
    for (int j = 0; j < 4; j++) {
        size_t o = (size_t)(n0 + r) * Kd + k0 + c4 + j;
        t16[o] = __float2half_rn(Ts[c4 + j][r]);
    }
}

__global__ __launch_bounds__(256) void prep(const float* __restrict__ x,
        const float* __restrict__ Wq, const float* __restrict__ Wk,
        const float* __restrict__ Wv, const float* __restrict__ Wo) {
    __shared__ float Ts[32][33];
    int bx = blockIdx.x, tid = threadIdx.x;
    if (bx < 4096) {                       // x fp16 hi/lo split
        int i = (bx * 256 + tid) * 4;
        float4 v = *(const float4*)(x + i);
        float vv[4] = {v.x, v.y, v.z, v.w};
        #pragma unroll
        for (int j = 0; j < 4; j++) {
            __half h = __float2half_rn(vv[j]);
            g_x16hi[i + j] = h;
            g_x16lo[i + j] = __float2half_rn(vv[j] - __half2float(h));
        }
    } else if (bx < 5120) {
        convT16_body(Wq, g_w16, DD, DD, bx - 4096, tid, Ts);
    } else if (bx < 5376) {
        convT16_body(Wk, g_w16 + (size_t)NH * HD * DD, DD, NKV * HD, bx - 5120, tid, Ts);
    } else if (bx < 5632) {
        convT16_body(Wv, g_w16 + (size_t)(NH + NKV) * HD * DD, DD, NKV * HD,
                     bx - 5376, tid, Ts);
    } else if (bx < 6656) {
        convT16_body(Wo, g_wo16, DD, DD, bx - 5632, tid, Ts);
    } else {                               // rope table
        int idx = (bx - 6656) * 256 + tid;
        int t = idx >> 5, pair = idx & 31;
        float freq = (float)pow(500000.0, -(double)pair / 32.0);
        float ang = (float)t * freq;
        g_cos[idx] = (float)cos((double)ang);
        g_sin[idx] = (float)sin((double)ang);
    }
}

// ---------------------------------------------------------------------------
extern "C" void kernel_launch(void* const* d_in, const int* in_sizes, int n_in,
                              void* d_out, int out_size) {
    const float* x  = (const float*)d_in[0];
    // d_in[1] = causal mask — handled analytically
    const float* Wq = (const float*)d_in[2];
    const float* Wk = (const float*)d_in[3];
    const float* Wv = (const float*)d_in[4];
    const float* Wo = (const float*)d_in[5];
    float* out = (float*)d_out;

    __half *x16hi, *x16lo, *w16, *wo16;
    __half *q16hi, *q16lo, *k16, *v16, *a16;
    cudaGetSymbolAddress((void**)&x16hi, g_x16hi);
    cudaGetSymbolAddress((void**)&x16lo, g_x16lo);
    cudaGetSymbolAddress((void**)&w16,  g_w16);
    cudaGetSymbolAddress((void**)&wo16, g_wo16);
    cudaGetSymbolAddress((void**)&q16hi, g_q16hi);
    cudaGetSymbolAddress((void**)&q16lo, g_q16lo);
    cudaGetSymbolAddress((void**)&k16, g_k16);
    cudaGetSymbolAddress((void**)&v16, g_v16);
    cudaGetSymbolAddress((void**)&a16, g_a16);

    cudaFuncSetAttribute(gemm_qkv, cudaFuncAttributeMaxDynamicSharedMemorySize, 147456);
    cudaFuncSetAttribute(gemm_out, cudaFuncAttributeMaxDynamicSharedMemorySize, 73728);
    cudaFuncSetAttribute(attn_mma, cudaFuncAttributeMaxDynamicSharedMemorySize, 65536);

    prep<<<6912, 256>>>(x, Wq, Wk, Wv, Wo);

    // fused QKV projection + RoPE/split epilogue
    gemm_qkv<<<dim3(NQKV / 128, MM / 128), 256, 147456>>>(x16hi, x16lo, w16,
                                                          MM, NQKV, DD);

    attn_mma<<<dim3(TT / 64, BB * NH), 128, 65536>>>(q16hi, q16lo, k16,
                                                     v16, a16);

    gemm_out<<<dim3(DD / 128, MM / 64), 128, 73728>>>(a16, wo16, out,
                                                      MM, DD, DD);
}

// round 12
// speedup vs baseline: 1.6827x; 1.1466x over previous
#include <cuda_runtime.h>
#include <cuda_bf16.h>
#include <cuda_fp16.h>
#include <math.h>
#include <stdint.h>

#define BB 2
#define TT 2048
#define DD 1024
#define NH 16
#define NKV 4
#define HD 64
#define NREP 4           // NH / NKV
#define MM (BB*TT)       // 4096
#define NQKV (NH*HD + 2*NKV*HD)   // 1536 fused QKV output width

// ---------------- scratch (device globals; no runtime allocation) -----------
__device__ __align__(16) float g_cos[TT*32];
__device__ __align__(16) float g_sin[TT*32];
__device__ __half g_x16hi[MM*DD], g_x16lo[MM*DD];   // x fp16 2-term split
__device__ __half g_w16[NQKV*DD];                   // fused QKV weights^T fp16 [N][K]
__device__ __half g_wo16[DD*DD];                    // Wo^T fp16 [N][K]
__device__ __half g_q16[BB*NH*TT*HD];               // Q fp16 [b][h][t][d]
__device__ __half g_k16[BB*NKV*TT*HD];              // K fp16 [b][kvh][t][d]
__device__ __half g_v16[BB*NKV*TT*HD];              // V fp16 [b][kvh][t][d]
__device__ __half g_a16[MM*DD];                     // attention out fp16

// ---------------- helpers ----------------------------------------------------
__device__ __forceinline__ uint32_t smem_u32(const void* p) {
    uint32_t a;
    asm("{ .reg .u64 t; cvta.to.shared.u64 t, %1; cvt.u32.u64 %0, t; }"
        : "=r"(a) : "l"(p));
    return a;
}
#define SWZ(off) ((off) ^ (((off) >> 3) & 0x70))

#define CP_ASYNC16(dst, src) \
    asm volatile("cp.async.cg.shared.global [%0], [%1], 16;" \
                 :: "r"(dst), "l"(src) : "memory")
#define CP_COMMIT() asm volatile("cp.async.commit_group;" ::: "memory")
#define CP_WAIT(n)  asm volatile("cp.async.wait_group %0;" :: "n"(n) : "memory")

#define LDSM4(r0, r1, r2, r3, addr) \
    asm volatile("ldmatrix.sync.aligned.m8n8.x4.shared.b16 {%0,%1,%2,%3}, [%4];" \
                 : "=r"(r0), "=r"(r1), "=r"(r2), "=r"(r3) : "r"(addr))

#define LDSM4T(r0, r1, r2, r3, addr) \
    asm volatile("ldmatrix.sync.aligned.m8n8.x4.trans.shared.b16 {%0,%1,%2,%3}, [%4];" \
                 : "=r"(r0), "=r"(r1), "=r"(r2), "=r"(r3) : "r"(addr))

#define MMAH(c, a, b0, b1) \
    asm volatile("mma.sync.aligned.m16n8k16.row.col.f32.f16.f16.f32 " \
                 "{%0,%1,%2,%3}, {%4,%5,%6,%7}, {%8,%9}, {%0,%1,%2,%3};" \
                 : "+f"((c)[0]), "+f"((c)[1]), "+f"((c)[2]), "+f"((c)[3]) \
                 : "r"((a)[0]), "r"((a)[1]), "r"((a)[2]), "r"((a)[3]), \
                   "r"(b0), "r"(b1))

__device__ __forceinline__ uint32_t packh(float a, float b) {
    __half2 h = __floats2half2_rn(a, b);
    return *(uint32_t*)&h;
}

// ---------------------------------------------------------------------------
// QKV GEMM: (xhi+xlo fp16) @ (W fp16)^T, fp32 acc. 128x128 tile, BK=64,
// 3-stage cp.async (3 x 48KB). Fused epilogue: RoPE (smem-staged cos/sin),
// Q -> fp16, K -> fp16, V -> fp16.
// ---------------------------------------------------------------------------
__global__ __launch_bounds__(256, 1) void gemm_qkv(
        const __half* __restrict__ Ahi, const __half* __restrict__ Alo,
        const __half* __restrict__ B16, int M, int N, int K) {
    extern __shared__ char smem[];
    uint32_t sbase = smem_u32(smem);
    int tid = threadIdx.x, wid = tid >> 5, lid = tid & 31;
    int m0 = blockIdx.y * 128, n0 = blockIdx.x * 128;
    int wm = wid & 1, wn = wid >> 1;
    const int nch = K / 64;
    const int rr = tid >> 3;
    const int uu = tid & 7;

    float acc[4][4][4] = {};

    auto load_chunk = [&](int buf, int ch) {
        int k0 = ch * 64;
        uint32_t dbase = sbase + (uint32_t)buf * 49152u;
        #pragma unroll
        for (int arr = 0; arr < 3; arr++) {
            const __half* s = (arr == 0) ? Ahi : (arr == 1) ? Alo : B16;
            int rb = (arr < 2) ? m0 : n0;
            uint32_t ab = dbase + (uint32_t)arr * 16384u;
            #pragma unroll
            for (int it = 0; it < 4; it++) {
                int r = it * 32 + rr;
                CP_ASYNC16(ab + SWZ(r * 128 + uu * 16),
                           s + (size_t)(rb + r) * K + k0 + uu * 8);
            }
        }
        CP_COMMIT();
    };

    load_chunk(0, 0);
    load_chunk(1, 1);

    for (int ch = 0; ch < nch; ch++) {
        if (ch < nch - 1) { CP_WAIT(1); } else { CP_WAIT(0); }
        __syncthreads();
        if (ch + 2 < nch) load_chunk((ch + 2) % 3, ch + 2);

        uint32_t db = sbase + (uint32_t)(ch % 3) * 49152u;
        uint32_t abh = db, abl = db + 16384u, bb = db + 32768u;
        int g = lid >> 3, w8 = lid & 7;

        #pragma unroll
        for (int ks = 0; ks < 4; ks++) {
            uint32_t ah[4][4], al[4][4], bh[4][2];
            int arow = wm * 64 + (lid & 15);
            int acol = ks * 32 + (lid >> 4) * 16;
            #pragma unroll
            for (int mi = 0; mi < 4; mi++) {
                uint32_t off = SWZ((arow + mi * 16) * 128 + acol);
                LDSM4(ah[mi][0], ah[mi][1], ah[mi][2], ah[mi][3], abh + off);
                LDSM4(al[mi][0], al[mi][1], al[mi][2], al[mi][3], abl + off);
            }
            #pragma unroll
            for (int p = 0; p < 2; p++) {
                int nrow = wn * 32 + p * 16 + (g >> 1) * 8 + w8;
                uint32_t off = SWZ(nrow * 128 + ks * 32 + (g & 1) * 16);
                LDSM4(bh[2*p][0], bh[2*p][1], bh[2*p+1][0], bh[2*p+1][1], bb + off);
            }
            #pragma unroll
            for (int mi = 0; mi < 4; mi++)
                #pragma unroll
                for (int ni = 0; ni < 4; ni++) {
                    MMAH(acc[mi][ni], ah[mi], bh[ni][0], bh[ni][1]);
                    MMAH(acc[mi][ni], al[mi], bh[ni][0], bh[ni][1]);
                }
        }
        __syncthreads();
    }

    // ---- fused epilogue ----
    // cols [0,1024)=Q, [1024,1280)=K, [1280,1536)=V (uniform per CTA)
    int region = (blockIdx.x < 8) ? 0 : (blockIdx.x < 10) ? 1 : 2;
    float* cs_s = (float*)smem;               // 16KB: cos[128][32]
    float* sn_s = (float*)(smem + 16384);     // 16KB: sin[128][32]
    if (region < 2) {
        int tbase = m0 & (TT - 1);
        #pragma unroll
        for (int i = 0; i < 4; i++) {
            int idx = i * 256 + tid;
            *(float4*)(smem + idx * 16) =
                *(const float4*)&g_cos[(size_t)tbase * 32 + idx * 4];
            *(float4*)(smem + 16384 + idx * 16) =
                *(const float4*)&g_sin[(size_t)tbase * 32 + idx * 4];
        }
        __syncthreads();
    }
    #pragma unroll
    for (int mi = 0; mi < 4; mi++) {
        int row = m0 + wm * 64 + mi * 16 + (lid >> 2);
        #pragma unroll
        for (int r2 = 0; r2 < 2; r2++) {
            int trow = row + r2 * 8;
            int b = trow >> 11, t = trow & (TT - 1);
            int tl = trow - m0;
            #pragma unroll
            for (int ni = 0; ni < 4; ni++) {
                int c = n0 + wn * 32 + ni * 8 + (lid & 3) * 2;
                float v0 = acc[mi][ni][r2 * 2], v1 = acc[mi][ni][r2 * 2 + 1];
                if (region == 2) {
                    int cc = c - 1280;
                    int kvh = cc >> 6, d = cc & 63;
                    *(uint32_t*)&g_v16[((size_t)(b * NKV + kvh) * TT + t) * HD + d] =
                        packh(v0, v1);
                } else {
                    int cc = (region == 1) ? c - 1024 : c;
                    int hh = cc >> 6, d = cc & 63;
                    int ci = tl * 32 + (d >> 1);
                    float cs = cs_s[ci], sn = sn_s[ci];
                    float r0 = v0 * cs - v1 * sn;
                    float r1 = v1 * cs + v0 * sn;
                    if (region == 1) {
                        size_t o = ((size_t)(b * NKV + hh) * TT + t) * HD + d;
                        *(uint32_t*)&g_k16[o] = packh(r0, r1);
                    } else {
                        size_t o = ((size_t)(b * NH + hh) * TT + t) * HD + d;
                        *(uint32_t*)&g_q16[o] = packh(r0, r1);
                    }
                }
            }
        }
    }
}

// ---------------------------------------------------------------------------
// O-projection GEMM: single-term fp16 x fp16 (fp32 acc).
// 64x128 CTA tile, 128 threads, 3-stage (3 x 24KB) -> 2 CTAs/SM.
// ---------------------------------------------------------------------------
__global__ __launch_bounds__(128, 2) void gemm_out(
        const __half* __restrict__ A, const __half* __restrict__ B,
        float* __restrict__ C, int M, int N, int K) {
    extern __shared__ char smem[];
    uint32_t sbase = smem_u32(smem);
    int tid = threadIdx.x, wid = tid >> 5, lid = tid & 31;
    int m0 = blockIdx.y * 64, n0 = blockIdx.x * 128;
    const int nch = K / 64;
    const int rr = tid >> 3, uu = tid & 7;

    float acc[4][4][4] = {};

    auto load_chunk = [&](int buf, int ch) {
        int k0 = ch * 64;
        uint32_t dbase = sbase + (uint32_t)buf * 24576u;
        #pragma unroll
        for (int it = 0; it < 4; it++) {
            int r = it * 16 + rr;
            CP_ASYNC16(dbase + SWZ(r * 128 + uu * 16),
                       A + (size_t)(m0 + r) * K + k0 + uu * 8);
        }
        #pragma unroll
        for (int it = 0; it < 8; it++) {
            int r = it * 16 + rr;
            CP_ASYNC16(dbase + 8192u + SWZ(r * 128 + uu * 16),
                       B + (size_t)(n0 + r) * K + k0 + uu * 8);
        }
        CP_COMMIT();
    };

    load_chunk(0, 0);
    load_chunk(1, 1);

    for (int ch = 0; ch < nch; ch++) {
        if (ch < nch - 1) { CP_WAIT(1); } else { CP_WAIT(0); }
        __syncthreads();
        if (ch + 2 < nch) load_chunk((ch + 2) % 3, ch + 2);

        uint32_t db = sbase + (uint32_t)(ch % 3) * 24576u;
        uint32_t ab_ = db, bb = db + 8192u;
        int g = lid >> 3, w8 = lid & 7;

        #pragma unroll
        for (int ks = 0; ks < 4; ks++) {
            uint32_t ah[4][4], bh[4][2];
            int arow = lid & 15;
            int acol = ks * 32 + (lid >> 4) * 16;
            #pragma unroll
            for (int mi = 0; mi < 4; mi++) {
                uint32_t off = SWZ((arow + mi * 16) * 128 + acol);
                LDSM4(ah[mi][0], ah[mi][1], ah[mi][2], ah[mi][3], ab_ + off);
            }
            #pragma unroll
            for (int p = 0; p < 2; p++) {
                int nrow = wid * 32 + p * 16 + (g >> 1) * 8 + w8;
                uint32_t off = SWZ(nrow * 128 + ks * 32 + (g & 1) * 16);
                LDSM4(bh[2*p][0], bh[2*p][1], bh[2*p+1][0], bh[2*p+1][1], bb + off);
            }
            #pragma unroll
            for (int mi = 0; mi < 4; mi++)
                #pragma unroll
                for (int ni = 0; ni < 4; ni++)
                    MMAH(acc[mi][ni], ah[mi], bh[ni][0], bh[ni][1]);
        }
        __syncthreads();
    }

    #pragma unroll
    for (int mi = 0; mi < 4; mi++) {
        int row = m0 + mi * 16 + (lid >> 2);
        #pragma unroll
        for (int ni = 0; ni < 4; ni++) {
            int col = n0 + wid * 32 + ni * 8 + (lid & 3) * 2;
            *(float2*)&C[(size_t)row * N + col] =
                make_float2(acc[mi][ni][0], acc[mi][ni][1]);
            *(float2*)&C[(size_t)(row + 8) * N + col] =
                make_float2(acc[mi][ni][2], acc[mi][ni][3]);
        }
    }
}

// ---------------------------------------------------------------------------
// HMMA flash attention, causal. 64-query tiles, 128 threads (4 warps),
// grid (T/64 reversed, B*NH). smem: Q 8KB + 3 x 16KB = 56KB -> 3 CTAs/SM.
// S = Q(fp16) K(fp16)^T single-term; PV fp16 (V via ldmatrix.trans).
// ---------------------------------------------------------------------------
__global__ __launch_bounds__(128, 3) void attn_mma(
        const __half* __restrict__ Q16, const __half* __restrict__ K16,
        const __half* __restrict__ Vt, __half* __restrict__ Oh) {
    extern __shared__ char smem[];
    uint32_t sbase = smem_u32(smem);
    const uint32_t QHI = 0, BUF = 8192;   // 3 x 16KB chunk buffers

    int tid = threadIdx.x, wid = tid >> 5, lid = tid & 31;
    int qt = gridDim.x - 1 - blockIdx.x;
    int bh = blockIdx.y;
    int b = bh / NH, h = bh % NH, kvh = h / NREP;
    int q0 = qt * 64;

    const __half* qb16 = Q16 + (size_t)(b * NH + h) * TT * HD;
    const __half* kb16 = K16 + (size_t)(b * NKV + kvh) * TT * HD;
    const __half* vbase = Vt + (size_t)(b * NKV + kvh) * TT * HD;   // [t][d]

    // stage Q (own commit group): 64 rows
    {
        #pragma unroll
        for (int it = 0; it < 4; it++) {
            int idx = it * 128 + tid;
            int r = idx >> 3, u = idx & 7;
            CP_ASYNC16(sbase + QHI + SWZ(r * 128 + u * 16),
                       qb16 + (size_t)(q0 + r) * HD + u * 8);
        }
        CP_COMMIT();
    }

    auto load_chunk = [&](int buf, int kt) {
        uint32_t db = sbase + BUF + (uint32_t)buf * 16384u;
        #pragma unroll
        for (int arr = 0; arr < 2; arr++) {
            uint32_t ab = db + (uint32_t)arr * 8192u;
            const __half* s = arr ? vbase : kb16;
            #pragma unroll
            for (int it = 0; it < 4; it++) {
                int idx = it * 128 + tid;
                int r = idx >> 3, u = idx & 7;
                CP_ASYNC16(ab + SWZ(r * 128 + u * 16),
                           s + (size_t)(kt * 64 + r) * HD + u * 8);
            }
        }
        CP_COMMIT();
    };

    int nch = qt + 1;
    load_chunk(0, 0);
    load_chunk(1, (nch > 1) ? 1 : 0);

    CP_WAIT(2);
    __syncthreads();
    uint32_t qf[4][4];
    {
        int arow = wid * 16 + (lid & 15);
        #pragma unroll
        for (int ks = 0; ks < 4; ks++) {
            uint32_t off = SWZ(arow * 128 + ks * 32 + (lid >> 4) * 16);
            LDSM4(qf[ks][0], qf[ks][1], qf[ks][2], qf[ks][3], sbase + QHI + off);
        }
    }

    float oacc[8][4] = {};
    float mA = -1e30f, mB = -1e30f, lA = 0.f, lB = 0.f;
    const int g = lid >> 3, w8 = lid & 7;
    const int qrA = q0 + wid * 16 + (lid >> 2);
    const float SC = 0.125f * 1.4426950408889634f;   // scale * log2(e)
    const int vrow16 = lid & 15, vhi16 = (lid >> 4) & 1;

    for (int ch = 0; ch < nch; ch++) {
        if (ch < nch - 1) { CP_WAIT(1); } else { CP_WAIT(0); }
        __syncthreads();
        if (ch + 2 < nch) load_chunk((ch + 2) % 3, ch + 2);

        int kt = ch;
        {
            uint32_t kb = sbase + BUF + (uint32_t)(ch % 3) * 16384u;
            uint32_t vb = kb + 8192u;

            // ---- S = Q K^T (single-term fp16) ----
            float sacc[8][4] = {};
            #pragma unroll
            for (int ks = 0; ks < 4; ks++) {
                #pragma unroll
                for (int p = 0; p < 4; p++) {
                    int nrow = p * 16 + (g >> 1) * 8 + w8;
                    uint32_t off = SWZ(nrow * 128 + ks * 32 + (g & 1) * 16);
                    uint32_t b0, b1, b2, b3;
                    LDSM4(b0, b1, b2, b3, kb + off);
                    MMAH(sacc[2*p],   qf[ks], b0, b1);
                    MMAH(sacc[2*p+1], qf[ks], b2, b3);
                }
            }

            // ---- scale (log2 domain) + causal mask ----
            #pragma unroll
            for (int nt = 0; nt < 8; nt++) {
                int kc = kt * 64 + nt * 8 + (lid & 3) * 2;
                #pragma unroll
                for (int j = 0; j < 4; j++) sacc[nt][j] *= SC;
                if (kc > qrA)         sacc[nt][0] = -1e9f;
                if (kc + 1 > qrA)     sacc[nt][1] = -1e9f;
                if (kc > qrA + 8)     sacc[nt][2] = -1e9f;
                if (kc + 1 > qrA + 8) sacc[nt][3] = -1e9f;
            }

            // ---- online softmax (base-2) with corr-skip ----
            float rmA = -1e30f, rmB = -1e30f;
            #pragma unroll
            for (int nt = 0; nt < 8; nt++) {
                rmA = fmaxf(rmA, fmaxf(sacc[nt][0], sacc[nt][1]));
                rmB = fmaxf(rmB, fmaxf(sacc[nt][2], sacc[nt][3]));
            }
            rmA = fmaxf(rmA, __shfl_xor_sync(0xffffffffu, rmA, 1));
            rmA = fmaxf(rmA, __shfl_xor_sync(0xffffffffu, rmA, 2));
            rmB = fmaxf(rmB, __shfl_xor_sync(0xffffffffu, rmB, 1));
            rmB = fmaxf(rmB, __shfl_xor_sync(0xffffffffu, rmB, 2));
            float mnA = fmaxf(mA, rmA), mnB = fmaxf(mB, rmB);
            float corrA = 1.f, corrB = 1.f;
            if (mnA > mA || mnB > mB) {
                corrA = exp2f(mA - mnA);
                corrB = exp2f(mB - mnB);
                #pragma unroll
                for (int nt = 0; nt < 8; nt++) {
                    oacc[nt][0] *= corrA; oacc[nt][1] *= corrA;
                    oacc[nt][2] *= corrB; oacc[nt][3] *= corrB;
                }
            }
            mA = mnA; mB = mnB;
            float rsA = 0.f, rsB = 0.f;
            #pragma unroll
            for (int nt = 0; nt < 8; nt++) {
                sacc[nt][0] = exp2f(sacc[nt][0] - mA);
                sacc[nt][1] = exp2f(sacc[nt][1] - mA);
                sacc[nt][2] = exp2f(sacc[nt][2] - mB);
                sacc[nt][3] = exp2f(sacc[nt][3] - mB);
                rsA += sacc[nt][0] + sacc[nt][1];
                rsB += sacc[nt][2] + sacc[nt][3];
            }
            rsA += __shfl_xor_sync(0xffffffffu, rsA, 1);
            rsA += __shfl_xor_sync(0xffffffffu, rsA, 2);
            rsB += __shfl_xor_sync(0xffffffffu, rsB, 1);
            rsB += __shfl_xor_sync(0xffffffffu, rsB, 2);
            lA = lA * corrA + rsA;
            lB = lB * corrB + rsB;

            // ---- O += P V (fp16; V untransposed via ldmatrix.trans) ----
            #pragma unroll
            for (int k2 = 0; k2 < 4; k2++) {
                uint32_t pa[4];
                pa[0] = packh(sacc[2*k2][0],   sacc[2*k2][1]);
                pa[1] = packh(sacc[2*k2][2],   sacc[2*k2][3]);
                pa[2] = packh(sacc[2*k2+1][0], sacc[2*k2+1][1]);
                pa[3] = packh(sacc[2*k2+1][2], sacc[2*k2+1][3]);
                #pragma unroll
                for (int p = 0; p < 4; p++) {
                    uint32_t off = SWZ((k2 * 16 + vrow16) * 128 + p * 32 + vhi16 * 16);
                    uint32_t b0, b1, b2, b3;
                    LDSM4T(b0, b1, b2, b3, vb + off);
                    MMAH(oacc[2*p],   pa, b0, b1);
                    MMAH(oacc[2*p+1], pa, b2, b3);
                }
            }
        }
        __syncthreads();
    }

    // ---- epilogue: normalize, fp16 store ----
    float invA = 1.f / lA, invB = 1.f / lB;
    size_t rowA = (size_t)(b * TT + qrA);
    size_t rowB = rowA + 8;
    int colb = h * HD + (lid & 3) * 2;
    #pragma unroll
    for (int nt = 0; nt < 8; nt++) {
        *(uint32_t*)&Oh[rowA * DD + colb + nt * 8] =
            packh(oacc[nt][0] * invA, oacc[nt][1] * invA);
        *(uint32_t*)&Oh[rowB * DD + colb + nt * 8] =
            packh(oacc[nt][2] * invB, oacc[nt][3] * invB);
    }
}

// ---------------------------------------------------------------------------
// prep: x fp16 hi/lo split + fused QKV weight transpose (fp16) +
// Wo transpose (fp16) + rope table (sections on blockIdx.x)
// ---------------------------------------------------------------------------
__device__ __forceinline__ void convT16_body(const float* __restrict__ W,
        __half* __restrict__ t16, int Kd, int Nd, int idx, int tid, float (*Ts)[33]) {
    int nt = idx % (Nd / 32), kt = idx / (Nd / 32);
    int k0 = kt * 32, n0 = nt * 32;
    int r = tid >> 3, c4 = (tid & 7) * 4;
    float4 v = *(const float4*)&W[(size_t)(k0 + r) * Nd + n0 + c4];
    Ts[r][c4] = v.x; Ts[r][c4 + 1] = v.y; Ts[r][c4 + 2] = v.z; Ts[r][c4 + 3] = v.w;
    __syncthreads();
    #pragma unroll
    for (int j = 0; j < 4; j++) {
        size_t o = (size_t)(n0 + r) * Kd + k0 + c4 + j;
        t16[o] = __float2half_rn(Ts[c4 + j][r]);
    }
}

__global__ __launch_bounds__(256) void prep(const float* __restrict__ x,
        const float* __restrict__ Wq, const float* __restrict__ Wk,
        const float* __restrict__ Wv, const float* __restrict__ Wo) {
    __shared__ float Ts[32][33];
    int bx = blockIdx.x, tid = threadIdx.x;
    if (bx < 4096) {                       // x fp16 hi/lo split
        int i = (bx * 256 + tid) * 4;
        float4 v = *(const float4*)(x + i);
        float vv[4] = {v.x, v.y, v.z, v.w};
        #pragma unroll
        for (int j = 0; j < 4; j++) {
            __half h = __float2half_rn(vv[j]);
            g_x16hi[i + j] = h;
            g_x16lo[i + j] = __float2half_rn(vv[j] - __half2float(h));
        }
    } else if (bx < 5120) {
        convT16_body(Wq, g_w16, DD, DD, bx - 4096, tid, Ts);
    } else if (bx < 5376) {
        convT16_body(Wk, g_w16 + (size_t)NH * HD * DD, DD, NKV * HD, bx - 5120, tid, Ts);
    } else if (bx < 5632) {
        convT16_body(Wv, g_w16 + (size_t)(NH + NKV) * HD * DD, DD, NKV * HD,
                     bx - 5376, tid, Ts);
    } else if (bx < 6656) {
        convT16_body(Wo, g_wo16, DD, DD, bx - 5632, tid, Ts);
    } else {                               // rope table (fp32 trig; freq kept
                                           // bit-identical via double pow)
        int idx = (bx - 6656) * 256 + tid;
        int t = idx >> 5, pair = idx & 31;
        float freq = (float)pow(500000.0, -(double)pair / 32.0);
        float ang = (float)t * freq;
        float s, c;
        sincosf(ang, &s, &c);
        g_cos[idx] = c;
        g_sin[idx] = s;
    }
}

// ---------------------------------------------------------------------------
extern "C" void kernel_launch(void* const* d_in, const int* in_sizes, int n_in,
                              void* d_out, int out_size) {
    const float* x  = (const float*)d_in[0];
    // d_in[1] = causal mask — handled analytically
    const float* Wq = (const float*)d_in[2];
    const float* Wk = (const float*)d_in[3];
    const float* Wv = (const float*)d_in[4];
    const float* Wo = (const float*)d_in[5];
    float* out = (float*)d_out;

    __half *x16hi, *x16lo, *w16, *wo16;
    __half *q16, *k16, *v16, *a16;
    cudaGetSymbolAddress((void**)&x16hi, g_x16hi);
    cudaGetSymbolAddress((void**)&x16lo, g_x16lo);
    cudaGetSymbolAddress((void**)&w16,  g_w16);
    cudaGetSymbolAddress((void**)&wo16, g_wo16);
    cudaGetSymbolAddress((void**)&q16, g_q16);
    cudaGetSymbolAddress((void**)&k16, g_k16);
    cudaGetSymbolAddress((void**)&v16, g_v16);
    cudaGetSymbolAddress((void**)&a16, g_a16);

    cudaFuncSetAttribute(gemm_qkv, cudaFuncAttributeMaxDynamicSharedMemorySize, 147456);
    cudaFuncSetAttribute(gemm_out, cudaFuncAttributeMaxDynamicSharedMemorySize, 73728);
    cudaFuncSetAttribute(attn_mma, cudaFuncAttributeMaxDynamicSharedMemorySize, 57344);

    prep<<<6912, 256>>>(x, Wq, Wk, Wv, Wo);

    // fused QKV projection + RoPE epilogue
    gemm_qkv<<<dim3(NQKV / 128, MM / 128), 256, 147456>>>(x16hi, x16lo, w16,
                                                          MM, NQKV, DD);

    attn_mma<<<dim3(TT / 64, BB * NH), 128, 57344>>>(q16, k16, v16, a16);

    gemm_out<<<dim3(DD / 128, MM / 64), 128, 73728>>>(a16, wo16, out,
                                                      MM, DD, DD);
}

// round 13
// speedup vs baseline: 1.7093x; 1.0158x over previous
#include <cuda_runtime.h>
#include <cuda_bf16.h>
#include <cuda_fp16.h>
#include <math.h>
#include <stdint.h>

#define BB 2
#define TT 2048
#define DD 1024
#define NH 16
#define NKV 4
#define HD 64
#define NREP 4           // NH / NKV
#define MM (BB*TT)       // 4096
#define NQKV (NH*HD + 2*NKV*HD)   // 1536 fused QKV output width

// ---------------- scratch (device globals; no runtime allocation) -----------
__device__ __align__(16) float g_cos[TT*32];
__device__ __align__(16) float g_sin[TT*32];
__device__ __half g_x16hi[MM*DD], g_x16lo[MM*DD];   // x fp16 2-term split
__device__ __half g_w16[NQKV*DD];                   // fused QKV weights^T fp16 [N][K]
__device__ __half g_wo16[DD*DD];                    // Wo^T fp16 [N][K]
__device__ __half g_q16[BB*NH*TT*HD];               // Q fp16 [b][h][t][d]
__device__ __half g_k16[BB*NKV*TT*HD];              // K fp16 [b][kvh][t][d]
__device__ __half g_v16[BB*NKV*TT*HD];              // V fp16 [b][kvh][t][d]
__device__ __half g_a16[MM*DD];                     // attention out fp16

// ---------------- helpers ----------------------------------------------------
__device__ __forceinline__ uint32_t smem_u32(const void* p) {
    uint32_t a;
    asm("{ .reg .u64 t; cvta.to.shared.u64 t, %1; cvt.u32.u64 %0, t; }"
        : "=r"(a) : "l"(p));
    return a;
}
#define SWZ(off) ((off) ^ (((off) >> 3) & 0x70))

#define CP_ASYNC16(dst, src) \
    asm volatile("cp.async.cg.shared.global [%0], [%1], 16;" \
                 :: "r"(dst), "l"(src) : "memory")
#define CP_COMMIT() asm volatile("cp.async.commit_group;" ::: "memory")
#define CP_WAIT(n)  asm volatile("cp.async.wait_group %0;" :: "n"(n) : "memory")

#define LDSM4(r0, r1, r2, r3, addr) \
    asm volatile("ldmatrix.sync.aligned.m8n8.x4.shared.b16 {%0,%1,%2,%3}, [%4];" \
                 : "=r"(r0), "=r"(r1), "=r"(r2), "=r"(r3) : "r"(addr))

#define LDSM4T(r0, r1, r2, r3, addr) \
    asm volatile("ldmatrix.sync.aligned.m8n8.x4.trans.shared.b16 {%0,%1,%2,%3}, [%4];" \
                 : "=r"(r0), "=r"(r1), "=r"(r2), "=r"(r3) : "r"(addr))

#define MMAH(c, a, b0, b1) \
    asm volatile("mma.sync.aligned.m16n8k16.row.col.f32.f16.f16.f32 " \
                 "{%0,%1,%2,%3}, {%4,%5,%6,%7}, {%8,%9}, {%0,%1,%2,%3};" \
                 : "+f"((c)[0]), "+f"((c)[1]), "+f"((c)[2]), "+f"((c)[3]) \
                 : "r"((a)[0]), "r"((a)[1]), "r"((a)[2]), "r"((a)[3]), \
                   "r"(b0), "r"(b1))

__device__ __forceinline__ uint32_t packh(float a, float b) {
    __half2 h = __floats2half2_rn(a, b);
    return *(uint32_t*)&h;
}

// ---------------------------------------------------------------------------
// QKV GEMM: (xhi+xlo fp16) @ (W fp16)^T, fp32 acc.
// 64x128 CTA tile, 128 threads (4 warps, each full-M x 32-N), BK=64,
// 3-stage cp.async (3 x 32KB) -> 2 CTAs/SM.
// Fused epilogue: RoPE (smem-staged cos/sin), Q/K/V -> fp16.
// ---------------------------------------------------------------------------
__global__ __launch_bounds__(128, 2) void gemm_qkv(
        const __half* __restrict__ Ahi, const __half* __restrict__ Alo,
        const __half* __restrict__ B16, int M, int N, int K) {
    extern __shared__ char smem[];
    uint32_t sbase = smem_u32(smem);
    int tid = threadIdx.x, wid = tid >> 5, lid = tid & 31;
    int m0 = blockIdx.y * 64, n0 = blockIdx.x * 128;
    const int nch = K / 64;
    const int rr = tid >> 3, uu = tid & 7;   // rr 0..15

    float acc[4][4][4] = {};

    auto load_chunk = [&](int buf, int ch) {
        int k0 = ch * 64;
        uint32_t dbase = sbase + (uint32_t)buf * 32768u;
        #pragma unroll
        for (int it = 0; it < 4; it++) {       // A hi: 64 rows
            int r = it * 16 + rr;
            CP_ASYNC16(dbase + SWZ(r * 128 + uu * 16),
                       Ahi + (size_t)(m0 + r) * K + k0 + uu * 8);
        }
        #pragma unroll
        for (int it = 0; it < 4; it++) {       // A lo: 64 rows
            int r = it * 16 + rr;
            CP_ASYNC16(dbase + 8192u + SWZ(r * 128 + uu * 16),
                       Alo + (size_t)(m0 + r) * K + k0 + uu * 8);
        }
        #pragma unroll
        for (int it = 0; it < 8; it++) {       // B: 128 rows
            int r = it * 16 + rr;
            CP_ASYNC16(dbase + 16384u + SWZ(r * 128 + uu * 16),
                       B16 + (size_t)(n0 + r) * K + k0 + uu * 8);
        }
        CP_COMMIT();
    };

    load_chunk(0, 0);
    load_chunk(1, 1);

    for (int ch = 0; ch < nch; ch++) {
        if (ch < nch - 1) { CP_WAIT(1); } else { CP_WAIT(0); }
        __syncthreads();
        if (ch + 2 < nch) load_chunk((ch + 2) % 3, ch + 2);

        uint32_t db = sbase + (uint32_t)(ch % 3) * 32768u;
        uint32_t abh = db, abl = db + 8192u, bb = db + 16384u;
        int g = lid >> 3, w8 = lid & 7;

        #pragma unroll
        for (int ks = 0; ks < 4; ks++) {
            uint32_t ah[4][4], al[4][4], bh[4][2];
            int arow = lid & 15;
            int acol = ks * 32 + (lid >> 4) * 16;
            #pragma unroll
            for (int mi = 0; mi < 4; mi++) {
                uint32_t off = SWZ((arow + mi * 16) * 128 + acol);
                LDSM4(ah[mi][0], ah[mi][1], ah[mi][2], ah[mi][3], abh + off);
                LDSM4(al[mi][0], al[mi][1], al[mi][2], al[mi][3], abl + off);
            }
            #pragma unroll
            for (int p = 0; p < 2; p++) {
                int nrow = wid * 32 + p * 16 + (g >> 1) * 8 + w8;
                uint32_t off = SWZ(nrow * 128 + ks * 32 + (g & 1) * 16);
                LDSM4(bh[2*p][0], bh[2*p][1], bh[2*p+1][0], bh[2*p+1][1], bb + off);
            }
            #pragma unroll
            for (int mi = 0; mi < 4; mi++)
                #pragma unroll
                for (int ni = 0; ni < 4; ni++) {
                    MMAH(acc[mi][ni], ah[mi], bh[ni][0], bh[ni][1]);
                    MMAH(acc[mi][ni], al[mi], bh[ni][0], bh[ni][1]);
                }
        }
        __syncthreads();
    }

    // ---- fused epilogue ----
    // cols [0,1024)=Q, [1024,1280)=K, [1280,1536)=V (uniform per CTA)
    int region = (blockIdx.x < 8) ? 0 : (blockIdx.x < 10) ? 1 : 2;
    float* cs_s = (float*)smem;               // 8KB: cos[64][32]
    float* sn_s = (float*)(smem + 8192);      // 8KB: sin[64][32]
    if (region < 2) {
        int tbase = m0 & (TT - 1);
        #pragma unroll
        for (int i = 0; i < 4; i++) {
            int idx = i * 128 + tid;          // 512 float4 per table
            *(float4*)(smem + idx * 16) =
                *(const float4*)&g_cos[(size_t)tbase * 32 + idx * 4];
            *(float4*)(smem + 8192 + idx * 16) =
                *(const float4*)&g_sin[(size_t)tbase * 32 + idx * 4];
        }
        __syncthreads();
    }
    #pragma unroll
    for (int mi = 0; mi < 4; mi++) {
        int row = m0 + mi * 16 + (lid >> 2);
        #pragma unroll
        for (int r2 = 0; r2 < 2; r2++) {
            int trow = row + r2 * 8;
            int b = trow >> 11, t = trow & (TT - 1);
            int tl = trow - m0;
            #pragma unroll
            for (int ni = 0; ni < 4; ni++) {
                int c = n0 + wid * 32 + ni * 8 + (lid & 3) * 2;
                float v0 = acc[mi][ni][r2 * 2], v1 = acc[mi][ni][r2 * 2 + 1];
                if (region == 2) {
                    int cc = c - 1280;
                    int kvh = cc >> 6, d = cc & 63;
                    *(uint32_t*)&g_v16[((size_t)(b * NKV + kvh) * TT + t) * HD + d] =
                        packh(v0, v1);
                } else {
                    int cc = (region == 1) ? c - 1024 : c;
                    int hh = cc >> 6, d = cc & 63;
                    int ci = tl * 32 + (d >> 1);
                    float cs = cs_s[ci], sn = sn_s[ci];
                    float r0 = v0 * cs - v1 * sn;
                    float r1 = v1 * cs + v0 * sn;
                    if (region == 1) {
                        size_t o = ((size_t)(b * NKV + hh) * TT + t) * HD + d;
                        *(uint32_t*)&g_k16[o] = packh(r0, r1);
                    } else {
                        size_t o = ((size_t)(b * NH + hh) * TT + t) * HD + d;
                        *(uint32_t*)&g_q16[o] = packh(r0, r1);
                    }
                }
            }
        }
    }
}

// ---------------------------------------------------------------------------
// O-projection GEMM: single-term fp16 x fp16 (fp32 acc).
// 64x128 CTA tile, 128 threads, 3-stage (3 x 24KB) -> 2 CTAs/SM.
// ---------------------------------------------------------------------------
__global__ __launch_bounds__(128, 2) void gemm_out(
        const __half* __restrict__ A, const __half* __restrict__ B,
        float* __restrict__ C, int M, int N, int K) {
    extern __shared__ char smem[];
    uint32_t sbase = smem_u32(smem);
    int tid = threadIdx.x, wid = tid >> 5, lid = tid & 31;
    int m0 = blockIdx.y * 64, n0 = blockIdx.x * 128;
    const int nch = K / 64;
    const int rr = tid >> 3, uu = tid & 7;

    float acc[4][4][4] = {};

    auto load_chunk = [&](int buf, int ch) {
        int k0 = ch * 64;
        uint32_t dbase = sbase + (uint32_t)buf * 24576u;
        #pragma unroll
        for (int it = 0; it < 4; it++) {
            int r = it * 16 + rr;
            CP_ASYNC16(dbase + SWZ(r * 128 + uu * 16),
                       A + (size_t)(m0 + r) * K + k0 + uu * 8);
        }
        #pragma unroll
        for (int it = 0; it < 8; it++) {
            int r = it * 16 + rr;
            CP_ASYNC16(dbase + 8192u + SWZ(r * 128 + uu * 16),
                       B + (size_t)(n0 + r) * K + k0 + uu * 8);
        }
        CP_COMMIT();
    };

    load_chunk(0, 0);
    load_chunk(1, 1);

    for (int ch = 0; ch < nch; ch++) {
        if (ch < nch - 1) { CP_WAIT(1); } else { CP_WAIT(0); }
        __syncthreads();
        if (ch + 2 < nch) load_chunk((ch + 2) % 3, ch + 2);

        uint32_t db = sbase + (uint32_t)(ch % 3) * 24576u;
        uint32_t ab_ = db, bb = db + 8192u;
        int g = lid >> 3, w8 = lid & 7;

        #pragma unroll
        for (int ks = 0; ks < 4; ks++) {
            uint32_t ah[4][4], bh[4][2];
            int arow = lid & 15;
            int acol = ks * 32 + (lid >> 4) * 16;
            #pragma unroll
            for (int mi = 0; mi < 4; mi++) {
                uint32_t off = SWZ((arow + mi * 16) * 128 + acol);
                LDSM4(ah[mi][0], ah[mi][1], ah[mi][2], ah[mi][3], ab_ + off);
            }
            #pragma unroll
            for (int p = 0; p < 2; p++) {
                int nrow = wid * 32 + p * 16 + (g >> 1) * 8 + w8;
                uint32_t off = SWZ(nrow * 128 + ks * 32 + (g & 1) * 16);
                LDSM4(bh[2*p][0], bh[2*p][1], bh[2*p+1][0], bh[2*p+1][1], bb + off);
            }
            #pragma unroll
            for (int mi = 0; mi < 4; mi++)
                #pragma unroll
                for (int ni = 0; ni < 4; ni++)
                    MMAH(acc[mi][ni], ah[mi], bh[ni][0], bh[ni][1]);
        }
        __syncthreads();
    }

    #pragma unroll
    for (int mi = 0; mi < 4; mi++) {
        int row = m0 + mi * 16 + (lid >> 2);
        #pragma unroll
        for (int ni = 0; ni < 4; ni++) {
            int col = n0 + wid * 32 + ni * 8 + (lid & 3) * 2;
            *(float2*)&C[(size_t)row * N + col] =
                make_float2(acc[mi][ni][0], acc[mi][ni][1]);
            *(float2*)&C[(size_t)(row + 8) * N + col] =
                make_float2(acc[mi][ni][2], acc[mi][ni][3]);
        }
    }
}

// ---------------------------------------------------------------------------
// HMMA flash attention, causal. 64-query tiles, 128 threads (4 warps),
// grid (T/64 reversed, B*NH). smem: Q 8KB + 3 x 16KB = 56KB -> 3 CTAs/SM.
// S = Q(fp16) K(fp16)^T single-term; PV fp16 (V via ldmatrix.trans).
// Causal mask applied only on the diagonal chunk.
// ---------------------------------------------------------------------------
__global__ __launch_bounds__(128, 3) void attn_mma(
        const __half* __restrict__ Q16, const __half* __restrict__ K16,
        const __half* __restrict__ Vt, __half* __restrict__ Oh) {
    extern __shared__ char smem[];
    uint32_t sbase = smem_u32(smem);
    const uint32_t QHI = 0, BUF = 8192;   // 3 x 16KB chunk buffers

    int tid = threadIdx.x, wid = tid >> 5, lid = tid & 31;
    int qt = gridDim.x - 1 - blockIdx.x;
    int bh = blockIdx.y;
    int b = bh / NH, h = bh % NH, kvh = h / NREP;
    int q0 = qt * 64;

    const __half* qb16 = Q16 + (size_t)(b * NH + h) * TT * HD;
    const __half* kb16 = K16 + (size_t)(b * NKV + kvh) * TT * HD;
    const __half* vbase = Vt + (size_t)(b * NKV + kvh) * TT * HD;   // [t][d]

    // stage Q (own commit group): 64 rows
    {
        #pragma unroll
        for (int it = 0; it < 4; it++) {
            int idx = it * 128 + tid;
            int r = idx >> 3, u = idx & 7;
            CP_ASYNC16(sbase + QHI + SWZ(r * 128 + u * 16),
                       qb16 + (size_t)(q0 + r) * HD + u * 8);
        }
        CP_COMMIT();
    }

    auto load_chunk = [&](int buf, int kt) {
        uint32_t db = sbase + BUF + (uint32_t)buf * 16384u;
        #pragma unroll
        for (int arr = 0; arr < 2; arr++) {
            uint32_t ab = db + (uint32_t)arr * 8192u;
            const __half* s = arr ? vbase : kb16;
            #pragma unroll
            for (int it = 0; it < 4; it++) {
                int idx = it * 128 + tid;
                int r = idx >> 3, u = idx & 7;
                CP_ASYNC16(ab + SWZ(r * 128 + u * 16),
                           s + (size_t)(kt * 64 + r) * HD + u * 8);
            }
        }
        CP_COMMIT();
    };

    int nch = qt + 1;
    load_chunk(0, 0);
    load_chunk(1, (nch > 1) ? 1 : 0);

    CP_WAIT(2);
    __syncthreads();
    uint32_t qf[4][4];
    {
        int arow = wid * 16 + (lid & 15);
        #pragma unroll
        for (int ks = 0; ks < 4; ks++) {
            uint32_t off = SWZ(arow * 128 + ks * 32 + (lid >> 4) * 16);
            LDSM4(qf[ks][0], qf[ks][1], qf[ks][2], qf[ks][3], sbase + QHI + off);
        }
    }

    float oacc[8][4] = {};
    float mA = -1e30f, mB = -1e30f, lA = 0.f, lB = 0.f;
    const int g = lid >> 3, w8 = lid & 7;
    const int qrA = q0 + wid * 16 + (lid >> 2);
    const float SC = 0.125f * 1.4426950408889634f;   // scale * log2(e)
    const int vrow16 = lid & 15, vhi16 = (lid >> 4) & 1;

    for (int ch = 0; ch < nch; ch++) {
        if (ch < nch - 1) { CP_WAIT(1); } else { CP_WAIT(0); }
        __syncthreads();
        if (ch + 2 < nch) load_chunk((ch + 2) % 3, ch + 2);

        int kt = ch;
        {
            uint32_t kb = sbase + BUF + (uint32_t)(ch % 3) * 16384u;
            uint32_t vb = kb + 8192u;

            // ---- S = Q K^T (single-term fp16) ----
            float sacc[8][4] = {};
            #pragma unroll
            for (int ks = 0; ks < 4; ks++) {
                #pragma unroll
                for (int p = 0; p < 4; p++) {
                    int nrow = p * 16 + (g >> 1) * 8 + w8;
                    uint32_t off = SWZ(nrow * 128 + ks * 32 + (g & 1) * 16);
                    uint32_t b0, b1, b2, b3;
                    LDSM4(b0, b1, b2, b3, kb + off);
                    MMAH(sacc[2*p],   qf[ks], b0, b1);
                    MMAH(sacc[2*p+1], qf[ks], b2, b3);
                }
            }

            // ---- scale (log2 domain); causal mask on diagonal chunk only ----
            #pragma unroll
            for (int nt = 0; nt < 8; nt++)
                #pragma unroll
                for (int j = 0; j < 4; j++) sacc[nt][j] *= SC;
            if (kt == qt) {
                #pragma unroll
                for (int nt = 0; nt < 8; nt++) {
                    int kc = kt * 64 + nt * 8 + (lid & 3) * 2;
                    if (kc > qrA)         sacc[nt][0] = -1e9f;
                    if (kc + 1 > qrA)     sacc[nt][1] = -1e9f;
                    if (kc > qrA + 8)     sacc[nt][2] = -1e9f;
                    if (kc + 1 > qrA + 8) sacc[nt][3] = -1e9f;
                }
            }

            // ---- online softmax (base-2) with corr-skip ----
            float rmA = -1e30f, rmB = -1e30f;
            #pragma unroll
            for (int nt = 0; nt < 8; nt++) {
                rmA = fmaxf(rmA, fmaxf(sacc[nt][0], sacc[nt][1]));
                rmB = fmaxf(rmB, fmaxf(sacc[nt][2], sacc[nt][3]));
            }
            rmA = fmaxf(rmA, __shfl_xor_sync(0xffffffffu, rmA, 1));
            rmA = fmaxf(rmA, __shfl_xor_sync(0xffffffffu, rmA, 2));
            rmB = fmaxf(rmB, __shfl_xor_sync(0xffffffffu, rmB, 1));
            rmB = fmaxf(rmB, __shfl_xor_sync(0xffffffffu, rmB, 2));
            float mnA = fmaxf(mA, rmA), mnB = fmaxf(mB, rmB);
            float corrA = 1.f, corrB = 1.f;
            if (mnA > mA || mnB > mB) {
                corrA = exp2f(mA - mnA);
                corrB = exp2f(mB - mnB);
                #pragma unroll
                for (int nt = 0; nt < 8; nt++) {
                    oacc[nt][0] *= corrA; oacc[nt][1] *= corrA;
                    oacc[nt][2] *= corrB; oacc[nt][3] *= corrB;
                }
            }
            mA = mnA; mB = mnB;
            float rsA = 0.f, rsB = 0.f;
            #pragma unroll
            for (int nt = 0; nt < 8; nt++) {
                sacc[nt][0] = exp2f(sacc[nt][0] - mA);
                sacc[nt][1] = exp2f(sacc[nt][1] - mA);
                sacc[nt][2] = exp2f(sacc[nt][2] - mB);
                sacc[nt][3] = exp2f(sacc[nt][3] - mB);
                rsA += sacc[nt][0] + sacc[nt][1];
                rsB += sacc[nt][2] + sacc[nt][3];
            }
            rsA += __shfl_xor_sync(0xffffffffu, rsA, 1);
            rsA += __shfl_xor_sync(0xffffffffu, rsA, 2);
            rsB += __shfl_xor_sync(0xffffffffu, rsB, 1);
            rsB += __shfl_xor_sync(0xffffffffu, rsB, 2);
            lA = lA * corrA + rsA;
            lB = lB * corrB + rsB;

            // ---- O += P V (fp16; V untransposed via ldmatrix.trans) ----
            #pragma unroll
            for (int k2 = 0; k2 < 4; k2++) {
                uint32_t pa[4];
                pa[0] = packh(sacc[2*k2][0],   sacc[2*k2][1]);
                pa[1] = packh(sacc[2*k2][2],   sacc[2*k2][3]);
                pa[2] = packh(sacc[2*k2+1][0], sacc[2*k2+1][1]);
                pa[3] = packh(sacc[2*k2+1][2], sacc[2*k2+1][3]);
                #pragma unroll
                for (int p = 0; p < 4; p++) {
                    uint32_t off = SWZ((k2 * 16 + vrow16) * 128 + p * 32 + vhi16 * 16);
                    uint32_t b0, b1, b2, b3;
                    LDSM4T(b0, b1, b2, b3, vb + off);
                    MMAH(oacc[2*p],   pa, b0, b1);
                    MMAH(oacc[2*p+1], pa, b2, b3);
                }
            }
        }
        __syncthreads();
    }

    // ---- epilogue: normalize, fp16 store ----
    float invA = 1.f / lA, invB = 1.f / lB;
    size_t rowA = (size_t)(b * TT + qrA);
    size_t rowB = rowA + 8;
    int colb = h * HD + (lid & 3) * 2;
    #pragma unroll
    for (int nt = 0; nt < 8; nt++) {
        *(uint32_t*)&Oh[rowA * DD + colb + nt * 8] =
            packh(oacc[nt][0] * invA, oacc[nt][1] * invA);
        *(uint32_t*)&Oh[rowB * DD + colb + nt * 8] =
            packh(oacc[nt][2] * invB, oacc[nt][3] * invB);
    }
}

// ---------------------------------------------------------------------------
// prep: x fp16 hi/lo split + fused QKV weight transpose (fp16) +
// Wo transpose (fp16) + rope table (sections on blockIdx.x)
// ---------------------------------------------------------------------------
__device__ __forceinline__ void convT16_body(const float* __restrict__ W,
        __half* __restrict__ t16, int Kd, int Nd, int idx, int tid, float (*Ts)[33]) {
    int nt = idx % (Nd / 32), kt = idx / (Nd / 32);
    int k0 = kt * 32, n0 = nt * 32;
    int r = tid >> 3, c4 = (tid & 7) * 4;
    float4 v = *(const float4*)&W[(size_t)(k0 + r) * Nd + n0 + c4];
    Ts[r][c4] = v.x; Ts[r][c4 + 1] = v.y; Ts[r][c4 + 2] = v.z; Ts[r][c4 + 3] = v.w;
    __syncthreads();
    #pragma unroll
    for (int j = 0; j < 4; j++) {
        size_t o = (size_t)(n0 + r) * Kd + k0 + c4 + j;
        t16[o] = __float2half_rn(Ts[c4 + j][r]);
    }
}

__global__ __launch_bounds__(256) void prep(const float* __restrict__ x,
        const float* __restrict__ Wq, const float* __restrict__ Wk,
        const float* __restrict__ Wv, const float* __restrict__ Wo) {
    __shared__ float Ts[32][33];
    int bx = blockIdx.x, tid = threadIdx.x;
    if (bx < 4096) {                       // x fp16 hi/lo split
        int i = (bx * 256 + tid) * 4;
        float4 v = *(const float4*)(x + i);
        float vv[4] = {v.x, v.y, v.z, v.w};
        #pragma unroll
        for (int j = 0; j < 4; j++) {
            __half h = __float2half_rn(vv[j]);
            g_x16hi[i + j] = h;
            g_x16lo[i + j] = __float2half_rn(vv[j] - __half2float(h));
        }
    } else if (bx < 5120) {
        convT16_body(Wq, g_w16, DD, DD, bx - 4096, tid, Ts);
    } else if (bx < 5376) {
        convT16_body(Wk, g_w16 + (size_t)NH * HD * DD, DD, NKV * HD, bx - 5120, tid, Ts);
    } else if (bx < 5632) {
        convT16_body(Wv, g_w16 + (size_t)(NH + NKV) * HD * DD, DD, NKV * HD,
                     bx - 5376, tid, Ts);
    } else if (bx < 6656) {
        convT16_body(Wo, g_wo16, DD, DD, bx - 5632, tid, Ts);
    } else {                               // rope table (fp32 trig; freq kept
                                           // bit-identical via double pow)
        int idx = (bx - 6656) * 256 + tid;
        int t = idx >> 5, pair = idx & 31;
        float freq = (float)pow(500000.0, -(double)pair / 32.0);
        float ang = (float)t * freq;
        float s, c;
        sincosf(ang, &s, &c);
        g_cos[idx] = c;
        g_sin[idx] = s;
    }
}

// ---------------------------------------------------------------------------
extern "C" void kernel_launch(void* const* d_in, const int* in_sizes, int n_in,
                              void* d_out, int out_size) {
    const float* x  = (const float*)d_in[0];
    // d_in[1] = causal mask — handled analytically
    const float* Wq = (const float*)d_in[2];
    const float* Wk = (const float*)d_in[3];
    const float* Wv = (const float*)d_in[4];
    const float* Wo = (const float*)d_in[5];
    float* out = (float*)d_out;

    __half *x16hi, *x16lo, *w16, *wo16;
    __half *q16, *k16, *v16, *a16;
    cudaGetSymbolAddress((void**)&x16hi, g_x16hi);
    cudaGetSymbolAddress((void**)&x16lo, g_x16lo);
    cudaGetSymbolAddress((void**)&w16,  g_w16);
    cudaGetSymbolAddress((void**)&wo16, g_wo16);
    cudaGetSymbolAddress((void**)&q16, g_q16);
    cudaGetSymbolAddress((void**)&k16, g_k16);
    cudaGetSymbolAddress((void**)&v16, g_v16);
    cudaGetSymbolAddress((void**)&a16, g_a16);

    cudaFuncSetAttribute(gemm_qkv, cudaFuncAttributeMaxDynamicSharedMemorySize, 98304);
    cudaFuncSetAttribute(gemm_out, cudaFuncAttributeMaxDynamicSharedMemorySize, 73728);
    cudaFuncSetAttribute(attn_mma, cudaFuncAttributeMaxDynamicSharedMemorySize, 57344);

    prep<<<6912, 256>>>(x, Wq, Wk, Wv, Wo);

    // fused QKV projection + RoPE epilogue
    gemm_qkv<<<dim3(NQKV / 128, MM / 64), 128, 98304>>>(x16hi, x16lo, w16,
                                                        MM, NQKV, DD);

    attn_mma<<<dim3(TT / 64, BB * NH), 128, 57344>>>(q16, k16, v16, a16);

    gemm_out<<<dim3(DD / 128, MM / 64), 128, 73728>>>(a16, wo16, out,
                                                      MM, DD, DD);
}

// round 14
// speedup vs baseline: 2.0714x; 1.2118x over previous
#include <cuda_runtime.h>
#include <cuda_bf16.h>
#include <cuda_fp16.h>
#include <math.h>
#include <stdint.h>

#define BB 2
#define TT 2048
#define DD 1024
#define NH 16
#define NKV 4
#define HD 64
#define NREP 4           // NH / NKV
#define MM (BB*TT)       // 4096
#define NQKV (NH*HD + 2*NKV*HD)   // 1536 fused QKV output width

// ---------------- scratch (device globals; no runtime allocation) -----------
__device__ __align__(16) float g_cos[TT*32];
__device__ __align__(16) float g_sin[TT*32];
__device__ __half g_x16[MM*DD];                     // x fp16
__device__ __half g_w16[NQKV*DD];                   // fused QKV weights^T fp16 [N][K]
__device__ __half g_wo16[DD*DD];                    // Wo^T fp16 [N][K]
__device__ __half g_q16[BB*NH*TT*HD];               // Q fp16 [b][h][t][d]
__device__ __half g_k16[BB*NKV*TT*HD];              // K fp16 [b][kvh][t][d]
__device__ __half g_v16[BB*NKV*TT*HD];              // V fp16 [b][kvh][t][d]
__device__ __half g_a16[MM*DD];                     // attention out fp16

// ---------------- helpers ----------------------------------------------------
__device__ __forceinline__ uint32_t smem_u32(const void* p) {
    uint32_t a;
    asm("{ .reg .u64 t; cvta.to.shared.u64 t, %1; cvt.u32.u64 %0, t; }"
        : "=r"(a) : "l"(p));
    return a;
}
#define SWZ(off) ((off) ^ (((off) >> 3) & 0x70))

#define CP_ASYNC16(dst, src) \
    asm volatile("cp.async.cg.shared.global [%0], [%1], 16;" \
                 :: "r"(dst), "l"(src) : "memory")
#define CP_COMMIT() asm volatile("cp.async.commit_group;" ::: "memory")
#define CP_WAIT(n)  asm volatile("cp.async.wait_group %0;" :: "n"(n) : "memory")

#define LDSM4(r0, r1, r2, r3, addr) \
    asm volatile("ldmatrix.sync.aligned.m8n8.x4.shared.b16 {%0,%1,%2,%3}, [%4];" \
                 : "=r"(r0), "=r"(r1), "=r"(r2), "=r"(r3) : "r"(addr))

#define LDSM4T(r0, r1, r2, r3, addr) \
    asm volatile("ldmatrix.sync.aligned.m8n8.x4.trans.shared.b16 {%0,%1,%2,%3}, [%4];" \
                 : "=r"(r0), "=r"(r1), "=r"(r2), "=r"(r3) : "r"(addr))

#define MMAH(c, a, b0, b1) \
    asm volatile("mma.sync.aligned.m16n8k16.row.col.f32.f16.f16.f32 " \
                 "{%0,%1,%2,%3}, {%4,%5,%6,%7}, {%8,%9}, {%0,%1,%2,%3};" \
                 : "+f"((c)[0]), "+f"((c)[1]), "+f"((c)[2]), "+f"((c)[3]) \
                 : "r"((a)[0]), "r"((a)[1]), "r"((a)[2]), "r"((a)[3]), \
                   "r"(b0), "r"(b1))

__device__ __forceinline__ uint32_t packh(float a, float b) {
    __half2 h = __floats2half2_rn(a, b);
    return *(uint32_t*)&h;
}

// ---------------------------------------------------------------------------
// QKV GEMM: x(fp16) @ W(fp16)^T, fp32 acc. 64x128 CTA tile, 128 threads
// (4 warps, each full-M x 32-N), BK=64, 3-stage cp.async (3 x 24KB) ->
// 2 CTAs/SM. Fused epilogue: RoPE (smem-staged cos/sin), Q/K/V -> fp16.
// ---------------------------------------------------------------------------
__global__ __launch_bounds__(128, 2) void gemm_qkv(
        const __half* __restrict__ A, const __half* __restrict__ B16,
        int M, int N, int K) {
    extern __shared__ char smem[];
    uint32_t sbase = smem_u32(smem);
    int tid = threadIdx.x, wid = tid >> 5, lid = tid & 31;
    int m0 = blockIdx.y * 64, n0 = blockIdx.x * 128;
    const int nch = K / 64;
    const int rr = tid >> 3, uu = tid & 7;   // rr 0..15

    float acc[4][4][4] = {};

    auto load_chunk = [&](int buf, int ch) {
        int k0 = ch * 64;
        uint32_t dbase = sbase + (uint32_t)buf * 24576u;
        #pragma unroll
        for (int it = 0; it < 4; it++) {       // A: 64 rows
            int r = it * 16 + rr;
            CP_ASYNC16(dbase + SWZ(r * 128 + uu * 16),
                       A + (size_t)(m0 + r) * K + k0 + uu * 8);
        }
        #pragma unroll
        for (int it = 0; it < 8; it++) {       // B: 128 rows
            int r = it * 16 + rr;
            CP_ASYNC16(dbase + 8192u + SWZ(r * 128 + uu * 16),
                       B16 + (size_t)(n0 + r) * K + k0 + uu * 8);
        }
        CP_COMMIT();
    };

    load_chunk(0, 0);
    load_chunk(1, 1);

    for (int ch = 0; ch < nch; ch++) {
        if (ch < nch - 1) { CP_WAIT(1); } else { CP_WAIT(0); }
        __syncthreads();
        if (ch + 2 < nch) load_chunk((ch + 2) % 3, ch + 2);

        uint32_t db = sbase + (uint32_t)(ch % 3) * 24576u;
        uint32_t ab_ = db, bb = db + 8192u;
        int g = lid >> 3, w8 = lid & 7;

        #pragma unroll
        for (int ks = 0; ks < 4; ks++) {
            uint32_t ah[4][4], bh[4][2];
            int arow = lid & 15;
            int acol = ks * 32 + (lid >> 4) * 16;
            #pragma unroll
            for (int mi = 0; mi < 4; mi++) {
                uint32_t off = SWZ((arow + mi * 16) * 128 + acol);
                LDSM4(ah[mi][0], ah[mi][1], ah[mi][2], ah[mi][3], ab_ + off);
            }
            #pragma unroll
            for (int p = 0; p < 2; p++) {
                int nrow = wid * 32 + p * 16 + (g >> 1) * 8 + w8;
                uint32_t off = SWZ(nrow * 128 + ks * 32 + (g & 1) * 16);
                LDSM4(bh[2*p][0], bh[2*p][1], bh[2*p+1][0], bh[2*p+1][1], bb + off);
            }
            #pragma unroll
            for (int mi = 0; mi < 4; mi++)
                #pragma unroll
                for (int ni = 0; ni < 4; ni++)
                    MMAH(acc[mi][ni], ah[mi], bh[ni][0], bh[ni][1]);
        }
        __syncthreads();
    }

    // ---- fused epilogue ----
    // cols [0,1024)=Q, [1024,1280)=K, [1280,1536)=V (uniform per CTA)
    int region = (blockIdx.x < 8) ? 0 : (blockIdx.x < 10) ? 1 : 2;
    float* cs_s = (float*)smem;               // 8KB: cos[64][32]
    float* sn_s = (float*)(smem + 8192);      // 8KB: sin[64][32]
    if (region < 2) {
        int tbase = m0 & (TT - 1);
        #pragma unroll
        for (int i = 0; i < 4; i++) {
            int idx = i * 128 + tid;          // 512 float4 per table
            *(float4*)(smem + idx * 16) =
                *(const float4*)&g_cos[(size_t)tbase * 32 + idx * 4];
            *(float4*)(smem + 8192 + idx * 16) =
                *(const float4*)&g_sin[(size_t)tbase * 32 + idx * 4];
        }
        __syncthreads();
    }
    #pragma unroll
    for (int mi = 0; mi < 4; mi++) {
        int row = m0 + mi * 16 + (lid >> 2);
        #pragma unroll
        for (int r2 = 0; r2 < 2; r2++) {
            int trow = row + r2 * 8;
            int b = trow >> 11, t = trow & (TT - 1);
            int tl = trow - m0;
            #pragma unroll
            for (int ni = 0; ni < 4; ni++) {
                int c = n0 + wid * 32 + ni * 8 + (lid & 3) * 2;
                float v0 = acc[mi][ni][r2 * 2], v1 = acc[mi][ni][r2 * 2 + 1];
                if (region == 2) {
                    int cc = c - 1280;
                    int kvh = cc >> 6, d = cc & 63;
                    *(uint32_t*)&g_v16[((size_t)(b * NKV + kvh) * TT + t) * HD + d] =
                        packh(v0, v1);
                } else {
                    int cc = (region == 1) ? c - 1024 : c;
                    int hh = cc >> 6, d = cc & 63;
                    int ci = tl * 32 + (d >> 1);
                    float cs = cs_s[ci], sn = sn_s[ci];
                    float r0 = v0 * cs - v1 * sn;
                    float r1 = v1 * cs + v0 * sn;
                    if (region == 1) {
                        size_t o = ((size_t)(b * NKV + hh) * TT + t) * HD + d;
                        *(uint32_t*)&g_k16[o] = packh(r0, r1);
                    } else {
                        size_t o = ((size_t)(b * NH + hh) * TT + t) * HD + d;
                        *(uint32_t*)&g_q16[o] = packh(r0, r1);
                    }
                }
            }
        }
    }
}

// ---------------------------------------------------------------------------
// O-projection GEMM: single-term fp16 x fp16 (fp32 acc).
// 128x128 CTA tile, 128 threads (2x2 warps, 64x64 warp tile), BK=64,
// 3-stage cp.async (3 x 32KB) -> 2 CTAs/SM. Grid 256 CTAs = single wave.
// ---------------------------------------------------------------------------
__global__ __launch_bounds__(128, 2) void gemm_out(
        const __half* __restrict__ A, const __half* __restrict__ B,
        float* __restrict__ C, int M, int N, int K) {
    extern __shared__ char smem[];
    uint32_t sbase = smem_u32(smem);
    int tid = threadIdx.x, wid = tid >> 5, lid = tid & 31;
    int m0 = blockIdx.y * 128, n0 = blockIdx.x * 128;
    int wm = wid & 1, wn = wid >> 1;
    const int nch = K / 64;
    const int rr = tid >> 3, uu = tid & 7;   // rr 0..15

    float acc[4][8][4] = {};

    auto load_chunk = [&](int buf, int ch) {
        int k0 = ch * 64;
        uint32_t dbase = sbase + (uint32_t)buf * 32768u;
        #pragma unroll
        for (int it = 0; it < 8; it++) {       // A: 128 rows
            int r = it * 16 + rr;
            CP_ASYNC16(dbase + SWZ(r * 128 + uu * 16),
                       A + (size_t)(m0 + r) * K + k0 + uu * 8);
        }
        #pragma unroll
        for (int it = 0; it < 8; it++) {       // B: 128 rows
            int r = it * 16 + rr;
            CP_ASYNC16(dbase + 16384u + SWZ(r * 128 + uu * 16),
                       B + (size_t)(n0 + r) * K + k0 + uu * 8);
        }
        CP_COMMIT();
    };

    load_chunk(0, 0);
    load_chunk(1, 1);

    for (int ch = 0; ch < nch; ch++) {
        if (ch < nch - 1) { CP_WAIT(1); } else { CP_WAIT(0); }
        __syncthreads();
        if (ch + 2 < nch) load_chunk((ch + 2) % 3, ch + 2);

        uint32_t db = sbase + (uint32_t)(ch % 3) * 32768u;
        uint32_t ab_ = db, bb = db + 16384u;
        int g = lid >> 3, w8 = lid & 7;

        #pragma unroll
        for (int ks = 0; ks < 4; ks++) {
            uint32_t ah[4][4], bh[8][2];
            int arow = wm * 64 + (lid & 15);
            int acol = ks * 32 + (lid >> 4) * 16;
            #pragma unroll
            for (int mi = 0; mi < 4; mi++) {
                uint32_t off = SWZ((arow + mi * 16) * 128 + acol);
                LDSM4(ah[mi][0], ah[mi][1], ah[mi][2], ah[mi][3], ab_ + off);
            }
            #pragma unroll
            for (int p = 0; p < 4; p++) {
                int nrow = wn * 64 + p * 16 + (g >> 1) * 8 + w8;
                uint32_t off = SWZ(nrow * 128 + ks * 32 + (g & 1) * 16);
                LDSM4(bh[2*p][0], bh[2*p][1], bh[2*p+1][0], bh[2*p+1][1], bb + off);
            }
            #pragma unroll
            for (int mi = 0; mi < 4; mi++)
                #pragma unroll
                for (int ni = 0; ni < 8; ni++)
                    MMAH(acc[mi][ni], ah[mi], bh[ni][0], bh[ni][1]);
        }
        __syncthreads();
    }

    #pragma unroll
    for (int mi = 0; mi < 4; mi++) {
        int row = m0 + wm * 64 + mi * 16 + (lid >> 2);
        #pragma unroll
        for (int ni = 0; ni < 8; ni++) {
            int col = n0 + wn * 64 + ni * 8 + (lid & 3) * 2;
            *(float2*)&C[(size_t)row * N + col] =
                make_float2(acc[mi][ni][0], acc[mi][ni][1]);
            *(float2*)&C[(size_t)(row + 8) * N + col] =
                make_float2(acc[mi][ni][2], acc[mi][ni][3]);
        }
    }
}

// ---------------------------------------------------------------------------
// HMMA flash attention, causal. 64-query tiles, 128 threads (4 warps),
// grid (T/64 reversed, B*NH). smem: Q 8KB + 3 x 16KB = 56KB -> 3 CTAs/SM.
// S = Q(fp16) K(fp16)^T single-term; PV fp16 (V via ldmatrix.trans).
// Causal mask applied only on the diagonal chunk.
// ---------------------------------------------------------------------------
__global__ __launch_bounds__(128, 3) void attn_mma(
        const __half* __restrict__ Q16, const __half* __restrict__ K16,
        const __half* __restrict__ Vt, __half* __restrict__ Oh) {
    extern __shared__ char smem[];
    uint32_t sbase = smem_u32(smem);
    const uint32_t QHI = 0, BUF = 8192;   // 3 x 16KB chunk buffers

    int tid = threadIdx.x, wid = tid >> 5, lid = tid & 31;
    int qt = gridDim.x - 1 - blockIdx.x;
    int bh = blockIdx.y;
    int b = bh / NH, h = bh % NH, kvh = h / NREP;
    int q0 = qt * 64;

    const __half* qb16 = Q16 + (size_t)(b * NH + h) * TT * HD;
    const __half* kb16 = K16 + (size_t)(b * NKV + kvh) * TT * HD;
    const __half* vbase = Vt + (size_t)(b * NKV + kvh) * TT * HD;   // [t][d]

    // stage Q (own commit group): 64 rows
    {
        #pragma unroll
        for (int it = 0; it < 4; it++) {
            int idx = it * 128 + tid;
            int r = idx >> 3, u = idx & 7;
            CP_ASYNC16(sbase + QHI + SWZ(r * 128 + u * 16),
                       qb16 + (size_t)(q0 + r) * HD + u * 8);
        }
        CP_COMMIT();
    }

    auto load_chunk = [&](int buf, int kt) {
        uint32_t db = sbase + BUF + (uint32_t)buf * 16384u;
        #pragma unroll
        for (int arr = 0; arr < 2; arr++) {
            uint32_t ab = db + (uint32_t)arr * 8192u;
            const __half* s = arr ? vbase : kb16;
            #pragma unroll
            for (int it = 0; it < 4; it++) {
                int idx = it * 128 + tid;
                int r = idx >> 3, u = idx & 7;
                CP_ASYNC16(ab + SWZ(r * 128 + u * 16),
                           s + (size_t)(kt * 64 + r) * HD + u * 8);
            }
        }
        CP_COMMIT();
    };

    int nch = qt + 1;
    load_chunk(0, 0);
    load_chunk(1, (nch > 1) ? 1 : 0);

    CP_WAIT(2);
    __syncthreads();
    uint32_t qf[4][4];
    {
        int arow = wid * 16 + (lid & 15);
        #pragma unroll
        for (int ks = 0; ks < 4; ks++) {
            uint32_t off = SWZ(arow * 128 + ks * 32 + (lid >> 4) * 16);
            LDSM4(qf[ks][0], qf[ks][1], qf[ks][2], qf[ks][3], sbase + QHI + off);
        }
    }

    float oacc[8][4] = {};
    float mA = -1e30f, mB = -1e30f, lA = 0.f, lB = 0.f;
    const int g = lid >> 3, w8 = lid & 7;
    const int qrA = q0 + wid * 16 + (lid >> 2);
    const float SC = 0.125f * 1.4426950408889634f;   // scale * log2(e)
    const int vrow16 = lid & 15, vhi16 = (lid >> 4) & 1;

    for (int ch = 0; ch < nch; ch++) {
        if (ch < nch - 1) { CP_WAIT(1); } else { CP_WAIT(0); }
        __syncthreads();
        if (ch + 2 < nch) load_chunk((ch + 2) % 3, ch + 2);

        int kt = ch;
        {
            uint32_t kb = sbase + BUF + (uint32_t)(ch % 3) * 16384u;
            uint32_t vb = kb + 8192u;

            // ---- S = Q K^T (single-term fp16) ----
            float sacc[8][4] = {};
            #pragma unroll
            for (int ks = 0; ks < 4; ks++) {
                #pragma unroll
                for (int p = 0; p < 4; p++) {
                    int nrow = p * 16 + (g >> 1) * 8 + w8;
                    uint32_t off = SWZ(nrow * 128 + ks * 32 + (g & 1) * 16);
                    uint32_t b0, b1, b2, b3;
                    LDSM4(b0, b1, b2, b3, kb + off);
                    MMAH(sacc[2*p],   qf[ks], b0, b1);
                    MMAH(sacc[2*p+1], qf[ks], b2, b3);
                }
            }

            // ---- scale (log2 domain); causal mask on diagonal chunk only ----
            #pragma unroll
            for (int nt = 0; nt < 8; nt++)
                #pragma unroll
                for (int j = 0; j < 4; j++) sacc[nt][j] *= SC;
            if (kt == qt) {
                #pragma unroll
                for (int nt = 0; nt < 8; nt++) {
                    int kc = kt * 64 + nt * 8 + (lid & 3) * 2;
                    if (kc > qrA)         sacc[nt][0] = -1e9f;
                    if (kc + 1 > qrA)     sacc[nt][1] = -1e9f;
                    if (kc > qrA + 8)     sacc[nt][2] = -1e9f;
                    if (kc + 1 > qrA + 8) sacc[nt][3] = -1e9f;
                }
            }

            // ---- online softmax (base-2) with corr-skip ----
            float rmA = -1e30f, rmB = -1e30f;
            #pragma unroll
            for (int nt = 0; nt < 8; nt++) {
                rmA = fmaxf(rmA, fmaxf(sacc[nt][0], sacc[nt][1]));
                rmB = fmaxf(rmB, fmaxf(sacc[nt][2], sacc[nt][3]));
            }
            rmA = fmaxf(rmA, __shfl_xor_sync(0xffffffffu, rmA, 1));
            rmA = fmaxf(rmA, __shfl_xor_sync(0xffffffffu, rmA, 2));
            rmB = fmaxf(rmB, __shfl_xor_sync(0xffffffffu, rmB, 1));
            rmB = fmaxf(rmB, __shfl_xor_sync(0xffffffffu, rmB, 2));
            float mnA = fmaxf(mA, rmA), mnB = fmaxf(mB, rmB);
            float corrA = 1.f, corrB = 1.f;
            if (mnA > mA || mnB > mB) {
                corrA = exp2f(mA - mnA);
                corrB = exp2f(mB - mnB);
                #pragma unroll
                for (int nt = 0; nt < 8; nt++) {
                    oacc[nt][0] *= corrA; oacc[nt][1] *= corrA;
                    oacc[nt][2] *= corrB; oacc[nt][3] *= corrB;
                }
            }
            mA = mnA; mB = mnB;
            float rsA = 0.f, rsB = 0.f;
            #pragma unroll
            for (int nt = 0; nt < 8; nt++) {
                sacc[nt][0] = exp2f(sacc[nt][0] - mA);
                sacc[nt][1] = exp2f(sacc[nt][1] - mA);
                sacc[nt][2] = exp2f(sacc[nt][2] - mB);
                sacc[nt][3] = exp2f(sacc[nt][3] - mB);
                rsA += sacc[nt][0] + sacc[nt][1];
                rsB += sacc[nt][2] + sacc[nt][3];
            }
            rsA += __shfl_xor_sync(0xffffffffu, rsA, 1);
            rsA += __shfl_xor_sync(0xffffffffu, rsA, 2);
            rsB += __shfl_xor_sync(0xffffffffu, rsB, 1);
            rsB += __shfl_xor_sync(0xffffffffu, rsB, 2);
            lA = lA * corrA + rsA;
            lB = lB * corrB + rsB;

            // ---- O += P V (fp16; V untransposed via ldmatrix.trans) ----
            #pragma unroll
            for (int k2 = 0; k2 < 4; k2++) {
                uint32_t pa[4];
                pa[0] = packh(sacc[2*k2][0],   sacc[2*k2][1]);
                pa[1] = packh(sacc[2*k2][2],   sacc[2*k2][3]);
                pa[2] = packh(sacc[2*k2+1][0], sacc[2*k2+1][1]);
                pa[3] = packh(sacc[2*k2+1][2], sacc[2*k2+1][3]);
                #pragma unroll
                for (int p = 0; p < 4; p++) {
                    uint32_t off = SWZ((k2 * 16 + vrow16) * 128 + p * 32 + vhi16 * 16);
                    uint32_t b0, b1, b2, b3;
                    LDSM4T(b0, b1, b2, b3, vb + off);
                    MMAH(oacc[2*p],   pa, b0, b1);
                    MMAH(oacc[2*p+1], pa, b2, b3);
                }
            }
        }
        __syncthreads();
    }

    // ---- epilogue: normalize, fp16 store ----
    float invA = 1.f / lA, invB = 1.f / lB;
    size_t rowA = (size_t)(b * TT + qrA);
    size_t rowB = rowA + 8;
    int colb = h * HD + (lid & 3) * 2;
    #pragma unroll
    for (int nt = 0; nt < 8; nt++) {
        *(uint32_t*)&Oh[rowA * DD + colb + nt * 8] =
            packh(oacc[nt][0] * invA, oacc[nt][1] * invA);
        *(uint32_t*)&Oh[rowB * DD + colb + nt * 8] =
            packh(oacc[nt][2] * invB, oacc[nt][3] * invB);
    }
}

// ---------------------------------------------------------------------------
// prep: x fp16 convert + fused QKV weight transpose (fp16) +
// Wo transpose (fp16) + rope table (sections on blockIdx.x)
// ---------------------------------------------------------------------------
__device__ __forceinline__ void convT16_body(const float* __restrict__ W,
        __half* __restrict__ t16, int Kd, int Nd, int idx, int tid, float (*Ts)[33]) {
    int nt = idx % (Nd / 32), kt = idx / (Nd / 32);
    int k0 = kt * 32, n0 = nt * 32;
    int r = tid >> 3, c4 = (tid & 7) * 4;
    float4 v = *(const float4*)&W[(size_t)(k0 + r) * Nd + n0 + c4];
    Ts[r][c4] = v.x; Ts[r][c4 + 1] = v.y; Ts[r][c4 + 2] = v.z; Ts[r][c4 + 3] = v.w;
    __syncthreads();
    #pragma unroll
    for (int j = 0; j < 4; j++) {
        size_t o = (size_t)(n0 + r) * Kd + k0 + c4 + j;
        t16[o] = __float2half_rn(Ts[c4 + j][r]);
    }
}

__global__ __launch_bounds__(256) void prep(const float* __restrict__ x,
        const float* __restrict__ Wq, const float* __restrict__ Wk,
        const float* __restrict__ Wv, const float* __restrict__ Wo) {
    __shared__ float Ts[32][33];
    int bx = blockIdx.x, tid = threadIdx.x;
    if (bx < 4096) {                       // x fp16 convert
        int i = (bx * 256 + tid) * 4;
        float4 v = *(const float4*)(x + i);
        *(uint32_t*)&g_x16[i]     = packh(v.x, v.y);
        *(uint32_t*)&g_x16[i + 2] = packh(v.z, v.w);
    } else if (bx < 5120) {
        convT16_body(Wq, g_w16, DD, DD, bx - 4096, tid, Ts);
    } else if (bx < 5376) {
        convT16_body(Wk, g_w16 + (size_t)NH * HD * DD, DD, NKV * HD, bx - 5120, tid, Ts);
    } else if (bx < 5632) {
        convT16_body(Wv, g_w16 + (size_t)(NH + NKV) * HD * DD, DD, NKV * HD,
                     bx - 5376, tid, Ts);
    } else if (bx < 6656) {
        convT16_body(Wo, g_wo16, DD, DD, bx - 5632, tid, Ts);
    } else {                               // rope table (fp32 trig; freq kept
                                           // bit-identical via double pow)
        int idx = (bx - 6656) * 256 + tid;
        int t = idx >> 5, pair = idx & 31;
        float freq = (float)pow(500000.0, -(double)pair / 32.0);
        float ang = (float)t * freq;
        float s, c;
        sincosf(ang, &s, &c);
        g_cos[idx] = c;
        g_sin[idx] = s;
    }
}

// ---------------------------------------------------------------------------
extern "C" void kernel_launch(void* const* d_in, const int* in_sizes, int n_in,
                              void* d_out, int out_size) {
    const float* x  = (const float*)d_in[0];
    // d_in[1] = causal mask — handled analytically
    const float* Wq = (const float*)d_in[2];
    const float* Wk = (const float*)d_in[3];
    const float* Wv = (const float*)d_in[4];
    const float* Wo = (const float*)d_in[5];
    float* out = (float*)d_out;

    __half *x16, *w16, *wo16;
    __half *q16, *k16, *v16, *a16;
    cudaGetSymbolAddress((void**)&x16, g_x16);
    cudaGetSymbolAddress((void**)&w16,  g_w16);
    cudaGetSymbolAddress((void**)&wo16, g_wo16);
    cudaGetSymbolAddress((void**)&q16, g_q16);
    cudaGetSymbolAddress((void**)&k16, g_k16);
    cudaGetSymbolAddress((void**)&v16, g_v16);
    cudaGetSymbolAddress((void**)&a16, g_a16);

    cudaFuncSetAttribute(gemm_qkv, cudaFuncAttributeMaxDynamicSharedMemorySize, 73728);
    cudaFuncSetAttribute(gemm_out, cudaFuncAttributeMaxDynamicSharedMemorySize, 98304);
    cudaFuncSetAttribute(attn_mma, cudaFuncAttributeMaxDynamicSharedMemorySize, 57344);

    prep<<<6912, 256>>>(x, Wq, Wk, Wv, Wo);

    // fused QKV projection + RoPE epilogue
    gemm_qkv<<<dim3(NQKV / 128, MM / 64), 128, 73728>>>(x16, w16, MM, NQKV, DD);

    attn_mma<<<dim3(TT / 64, BB * NH), 128, 57344>>>(q16, k16, v16, a16);

    gemm_out<<<dim3(DD / 128, MM / 128), 128, 98304>>>(a16, wo16, out,
                                                       MM, DD, DD);
}

// round 15
// speedup vs baseline: 2.1426x; 1.0343x over previous
#include <cuda_runtime.h>
#include <cuda_bf16.h>
#include <cuda_fp16.h>
#include <math.h>
#include <stdint.h>

#define BB 2
#define TT 2048
#define DD 1024
#define NH 16
#define NKV 4
#define HD 64
#define NREP 4           // NH / NKV
#define MM (BB*TT)       // 4096
#define NQKV (NH*HD + 2*NKV*HD)   // 1536 fused QKV output width

// ---------------- scratch (device globals; no runtime allocation) -----------
__device__ __align__(16) float g_cos[TT*32];
__device__ __align__(16) float g_sin[TT*32];
__device__ __half g_x16[MM*DD];                     // x fp16
__device__ __half g_w16[NQKV*DD];                   // fused QKV weights^T fp16 [N][K]
__device__ __half g_wo16[DD*DD];                    // Wo^T fp16 [N][K]
__device__ __half g_q16[BB*NH*TT*HD];               // Q fp16 [b][h][t][d]
__device__ __half g_k16[BB*NKV*TT*HD];              // K fp16 [b][kvh][t][d]
__device__ __half g_v16[BB*NKV*TT*HD];              // V fp16 [b][kvh][t][d]
__device__ __half g_a16[MM*DD];                     // attention out fp16

// ---------------- helpers ----------------------------------------------------
__device__ __forceinline__ uint32_t smem_u32(const void* p) {
    uint32_t a;
    asm("{ .reg .u64 t; cvta.to.shared.u64 t, %1; cvt.u32.u64 %0, t; }"
        : "=r"(a) : "l"(p));
    return a;
}
#define SWZ(off) ((off) ^ (((off) >> 3) & 0x70))

#define CP_ASYNC16(dst, src) \
    asm volatile("cp.async.cg.shared.global [%0], [%1], 16;" \
                 :: "r"(dst), "l"(src) : "memory")
#define CP_COMMIT() asm volatile("cp.async.commit_group;" ::: "memory")
#define CP_WAIT(n)  asm volatile("cp.async.wait_group %0;" :: "n"(n) : "memory")

#define LDSM4(r0, r1, r2, r3, addr) \
    asm volatile("ldmatrix.sync.aligned.m8n8.x4.shared.b16 {%0,%1,%2,%3}, [%4];" \
                 : "=r"(r0), "=r"(r1), "=r"(r2), "=r"(r3) : "r"(addr))

#define LDSM4T(r0, r1, r2, r3, addr) \
    asm volatile("ldmatrix.sync.aligned.m8n8.x4.trans.shared.b16 {%0,%1,%2,%3}, [%4];" \
                 : "=r"(r0), "=r"(r1), "=r"(r2), "=r"(r3) : "r"(addr))

#define MMAH(c, a, b0, b1) \
    asm volatile("mma.sync.aligned.m16n8k16.row.col.f32.f16.f16.f32 " \
                 "{%0,%1,%2,%3}, {%4,%5,%6,%7}, {%8,%9}, {%0,%1,%2,%3};" \
                 : "+f"((c)[0]), "+f"((c)[1]), "+f"((c)[2]), "+f"((c)[3]) \
                 : "r"((a)[0]), "r"((a)[1]), "r"((a)[2]), "r"((a)[3]), \
                   "r"(b0), "r"(b1))

#define EX2F16X2(d, a) \
    asm volatile("ex2.approx.f16x2 %0, %1;" : "=r"(d) : "r"(a))

__device__ __forceinline__ uint32_t packh(float a, float b) {
    __half2 h = __floats2half2_rn(a, b);
    return *(uint32_t*)&h;
}

// ---------------------------------------------------------------------------
// QKV GEMM: x(fp16) @ W(fp16)^T, fp32 acc. 64x128 CTA tile, 128 threads
// (4 warps, each full-M x 32-N), BK=64, 3-stage cp.async (3 x 24KB) ->
// 2 CTAs/SM. Fused epilogue: RoPE (smem-staged cos/sin), Q/K/V -> fp16.
// ---------------------------------------------------------------------------
__global__ __launch_bounds__(128, 2) void gemm_qkv(
        const __half* __restrict__ A, const __half* __restrict__ B16,
        int M, int N, int K) {
    extern __shared__ char smem[];
    uint32_t sbase = smem_u32(smem);
    int tid = threadIdx.x, wid = tid >> 5, lid = tid & 31;
    int m0 = blockIdx.y * 64, n0 = blockIdx.x * 128;
    const int nch = K / 64;
    const int rr = tid >> 3, uu = tid & 7;   // rr 0..15

    float acc[4][4][4] = {};

    auto load_chunk = [&](int buf, int ch) {
        int k0 = ch * 64;
        uint32_t dbase = sbase + (uint32_t)buf * 24576u;
        #pragma unroll
        for (int it = 0; it < 4; it++) {       // A: 64 rows
            int r = it * 16 + rr;
            CP_ASYNC16(dbase + SWZ(r * 128 + uu * 16),
                       A + (size_t)(m0 + r) * K + k0 + uu * 8);
        }
        #pragma unroll
        for (int it = 0; it < 8; it++) {       // B: 128 rows
            int r = it * 16 + rr;
            CP_ASYNC16(dbase + 8192u + SWZ(r * 128 + uu * 16),
                       B16 + (size_t)(n0 + r) * K + k0 + uu * 8);
        }
        CP_COMMIT();
    };

    load_chunk(0, 0);
    load_chunk(1, 1);

    for (int ch = 0; ch < nch; ch++) {
        if (ch < nch - 1) { CP_WAIT(1); } else { CP_WAIT(0); }
        __syncthreads();
        if (ch + 2 < nch) load_chunk((ch + 2) % 3, ch + 2);

        uint32_t db = sbase + (uint32_t)(ch % 3) * 24576u;
        uint32_t ab_ = db, bb = db + 8192u;
        int g = lid >> 3, w8 = lid & 7;

        #pragma unroll
        for (int ks = 0; ks < 4; ks++) {
            uint32_t ah[4][4], bh[4][2];
            int arow = lid & 15;
            int acol = ks * 32 + (lid >> 4) * 16;
            #pragma unroll
            for (int mi = 0; mi < 4; mi++) {
                uint32_t off = SWZ((arow + mi * 16) * 128 + acol);
                LDSM4(ah[mi][0], ah[mi][1], ah[mi][2], ah[mi][3], ab_ + off);
            }
            #pragma unroll
            for (int p = 0; p < 2; p++) {
                int nrow = wid * 32 + p * 16 + (g >> 1) * 8 + w8;
                uint32_t off = SWZ(nrow * 128 + ks * 32 + (g & 1) * 16);
                LDSM4(bh[2*p][0], bh[2*p][1], bh[2*p+1][0], bh[2*p+1][1], bb + off);
            }
            #pragma unroll
            for (int mi = 0; mi < 4; mi++)
                #pragma unroll
                for (int ni = 0; ni < 4; ni++)
                    MMAH(acc[mi][ni], ah[mi], bh[ni][0], bh[ni][1]);
        }
        __syncthreads();
    }

    // ---- fused epilogue ----
    // cols [0,1024)=Q, [1024,1280)=K, [1280,1536)=V (uniform per CTA)
    int region = (blockIdx.x < 8) ? 0 : (blockIdx.x < 10) ? 1 : 2;
    float* cs_s = (float*)smem;               // 8KB: cos[64][32]
    float* sn_s = (float*)(smem + 8192);      // 8KB: sin[64][32]
    if (region < 2) {
        int tbase = m0 & (TT - 1);
        #pragma unroll
        for (int i = 0; i < 4; i++) {
            int idx = i * 128 + tid;          // 512 float4 per table
            *(float4*)(smem + idx * 16) =
                *(const float4*)&g_cos[(size_t)tbase * 32 + idx * 4];
            *(float4*)(smem + 8192 + idx * 16) =
                *(const float4*)&g_sin[(size_t)tbase * 32 + idx * 4];
        }
        __syncthreads();
    }
    #pragma unroll
    for (int mi = 0; mi < 4; mi++) {
        int row = m0 + mi * 16 + (lid >> 2);
        #pragma unroll
        for (int r2 = 0; r2 < 2; r2++) {
            int trow = row + r2 * 8;
            int b = trow >> 11, t = trow & (TT - 1);
            int tl = trow - m0;
            #pragma unroll
            for (int ni = 0; ni < 4; ni++) {
                int c = n0 + wid * 32 + ni * 8 + (lid & 3) * 2;
                float v0 = acc[mi][ni][r2 * 2], v1 = acc[mi][ni][r2 * 2 + 1];
                if (region == 2) {
                    int cc = c - 1280;
                    int kvh = cc >> 6, d = cc & 63;
                    *(uint32_t*)&g_v16[((size_t)(b * NKV + kvh) * TT + t) * HD + d] =
                        packh(v0, v1);
                } else {
                    int cc = (region == 1) ? c - 1024 : c;
                    int hh = cc >> 6, d = cc & 63;
                    int ci = tl * 32 + (d >> 1);
                    float cs = cs_s[ci], sn = sn_s[ci];
                    float r0 = v0 * cs - v1 * sn;
                    float r1 = v1 * cs + v0 * sn;
                    if (region == 1) {
                        size_t o = ((size_t)(b * NKV + hh) * TT + t) * HD + d;
                        *(uint32_t*)&g_k16[o] = packh(r0, r1);
                    } else {
                        size_t o = ((size_t)(b * NH + hh) * TT + t) * HD + d;
                        *(uint32_t*)&g_q16[o] = packh(r0, r1);
                    }
                }
            }
        }
    }
}

// ---------------------------------------------------------------------------
// O-projection GEMM: single-term fp16 x fp16 (fp32 acc).
// 64x128 CTA tile, 128 threads, 3-stage (3 x 24KB) -> 2 CTAs/SM.
// ---------------------------------------------------------------------------
__global__ __launch_bounds__(128, 2) void gemm_out(
        const __half* __restrict__ A, const __half* __restrict__ B,
        float* __restrict__ C, int M, int N, int K) {
    extern __shared__ char smem[];
    uint32_t sbase = smem_u32(smem);
    int tid = threadIdx.x, wid = tid >> 5, lid = tid & 31;
    int m0 = blockIdx.y * 64, n0 = blockIdx.x * 128;
    const int nch = K / 64;
    const int rr = tid >> 3, uu = tid & 7;

    float acc[4][4][4] = {};

    auto load_chunk = [&](int buf, int ch) {
        int k0 = ch * 64;
        uint32_t dbase = sbase + (uint32_t)buf * 24576u;
        #pragma unroll
        for (int it = 0; it < 4; it++) {
            int r = it * 16 + rr;
            CP_ASYNC16(dbase + SWZ(r * 128 + uu * 16),
                       A + (size_t)(m0 + r) * K + k0 + uu * 8);
        }
        #pragma unroll
        for (int it = 0; it < 8; it++) {
            int r = it * 16 + rr;
            CP_ASYNC16(dbase + 8192u + SWZ(r * 128 + uu * 16),
                       B + (size_t)(n0 + r) * K + k0 + uu * 8);
        }
        CP_COMMIT();
    };

    load_chunk(0, 0);
    load_chunk(1, 1);

    for (int ch = 0; ch < nch; ch++) {
        if (ch < nch - 1) { CP_WAIT(1); } else { CP_WAIT(0); }
        __syncthreads();
        if (ch + 2 < nch) load_chunk((ch + 2) % 3, ch + 2);

        uint32_t db = sbase + (uint32_t)(ch % 3) * 24576u;
        uint32_t ab_ = db, bb = db + 8192u;
        int g = lid >> 3, w8 = lid & 7;

        #pragma unroll
        for (int ks = 0; ks < 4; ks++) {
            uint32_t ah[4][4], bh[4][2];
            int arow = lid & 15;
            int acol = ks * 32 + (lid >> 4) * 16;
            #pragma unroll
            for (int mi = 0; mi < 4; mi++) {
                uint32_t off = SWZ((arow + mi * 16) * 128 + acol);
                LDSM4(ah[mi][0], ah[mi][1], ah[mi][2], ah[mi][3], ab_ + off);
            }
            #pragma unroll
            for (int p = 0; p < 2; p++) {
                int nrow = wid * 32 + p * 16 + (g >> 1) * 8 + w8;
                uint32_t off = SWZ(nrow * 128 + ks * 32 + (g & 1) * 16);
                LDSM4(bh[2*p][0], bh[2*p][1], bh[2*p+1][0], bh[2*p+1][1], bb + off);
            }
            #pragma unroll
            for (int mi = 0; mi < 4; mi++)
                #pragma unroll
                for (int ni = 0; ni < 4; ni++)
                    MMAH(acc[mi][ni], ah[mi], bh[ni][0], bh[ni][1]);
        }
        __syncthreads();
    }

    #pragma unroll
    for (int mi = 0; mi < 4; mi++) {
        int row = m0 + mi * 16 + (lid >> 2);
        #pragma unroll
        for (int ni = 0; ni < 4; ni++) {
            int col = n0 + wid * 32 + ni * 8 + (lid & 3) * 2;
            *(float2*)&C[(size_t)row * N + col] =
                make_float2(acc[mi][ni][0], acc[mi][ni][1]);
            *(float2*)&C[(size_t)(row + 8) * N + col] =
                make_float2(acc[mi][ni][2], acc[mi][ni][3]);
        }
    }
}

// ---------------------------------------------------------------------------
// HMMA flash attention, causal. 64-query tiles, 128 threads (4 warps),
// grid (T/64 reversed, B*NH). smem: Q 8KB + 3 x 16KB = 56KB -> 3 CTAs/SM.
// S = Q K^T fp16; softmax via ex2.approx.f16x2; row-sum l via ones-MMA
// (persistent fp32 accumulator); PV fp16 (V via ldmatrix.trans).
// ---------------------------------------------------------------------------
__global__ __launch_bounds__(128, 3) void attn_mma(
        const __half* __restrict__ Q16, const __half* __restrict__ K16,
        const __half* __restrict__ Vt, __half* __restrict__ Oh) {
    extern __shared__ char smem[];
    uint32_t sbase = smem_u32(smem);
    const uint32_t QHI = 0, BUF = 8192;   // 3 x 16KB chunk buffers

    int tid = threadIdx.x, wid = tid >> 5, lid = tid & 31;
    int qt = gridDim.x - 1 - blockIdx.x;
    int bh = blockIdx.y;
    int b = bh / NH, h = bh % NH, kvh = h / NREP;
    int q0 = qt * 64;

    const __half* qb16 = Q16 + (size_t)(b * NH + h) * TT * HD;
    const __half* kb16 = K16 + (size_t)(b * NKV + kvh) * TT * HD;
    const __half* vbase = Vt + (size_t)(b * NKV + kvh) * TT * HD;   // [t][d]

    // stage Q (own commit group): 64 rows
    {
        #pragma unroll
        for (int it = 0; it < 4; it++) {
            int idx = it * 128 + tid;
            int r = idx >> 3, u = idx & 7;
            CP_ASYNC16(sbase + QHI + SWZ(r * 128 + u * 16),
                       qb16 + (size_t)(q0 + r) * HD + u * 8);
        }
        CP_COMMIT();
    }

    auto load_chunk = [&](int buf, int kt) {
        uint32_t db = sbase + BUF + (uint32_t)buf * 16384u;
        #pragma unroll
        for (int arr = 0; arr < 2; arr++) {
            uint32_t ab = db + (uint32_t)arr * 8192u;
            const __half* s = arr ? vbase : kb16;
            #pragma unroll
            for (int it = 0; it < 4; it++) {
                int idx = it * 128 + tid;
                int r = idx >> 3, u = idx & 7;
                CP_ASYNC16(ab + SWZ(r * 128 + u * 16),
                           s + (size_t)(kt * 64 + r) * HD + u * 8);
            }
        }
        CP_COMMIT();
    };

    int nch = qt + 1;
    load_chunk(0, 0);
    load_chunk(1, (nch > 1) ? 1 : 0);

    CP_WAIT(2);
    __syncthreads();
    uint32_t qf[4][4];
    {
        int arow = wid * 16 + (lid & 15);
        #pragma unroll
        for (int ks = 0; ks < 4; ks++) {
            uint32_t off = SWZ(arow * 128 + ks * 32 + (lid >> 4) * 16);
            LDSM4(qf[ks][0], qf[ks][1], qf[ks][2], qf[ks][3], sbase + QHI + off);
        }
    }

    float oacc[8][4] = {};
    float lacc[4] = {};                    // ones-MMA accumulator: row sums
    float mA = -1e30f, mB = -1e30f;
    const int g = lid >> 3, w8 = lid & 7;
    const int qrA = q0 + wid * 16 + (lid >> 2);
    const float SC = 0.125f * 1.4426950408889634f;   // scale * log2(e)
    const int vrow16 = lid & 15, vhi16 = (lid >> 4) & 1;
    const uint32_t ONES = 0x3C003C00u;     // half2(1.0, 1.0)

    for (int ch = 0; ch < nch; ch++) {
        if (ch < nch - 1) { CP_WAIT(1); } else { CP_WAIT(0); }
        __syncthreads();
        if (ch + 2 < nch) load_chunk((ch + 2) % 3, ch + 2);

        int kt = ch;
        {
            uint32_t kb = sbase + BUF + (uint32_t)(ch % 3) * 16384u;
            uint32_t vb = kb + 8192u;

            // ---- S = Q K^T (single-term fp16) ----
            float sacc[8][4] = {};
            #pragma unroll
            for (int ks = 0; ks < 4; ks++) {
                #pragma unroll
                for (int p = 0; p < 4; p++) {
                    int nrow = p * 16 + (g >> 1) * 8 + w8;
                    uint32_t off = SWZ(nrow * 128 + ks * 32 + (g & 1) * 16);
                    uint32_t b0, b1, b2, b3;
                    LDSM4(b0, b1, b2, b3, kb + off);
                    MMAH(sacc[2*p],   qf[ks], b0, b1);
                    MMAH(sacc[2*p+1], qf[ks], b2, b3);
                }
            }

            // ---- scale (log2 domain); causal mask on diagonal chunk only ----
            #pragma unroll
            for (int nt = 0; nt < 8; nt++)
                #pragma unroll
                for (int j = 0; j < 4; j++) sacc[nt][j] *= SC;
            if (kt == qt) {
                #pragma unroll
                for (int nt = 0; nt < 8; nt++) {
                    int kc = kt * 64 + nt * 8 + (lid & 3) * 2;
                    if (kc > qrA)         sacc[nt][0] = -1e9f;
                    if (kc + 1 > qrA)     sacc[nt][1] = -1e9f;
                    if (kc > qrA + 8)     sacc[nt][2] = -1e9f;
                    if (kc + 1 > qrA + 8) sacc[nt][3] = -1e9f;
                }
            }

            // ---- running max + rescale (corr-skip) ----
            float rmA = -1e30f, rmB = -1e30f;
            #pragma unroll
            for (int nt = 0; nt < 8; nt++) {
                rmA = fmaxf(rmA, fmaxf(sacc[nt][0], sacc[nt][1]));
                rmB = fmaxf(rmB, fmaxf(sacc[nt][2], sacc[nt][3]));
            }
            rmA = fmaxf(rmA, __shfl_xor_sync(0xffffffffu, rmA, 1));
            rmA = fmaxf(rmA, __shfl_xor_sync(0xffffffffu, rmA, 2));
            rmB = fmaxf(rmB, __shfl_xor_sync(0xffffffffu, rmB, 1));
            rmB = fmaxf(rmB, __shfl_xor_sync(0xffffffffu, rmB, 2));
            float mnA = fmaxf(mA, rmA), mnB = fmaxf(mB, rmB);
            if (mnA > mA || mnB > mB) {
                float corrA = exp2f(mA - mnA), corrB = exp2f(mB - mnB);
                #pragma unroll
                for (int nt = 0; nt < 8; nt++) {
                    oacc[nt][0] *= corrA; oacc[nt][1] *= corrA;
                    oacc[nt][2] *= corrB; oacc[nt][3] *= corrB;
                }
                lacc[0] *= corrA; lacc[1] *= corrA;
                lacc[2] *= corrB; lacc[3] *= corrB;
            }
            mA = mnA; mB = mnB;

            // ---- P = ex2(s - m) in fp16 (f16x2 MUFU); pa = PV A-fragments ----
            uint32_t pa[4][4];
            #pragma unroll
            for (int k2 = 0; k2 < 4; k2++) {
                uint32_t t0 = packh(sacc[2*k2][0] - mA,   sacc[2*k2][1] - mA);
                uint32_t t1 = packh(sacc[2*k2][2] - mB,   sacc[2*k2][3] - mB);
                uint32_t t2 = packh(sacc[2*k2+1][0] - mA, sacc[2*k2+1][1] - mA);
                uint32_t t3 = packh(sacc[2*k2+1][2] - mB, sacc[2*k2+1][3] - mB);
                EX2F16X2(pa[k2][0], t0);
                EX2F16X2(pa[k2][1], t1);
                EX2F16X2(pa[k2][2], t2);
                EX2F16X2(pa[k2][3], t3);
            }

            // ---- l += P @ ones (exact fp32 sum of fp16 P; quad-replicated) ----
            #pragma unroll
            for (int k2 = 0; k2 < 4; k2++)
                MMAH(lacc, pa[k2], ONES, ONES);

            // ---- O += P V (V untransposed via ldmatrix.trans) ----
            #pragma unroll
            for (int k2 = 0; k2 < 4; k2++) {
                #pragma unroll
                for (int p = 0; p < 4; p++) {
                    uint32_t off = SWZ((k2 * 16 + vrow16) * 128 + p * 32 + vhi16 * 16);
                    uint32_t b0, b1, b2, b3;
                    LDSM4T(b0, b1, b2, b3, vb + off);
                    MMAH(oacc[2*p],   pa[k2], b0, b1);
                    MMAH(oacc[2*p+1], pa[k2], b2, b3);
                }
            }
        }
        __syncthreads();
    }

    // ---- epilogue: normalize, fp16 store ----
    float invA = 1.f / lacc[0], invB = 1.f / lacc[2];
    size_t rowA = (size_t)(b * TT + qrA);
    size_t rowB = rowA + 8;
    int colb = h * HD + (lid & 3) * 2;
    #pragma unroll
    for (int nt = 0; nt < 8; nt++) {
        *(uint32_t*)&Oh[rowA * DD + colb + nt * 8] =
            packh(oacc[nt][0] * invA, oacc[nt][1] * invA);
        *(uint32_t*)&Oh[rowB * DD + colb + nt * 8] =
            packh(oacc[nt][2] * invB, oacc[nt][3] * invB);
    }
}

// ---------------------------------------------------------------------------
// prep: x fp16 convert + fused QKV weight transpose (fp16) +
// Wo transpose (fp16) + rope table (sections on blockIdx.x)
// ---------------------------------------------------------------------------
__device__ __forceinline__ void convT16_body(const float* __restrict__ W,
        __half* __restrict__ t16, int Kd, int Nd, int idx, int tid, float (*Ts)[33]) {
    int nt = idx % (Nd / 32), kt = idx / (Nd / 32);
    int k0 = kt * 32, n0 = nt * 32;
    int r = tid >> 3, c4 = (tid & 7) * 4;
    float4 v = *(const float4*)&W[(size_t)(k0 + r) * Nd + n0 + c4];
    Ts[r][c4] = v.x; Ts[r][c4 + 1] = v.y; Ts[r][c4 + 2] = v.z; Ts[r][c4 + 3] = v.w;
    __syncthreads();
    #pragma unroll
    for (int j = 0; j < 4; j++) {
        size_t o = (size_t)(n0 + r) * Kd + k0 + c4 + j;
        t16[o] = __float2half_rn(Ts[c4 + j][r]);
    }
}

__global__ __launch_bounds__(256) void prep(const float* __restrict__ x,
        const float* __restrict__ Wq, const float* __restrict__ Wk,
        const float* __restrict__ Wv, const float* __restrict__ Wo) {
    __shared__ float Ts[32][33];
    int bx = blockIdx.x, tid = threadIdx.x;
    if (bx < 4096) {                       // x fp16 convert
        int i = (bx * 256 + tid) * 4;
        float4 v = *(const float4*)(x + i);
        *(uint32_t*)&g_x16[i]     = packh(v.x, v.y);
        *(uint32_t*)&g_x16[i + 2] = packh(v.z, v.w);
    } else if (bx < 5120) {
        convT16_body(Wq, g_w16, DD, DD, bx - 4096, tid, Ts);
    } else if (bx < 5376) {
        convT16_body(Wk, g_w16 + (size_t)NH * HD * DD, DD, NKV * HD, bx - 5120, tid, Ts);
    } else if (bx < 5632) {
        convT16_body(Wv, g_w16 + (size_t)(NH + NKV) * HD * DD, DD, NKV * HD,
                     bx - 5376, tid, Ts);
    } else if (bx < 6656) {
        convT16_body(Wo, g_wo16, DD, DD, bx - 5632, tid, Ts);
    } else {                               // rope table (fp32 trig; freq kept
                                           // bit-identical via double pow)
        int idx = (bx - 6656) * 256 + tid;
        int t = idx >> 5, pair = idx & 31;
        float freq = (float)pow(500000.0, -(double)pair / 32.0);
        float ang = (float)t * freq;
        float s, c;
        sincosf(ang, &s, &c);
        g_cos[idx] = c;
        g_sin[idx] = s;
    }
}

// ---------------------------------------------------------------------------
extern "C" void kernel_launch(void* const* d_in, const int* in_sizes, int n_in,
                              void* d_out, int out_size) {
    const float* x  = (const float*)d_in[0];
    // d_in[1] = causal mask — handled analytically
    const float* Wq = (const float*)d_in[2];
    const float* Wk = (const float*)d_in[3];
    const float* Wv = (const float*)d_in[4];
    const float* Wo = (const float*)d_in[5];
    float* out = (float*)d_out;

    __half *x16, *w16, *wo16;
    __half *q16, *k16, *v16, *a16;
    cudaGetSymbolAddress((void**)&x16, g_x16);
    cudaGetSymbolAddress((void**)&w16,  g_w16);
    cudaGetSymbolAddress((void**)&wo16, g_wo16);
    cudaGetSymbolAddress((void**)&q16, g_q16);
    cudaGetSymbolAddress((void**)&k16, g_k16);
    cudaGetSymbolAddress((void**)&v16, g_v16);
    cudaGetSymbolAddress((void**)&a16, g_a16);

    cudaFuncSetAttribute(gemm_qkv, cudaFuncAttributeMaxDynamicSharedMemorySize, 73728);
    cudaFuncSetAttribute(gemm_out, cudaFuncAttributeMaxDynamicSharedMemorySize, 73728);
    cudaFuncSetAttribute(attn_mma, cudaFuncAttributeMaxDynamicSharedMemorySize, 57344);

    prep<<<6912, 256>>>(x, Wq, Wk, Wv, Wo);

    // fused QKV projection + RoPE epilogue
    gemm_qkv<<<dim3(NQKV / 128, MM / 64), 128, 73728>>>(x16, w16, MM, NQKV, DD);

    attn_mma<<<dim3(TT / 64, BB * NH), 128, 57344>>>(q16, k16, v16, a16);

    gemm_out<<<dim3(DD / 128, MM / 64), 128, 73728>>>(a16, wo16, out,
                                                      MM, DD, DD);
}